// round 2
// baseline (speedup 1.0000x reference)
#include <cuda_runtime.h>
#include <cuda_bf16.h>

// Problem constants
#define B_   4
#define S_   2048
#define H_   1024
#define NH_  16
#define HD_  64
#define MROWS (B_ * S_)        // 8192

// Scratch: Q,K,V in [B*NH, S, HD] layout (head-major), fp32.
__device__ float g_q[(size_t)B_ * NH_ * S_ * HD_];
__device__ float g_k[(size_t)B_ * NH_ * S_ * HD_];
__device__ float g_v[(size_t)B_ * NH_ * S_ * HD_];

// ---------------------------------------------------------------------------
// Kernel 1: fused QKV projection.
// out[m][n] = sum_k X[m][k] * W[n][k] + bias[n]
// Tile: BM=64, BN=64, BK=16, 256 threads, 4x4 per thread.
// Output written head-transposed: [(b*NH + h)*S + s]*HD + d.
// ---------------------------------------------------------------------------
#define GBK 16
#define GPAD 68   // row stride (floats) in shared, multiple of 4 for float4

__global__ __launch_bounds__(256, 4)
void qkv_gemm_kernel(const float* __restrict__ X,
                     const float* __restrict__ Wq, const float* __restrict__ bq,
                     const float* __restrict__ Wk, const float* __restrict__ bk,
                     const float* __restrict__ Wv, const float* __restrict__ bv)
{
    __shared__ float As[GBK][GPAD];  // X tile, k-major: As[k][m_local]
    __shared__ float Bs[GBK][GPAD];  // W tile, k-major: Bs[k][n_local]

    const int z = blockIdx.z;
    const float* __restrict__ W    = (z == 0) ? Wq : (z == 1) ? Wk : Wv;
    const float* __restrict__ bias = (z == 0) ? bq : (z == 1) ? bk : bv;
    float* __restrict__ out        = (z == 0) ? g_q : (z == 1) ? g_k : g_v;

    const int n0 = blockIdx.x * 64;
    const int m0 = blockIdx.y * 64;
    const int tid = threadIdx.x;
    const int tx = tid & 15;
    const int ty = tid >> 4;

    // loader mapping: 256 threads cover 64 rows x 16 k as float4
    const int lr = tid >> 2;          // 0..63
    const int lc = (tid & 3) * 4;     // 0,4,8,12

    float acc[4][4] = {};

    const int K = H_;
    for (int k0 = 0; k0 < K; k0 += GBK) {
        float4 xa = *(const float4*)&X[(size_t)(m0 + lr) * K + k0 + lc];
        float4 wb = *(const float4*)&W[(size_t)(n0 + lr) * K + k0 + lc];
        __syncthreads();   // protect previous iteration's reads
        As[lc + 0][lr] = xa.x; As[lc + 1][lr] = xa.y;
        As[lc + 2][lr] = xa.z; As[lc + 3][lr] = xa.w;
        Bs[lc + 0][lr] = wb.x; Bs[lc + 1][lr] = wb.y;
        Bs[lc + 2][lr] = wb.z; Bs[lc + 3][lr] = wb.w;
        __syncthreads();
        #pragma unroll
        for (int kk = 0; kk < GBK; ++kk) {
            float4 a4 = *(const float4*)&As[kk][ty * 4];
            float4 b4 = *(const float4*)&Bs[kk][tx * 4];
            float av[4] = {a4.x, a4.y, a4.z, a4.w};
            float bv4[4] = {b4.x, b4.y, b4.z, b4.w};
            #pragma unroll
            for (int i = 0; i < 4; ++i)
                #pragma unroll
                for (int j = 0; j < 4; ++j)
                    acc[i][j] = fmaf(av[i], bv4[j], acc[i][j]);
        }
    }

    // Write with bias, head-transposed layout.
    const int b  = m0 >> 11;              // m0 / 2048
    const int s0 = (m0 & (S_ - 1)) + ty * 4;
    const int h  = n0 >> 6;               // n0 / 64
    const int d0 = tx * 4;
    const float4 bi = *(const float4*)&bias[n0 + d0];
    #pragma unroll
    for (int i = 0; i < 4; ++i) {
        size_t off = (((size_t)(b * NH_ + h)) * S_ + (s0 + i)) * HD_ + d0;
        float4 r = make_float4(acc[i][0] + bi.x, acc[i][1] + bi.y,
                               acc[i][2] + bi.z, acc[i][3] + bi.w);
        *(float4*)&out[off] = r;
    }
}

// ---------------------------------------------------------------------------
// Kernel 2: causal flash attention, fp32.
// Grid: (32 q-tiles, 64 b*h). 256 threads. Q tile = 64 rows, K/V tiles = 64.
// Online softmax; matches reference:
//   probs = softmax( (where(j>i, -inf, qk) + amask[b,j]) / 8 )
// ---------------------------------------------------------------------------
#define APAD 68

__global__ __launch_bounds__(256, 3)
void attn_kernel(const float* __restrict__ amask, float* __restrict__ out)
{
    extern __shared__ float sm[];
    float* Qs = sm;                 // [64][APAD], d-major: Qs[d][i]
    float* Ks = Qs + 64 * APAD;     // [64][APAD], d-major: Ks[d][j]
    float* Vs = Ks + 64 * APAD;     // [64][APAD], natural:  Vs[j][d]
    float* Ps = Vs + 64 * APAD;     // [64][APAD], j-major:  Ps[j][i]

    const int qt = (int)gridDim.x - 1 - (int)blockIdx.x;  // heavy tiles first
    const int bh = blockIdx.y;
    const int b  = bh >> 4;
    const int h  = bh & 15;
    const int tid = threadIdx.x;
    const int tx = tid & 15;
    const int ty = tid >> 4;

    const float* __restrict__ qptr = g_q + (size_t)bh * S_ * HD_;
    const float* __restrict__ kptr = g_k + (size_t)bh * S_ * HD_;
    const float* __restrict__ vptr = g_v + (size_t)bh * S_ * HD_;
    const int q0 = qt * 64;

    // Load Q tile transposed into Qs[d][i].
    // 64 rows x 64 cols = 1024 float4 loads; 256 threads -> 4 each.
    const int lrow = tid >> 2;               // 0..63 (q/k/v row)
    const int lcb  = (tid & 3) * 16;         // 0,16,32,48 (d base)
    {
        #pragma unroll
        for (int t = 0; t < 4; ++t) {
            const int c = lcb + t * 4;       // d offset 0..60
            float4 v = *(const float4*)&qptr[(size_t)(q0 + lrow) * HD_ + c];
            Qs[(c + 0) * APAD + lrow] = v.x;
            Qs[(c + 1) * APAD + lrow] = v.y;
            Qs[(c + 2) * APAD + lrow] = v.z;
            Qs[(c + 3) * APAD + lrow] = v.w;
        }
    }

    float o[4][4] = {};
    float mrow[4] = {-1e30f, -1e30f, -1e30f, -1e30f};
    float lrowacc[4] = {};

    for (int kt = 0; kt <= qt; ++kt) {
        const int j0 = kt * 64;
        __syncthreads();  // Ks/Vs free to overwrite; also orders first-iter Qs
        {
            #pragma unroll
            for (int t = 0; t < 4; ++t) {
                const int c = lcb + t * 4;
                float4 kv = *(const float4*)&kptr[(size_t)(j0 + lrow) * HD_ + c];
                Ks[(c + 0) * APAD + lrow] = kv.x;
                Ks[(c + 1) * APAD + lrow] = kv.y;
                Ks[(c + 2) * APAD + lrow] = kv.z;
                Ks[(c + 3) * APAD + lrow] = kv.w;
                float4 vv = *(const float4*)&vptr[(size_t)(j0 + lrow) * HD_ + c];
                *(float4*)&Vs[lrow * APAD + c] = vv;
            }
        }
        __syncthreads();

        // S = Q @ K^T (64x64 tile, contraction over d=64)
        float s[4][4] = {};
        #pragma unroll 16
        for (int d = 0; d < HD_; ++d) {
            float4 a4 = *(const float4*)&Qs[d * APAD + ty * 4];
            float4 b4 = *(const float4*)&Ks[d * APAD + tx * 4];
            float av[4] = {a4.x, a4.y, a4.z, a4.w};
            float bv4[4] = {b4.x, b4.y, b4.z, b4.w};
            #pragma unroll
            for (int i = 0; i < 4; ++i)
                #pragma unroll
                for (int j = 0; j < 4; ++j)
                    s[i][j] = fmaf(av[i], bv4[j], s[i][j]);
        }

        // attention_mask for these 4 columns (zeros in this dataset, applied anyway)
        const float4 am4 = *(const float4*)&amask[(size_t)b * S_ + j0 + tx * 4];
        const float am[4] = {am4.x, am4.y, am4.z, am4.w};

        float p[4][4];
        #pragma unroll
        for (int i = 0; i < 4; ++i) {
            const int gi = q0 + ty * 4 + i;
            float rm = -1e30f;
            #pragma unroll
            for (int j = 0; j < 4; ++j) {
                const int gj = j0 + tx * 4 + j;
                float v = (s[i][j] + am[j]) * 0.125f;
                if (gj > gi) v = -1e30f;   // causal mask
                s[i][j] = v;
                rm = fmaxf(rm, v);
            }
            // reduce max across the 16-thread row group (lanes differ in bits 0-3)
            #pragma unroll
            for (int off = 1; off < 16; off <<= 1)
                rm = fmaxf(rm, __shfl_xor_sync(0xffffffffu, rm, off));

            const float mnew = fmaxf(mrow[i], rm);
            const float corr = __expf(mrow[i] - mnew);
            float rs = 0.f;
            #pragma unroll
            for (int j = 0; j < 4; ++j) {
                float pv = __expf(s[i][j] - mnew);
                p[i][j] = pv;
                rs += pv;
            }
            #pragma unroll
            for (int off = 1; off < 16; off <<= 1)
                rs += __shfl_xor_sync(0xffffffffu, rs, off);

            lrowacc[i] = lrowacc[i] * corr + rs;
            mrow[i] = mnew;
            #pragma unroll
            for (int d = 0; d < 4; ++d) o[i][d] *= corr;
        }

        // stage P transposed: Ps[j][i]
        #pragma unroll
        for (int i = 0; i < 4; ++i)
            #pragma unroll
            for (int j = 0; j < 4; ++j)
                Ps[(tx * 4 + j) * APAD + (ty * 4 + i)] = p[i][j];
        __syncthreads();

        // O += P @ V (contraction over j=64)
        #pragma unroll 16
        for (int j = 0; j < 64; ++j) {
            float4 p4 = *(const float4*)&Ps[j * APAD + ty * 4];
            float4 v4 = *(const float4*)&Vs[j * APAD + tx * 4];
            float pv4[4] = {p4.x, p4.y, p4.z, p4.w};
            float vv4[4] = {v4.x, v4.y, v4.z, v4.w};
            #pragma unroll
            for (int i = 0; i < 4; ++i)
                #pragma unroll
                for (int d = 0; d < 4; ++d)
                    o[i][d] = fmaf(pv4[i], vv4[d], o[i][d]);
        }
    }

    // finalize: divide by l, write to out[b][s][h*64+d]
    #pragma unroll
    for (int i = 0; i < 4; ++i) {
        const float inv = 1.0f / lrowacc[i];
        const int sg = q0 + ty * 4 + i;
        size_t off = ((size_t)b * S_ + sg) * H_ + h * HD_ + tx * 4;
        float4 r = make_float4(o[i][0] * inv, o[i][1] * inv,
                               o[i][2] * inv, o[i][3] * inv);
        *(float4*)&out[off] = r;
    }
}

// ---------------------------------------------------------------------------
// Launch
// ---------------------------------------------------------------------------
extern "C" void kernel_launch(void* const* d_in, const int* in_sizes, int n_in,
                              void* d_out, int out_size)
{
    const float* hidden = (const float*)d_in[0];
    const float* amask  = (const float*)d_in[1];
    const float* Wq = (const float*)d_in[2];
    const float* bq = (const float*)d_in[3];
    const float* Wk = (const float*)d_in[4];
    const float* bk = (const float*)d_in[5];
    const float* Wv = (const float*)d_in[6];
    const float* bv = (const float*)d_in[7];
    float* out = (float*)d_out;

    // QKV projection: grid (N/64=16, M/64=128, 3)
    dim3 ggrid(H_ / 64, MROWS / 64, 3);
    qkv_gemm_kernel<<<ggrid, 256>>>(hidden, Wq, bq, Wk, bk, Wv, bv);

    // Attention: grid (32 q-tiles, 64 bh), 68KB dynamic smem
    const int smem_bytes = 4 * 64 * APAD * (int)sizeof(float);
    cudaFuncSetAttribute(attn_kernel,
                         cudaFuncAttributeMaxDynamicSharedMemorySize,
                         smem_bytes);
    dim3 agrid(S_ / 64, B_ * NH_);
    attn_kernel<<<agrid, 256, smem_bytes>>>(amask, out);
}

// round 3
// speedup vs baseline: 1.0251x; 1.0251x over previous
#include <cuda_runtime.h>
#include <cuda_bf16.h>
#include <cstdint>

// Problem constants
#define B_   4
#define S_   2048
#define H_   1024
#define NH_  16
#define HD_  64
#define MROWS (B_ * S_)        // 8192

// Scratch: Q,K,V in [B*NH, S, HD] layout (head-major), fp32.
__device__ float g_q[(size_t)B_ * NH_ * S_ * HD_];
__device__ float g_k[(size_t)B_ * NH_ * S_ * HD_];
__device__ float g_v[(size_t)B_ * NH_ * S_ * HD_];

// ---------------------------------------------------------------------------
// tf32 helpers
// ---------------------------------------------------------------------------
__device__ __forceinline__ uint32_t f2tf32(float x) {
    uint32_t r;
    asm("cvt.rna.tf32.f32 %0, %1;" : "=r"(r) : "f"(x));
    return r;
}

__device__ __forceinline__ void mma_tf32(float* d, const uint32_t* a, const uint32_t* b) {
    asm volatile(
        "mma.sync.aligned.m16n8k8.row.col.f32.tf32.tf32.f32 "
        "{%0,%1,%2,%3}, {%4,%5,%6,%7}, {%8,%9}, {%0,%1,%2,%3};"
        : "+f"(d[0]), "+f"(d[1]), "+f"(d[2]), "+f"(d[3])
        : "r"(a[0]), "r"(a[1]), "r"(a[2]), "r"(a[3]), "r"(b[0]), "r"(b[1]));
}

// Fast exp on the FMA pipe (no MUFU). Valid for x <= 0 (softmax deltas).
// 2^y with y = x*log2(e); Cephes-style deg-6 poly on f in [-0.5, 0.5].
__device__ __forceinline__ float fexp(float x) {
    float y = x * 1.4426950408889634f;
    y = fmaxf(y, -126.0f);
    int n = __float2int_rn(y);
    float f = y - (float)n;
    float p =            1.535336188319500e-4f;
    p = fmaf(p, f, 1.339887440266574e-3f);
    p = fmaf(p, f, 9.618437357674640e-3f);
    p = fmaf(p, f, 5.550332471162809e-2f);
    p = fmaf(p, f, 2.402264791363012e-1f);
    p = fmaf(p, f, 6.931472028550421e-1f);
    p = fmaf(p, f, 1.0f);
    return __int_as_float(__float_as_int(p) + (n << 23));
}

// ---------------------------------------------------------------------------
// Kernel 1: QKV projection on tensor cores (3xTF32 for fp32-grade accuracy).
// out[m][n] = sum_k X[m][k] * W[n][k] + bias[n]
// BM=128, BN=64, BK=8, 256 threads = 8 warps (4 m-warps x 2 n-warps),
// warp tile 32x32 = 2x4 mma tiles of m16n8k8. Double-buffered smem holding
// pre-split tf32 hi/lo parts. D = Ah*Bh + Ah*Bl + Al*Bh.
// Output head-transposed into g_q/g_k/g_v: [(b*NH+h)*S + s]*64 + d.
// ---------------------------------------------------------------------------
#define BMM 128
#define BNN 64
#define BKK 8
#define APADG 132   // BMM + 4
#define BPADG 68    // BNN + 4

__global__ __launch_bounds__(256)
void qkv_mma_kernel(const float* __restrict__ X,
                    const float* __restrict__ Wq, const float* __restrict__ bq,
                    const float* __restrict__ Wk, const float* __restrict__ bk,
                    const float* __restrict__ Wv, const float* __restrict__ bv)
{
    __shared__ uint32_t Ah[2][BKK][APADG];
    __shared__ uint32_t Al[2][BKK][APADG];
    __shared__ uint32_t Bh[2][BKK][BPADG];
    __shared__ uint32_t Bl[2][BKK][BPADG];

    const int z = blockIdx.z;
    const float* __restrict__ W    = (z == 0) ? Wq : (z == 1) ? Wk : Wv;
    const float* __restrict__ bias = (z == 0) ? bq : (z == 1) ? bk : bv;
    float* __restrict__ out        = (z == 0) ? g_q : (z == 1) ? g_k : g_v;

    const int n0 = blockIdx.x * BNN;
    const int m0 = blockIdx.y * BMM;
    const int tid  = threadIdx.x;
    const int lane = tid & 31;
    const int w    = tid >> 5;
    const int wm = (w >> 1) * 32;   // warp m offset (0,32,64,96)
    const int wn = (w & 1) * 32;    // warp n offset (0,32)
    const int g = lane >> 2;        // 0..7
    const int t = lane & 3;         // 0..3

    // loaders
    const int lrA = tid >> 1;            // 0..127
    const int lcA = (tid & 1) * 4;       // 0 or 4
    const bool bload = tid < 128;
    const int lrB = (tid & 127) >> 1;    // 0..63
    const int lcB = (tid & 1) * 4;

    float acc[2][4][4] = {};

    // prologue: global load k-slice 0
    float4 xa = *(const float4*)&X[(size_t)(m0 + lrA) * H_ + lcA];
    float4 wb = make_float4(0.f, 0.f, 0.f, 0.f);
    if (bload) wb = *(const float4*)&W[(size_t)(n0 + lrB) * H_ + lcB];

    {
        const float* xs = &xa.x;
        #pragma unroll
        for (int i = 0; i < 4; ++i) {
            float v = xs[i];
            uint32_t hi = f2tf32(v);
            Ah[0][lcA + i][lrA] = hi;
            Al[0][lcA + i][lrA] = f2tf32(v - __uint_as_float(hi));
        }
        if (bload) {
            const float* ws = &wb.x;
            #pragma unroll
            for (int i = 0; i < 4; ++i) {
                float v = ws[i];
                uint32_t hi = f2tf32(v);
                Bh[0][lcB + i][lrB] = hi;
                Bl[0][lcB + i][lrB] = f2tf32(v - __uint_as_float(hi));
            }
        }
    }
    __syncthreads();

    const int NKT = H_ / BKK;   // 128
    for (int kt = 0; kt < NKT; ++kt) {
        const int st = kt & 1;
        float4 xn, wn4;
        if (kt < NKT - 1) {
            const int k0 = (kt + 1) * BKK;
            xn = *(const float4*)&X[(size_t)(m0 + lrA) * H_ + k0 + lcA];
            if (bload) wn4 = *(const float4*)&W[(size_t)(n0 + lrB) * H_ + k0 + lcB];
        }

        // load fragments
        uint32_t af[2][4], alf[2][4];
        #pragma unroll
        for (int mt = 0; mt < 2; ++mt) {
            const int mb = wm + mt * 16 + g;
            af[mt][0]  = Ah[st][t][mb];     af[mt][1]  = Ah[st][t][mb + 8];
            af[mt][2]  = Ah[st][t + 4][mb]; af[mt][3]  = Ah[st][t + 4][mb + 8];
            alf[mt][0] = Al[st][t][mb];     alf[mt][1] = Al[st][t][mb + 8];
            alf[mt][2] = Al[st][t + 4][mb]; alf[mt][3] = Al[st][t + 4][mb + 8];
        }
        uint32_t bf[4][2], blf[4][2];
        #pragma unroll
        for (int nt = 0; nt < 4; ++nt) {
            const int nb = wn + nt * 8 + g;
            bf[nt][0]  = Bh[st][t][nb]; bf[nt][1]  = Bh[st][t + 4][nb];
            blf[nt][0] = Bl[st][t][nb]; blf[nt][1] = Bl[st][t + 4][nb];
        }

        #pragma unroll
        for (int mt = 0; mt < 2; ++mt)
            #pragma unroll
            for (int nt = 0; nt < 4; ++nt) {
                mma_tf32(acc[mt][nt], af[mt],  bf[nt]);
                mma_tf32(acc[mt][nt], af[mt],  blf[nt]);
                mma_tf32(acc[mt][nt], alf[mt], bf[nt]);
            }

        if (kt < NKT - 1) {
            const int sn = st ^ 1;
            const float* xs = &xn.x;
            #pragma unroll
            for (int i = 0; i < 4; ++i) {
                float v = xs[i];
                uint32_t hi = f2tf32(v);
                Ah[sn][lcA + i][lrA] = hi;
                Al[sn][lcA + i][lrA] = f2tf32(v - __uint_as_float(hi));
            }
            if (bload) {
                const float* ws = &wn4.x;
                #pragma unroll
                for (int i = 0; i < 4; ++i) {
                    float v = ws[i];
                    uint32_t hi = f2tf32(v);
                    Bh[sn][lcB + i][lrB] = hi;
                    Bl[sn][lcB + i][lrB] = f2tf32(v - __uint_as_float(hi));
                }
            }
        }
        __syncthreads();
    }

    // epilogue: bias + head-transposed store
    const int h    = blockIdx.x;        // n0/64 == head (BNN == HD)
    const int bidx = m0 >> 11;          // m0 / 2048
    float* outp = out + (((size_t)(bidx * NH_ + h)) * S_ + (m0 & (S_ - 1))) * HD_;
    #pragma unroll
    for (int mt = 0; mt < 2; ++mt) {
        #pragma unroll
        for (int nt = 0; nt < 4; ++nt) {
            const int c = wn + nt * 8 + t * 2;
            const float2 bi = *(const float2*)&bias[n0 + c];
            const int r0 = wm + mt * 16 + g;
            float2 v0 = make_float2(acc[mt][nt][0] + bi.x, acc[mt][nt][1] + bi.y);
            float2 v1 = make_float2(acc[mt][nt][2] + bi.x, acc[mt][nt][3] + bi.y);
            *(float2*)&outp[(size_t)r0 * HD_ + c]       = v0;
            *(float2*)&outp[(size_t)(r0 + 8) * HD_ + c] = v1;
        }
    }
}

// ---------------------------------------------------------------------------
// Kernel 2: causal flash attention, fp32 matmuls + FMA-pipe exp.
// Grid: (32 q-tiles, 64 b*h). 256 threads. Q tile = 64 rows, K/V tiles = 64.
//   probs = softmax( (where(j>i, -inf, qk) + amask[b,j]) / 8 )
// ---------------------------------------------------------------------------
#define APAD 68

__global__ __launch_bounds__(256, 3)
void attn_kernel(const float* __restrict__ amask, float* __restrict__ out)
{
    extern __shared__ float sm[];
    float* Qs = sm;                 // [64][APAD], d-major: Qs[d][i]
    float* Ks = Qs + 64 * APAD;     // [64][APAD], d-major: Ks[d][j]
    float* Vs = Ks + 64 * APAD;     // [64][APAD], natural:  Vs[j][d]
    float* Ps = Vs + 64 * APAD;     // [64][APAD], j-major:  Ps[j][i]

    const int qt = (int)gridDim.x - 1 - (int)blockIdx.x;  // heavy tiles first
    const int bh = blockIdx.y;
    const int b  = bh >> 4;
    const int h  = bh & 15;
    const int tid = threadIdx.x;
    const int tx = tid & 15;
    const int ty = tid >> 4;

    const float* __restrict__ qptr = g_q + (size_t)bh * S_ * HD_;
    const float* __restrict__ kptr = g_k + (size_t)bh * S_ * HD_;
    const float* __restrict__ vptr = g_v + (size_t)bh * S_ * HD_;
    const int q0 = qt * 64;

    // Load Q tile transposed into Qs[d][i]: 1024 float4 / 256 threads = 4 each.
    const int lrow = tid >> 2;               // 0..63
    const int lcb  = (tid & 3) * 16;         // 0,16,32,48
    {
        #pragma unroll
        for (int t = 0; t < 4; ++t) {
            const int c = lcb + t * 4;
            float4 v = *(const float4*)&qptr[(size_t)(q0 + lrow) * HD_ + c];
            Qs[(c + 0) * APAD + lrow] = v.x;
            Qs[(c + 1) * APAD + lrow] = v.y;
            Qs[(c + 2) * APAD + lrow] = v.z;
            Qs[(c + 3) * APAD + lrow] = v.w;
        }
    }

    float o[4][4] = {};
    float mrow[4] = {-1e30f, -1e30f, -1e30f, -1e30f};
    float lrowacc[4] = {};

    for (int kt = 0; kt <= qt; ++kt) {
        const int j0 = kt * 64;
        __syncthreads();
        {
            #pragma unroll
            for (int t = 0; t < 4; ++t) {
                const int c = lcb + t * 4;
                float4 kv = *(const float4*)&kptr[(size_t)(j0 + lrow) * HD_ + c];
                Ks[(c + 0) * APAD + lrow] = kv.x;
                Ks[(c + 1) * APAD + lrow] = kv.y;
                Ks[(c + 2) * APAD + lrow] = kv.z;
                Ks[(c + 3) * APAD + lrow] = kv.w;
                float4 vv = *(const float4*)&vptr[(size_t)(j0 + lrow) * HD_ + c];
                *(float4*)&Vs[lrow * APAD + c] = vv;
            }
        }
        __syncthreads();

        // S = Q @ K^T
        float s[4][4] = {};
        #pragma unroll 16
        for (int d = 0; d < HD_; ++d) {
            float4 a4 = *(const float4*)&Qs[d * APAD + ty * 4];
            float4 b4 = *(const float4*)&Ks[d * APAD + tx * 4];
            float av[4] = {a4.x, a4.y, a4.z, a4.w};
            float bv4[4] = {b4.x, b4.y, b4.z, b4.w};
            #pragma unroll
            for (int i = 0; i < 4; ++i)
                #pragma unroll
                for (int j = 0; j < 4; ++j)
                    s[i][j] = fmaf(av[i], bv4[j], s[i][j]);
        }

        const float4 am4 = *(const float4*)&amask[(size_t)b * S_ + j0 + tx * 4];
        const float am[4] = {am4.x, am4.y, am4.z, am4.w};

        float p[4][4];
        #pragma unroll
        for (int i = 0; i < 4; ++i) {
            const int gi = q0 + ty * 4 + i;
            float rm = -1e30f;
            #pragma unroll
            for (int j = 0; j < 4; ++j) {
                const int gj = j0 + tx * 4 + j;
                float v = (s[i][j] + am[j]) * 0.125f;
                if (gj > gi) v = -1e30f;   // causal mask
                s[i][j] = v;
                rm = fmaxf(rm, v);
            }
            #pragma unroll
            for (int off = 1; off < 16; off <<= 1)
                rm = fmaxf(rm, __shfl_xor_sync(0xffffffffu, rm, off));

            const float mnew = fmaxf(mrow[i], rm);
            const float corr = fexp(mrow[i] - mnew);
            float rs = 0.f;
            #pragma unroll
            for (int j = 0; j < 4; ++j) {
                float pv = fexp(s[i][j] - mnew);
                p[i][j] = pv;
                rs += pv;
            }
            #pragma unroll
            for (int off = 1; off < 16; off <<= 1)
                rs += __shfl_xor_sync(0xffffffffu, rs, off);

            lrowacc[i] = lrowacc[i] * corr + rs;
            mrow[i] = mnew;
            #pragma unroll
            for (int d = 0; d < 4; ++d) o[i][d] *= corr;
        }

        // stage P transposed: Ps[j][i]
        #pragma unroll
        for (int i = 0; i < 4; ++i)
            #pragma unroll
            for (int j = 0; j < 4; ++j)
                Ps[(tx * 4 + j) * APAD + (ty * 4 + i)] = p[i][j];
        __syncthreads();

        // O += P @ V
        #pragma unroll 16
        for (int j = 0; j < 64; ++j) {
            float4 p4 = *(const float4*)&Ps[j * APAD + ty * 4];
            float4 v4 = *(const float4*)&Vs[j * APAD + tx * 4];
            float pv4[4] = {p4.x, p4.y, p4.z, p4.w};
            float vv4[4] = {v4.x, v4.y, v4.z, v4.w};
            #pragma unroll
            for (int i = 0; i < 4; ++i)
                #pragma unroll
                for (int d = 0; d < 4; ++d)
                    o[i][d] = fmaf(pv4[i], vv4[d], o[i][d]);
        }
    }

    // finalize
    #pragma unroll
    for (int i = 0; i < 4; ++i) {
        const float inv = 1.0f / lrowacc[i];
        const int sg = q0 + ty * 4 + i;
        size_t off = ((size_t)b * S_ + sg) * H_ + h * HD_ + tx * 4;
        float4 r = make_float4(o[i][0] * inv, o[i][1] * inv,
                               o[i][2] * inv, o[i][3] * inv);
        *(float4*)&out[off] = r;
    }
}

// ---------------------------------------------------------------------------
// Launch
// ---------------------------------------------------------------------------
extern "C" void kernel_launch(void* const* d_in, const int* in_sizes, int n_in,
                              void* d_out, int out_size)
{
    const float* hidden = (const float*)d_in[0];
    const float* amask  = (const float*)d_in[1];
    const float* Wq = (const float*)d_in[2];
    const float* bq = (const float*)d_in[3];
    const float* Wk = (const float*)d_in[4];
    const float* bk = (const float*)d_in[5];
    const float* Wv = (const float*)d_in[6];
    const float* bv = (const float*)d_in[7];
    float* out = (float*)d_out;

    // QKV projection: grid (H/64=16, M/128=64, 3)
    dim3 ggrid(H_ / BNN, MROWS / BMM, 3);
    qkv_mma_kernel<<<ggrid, 256>>>(hidden, Wq, bq, Wk, bk, Wv, bv);

    // Attention: grid (32 q-tiles, 64 bh), 68KB dynamic smem
    const int smem_bytes = 4 * 64 * APAD * (int)sizeof(float);
    cudaFuncSetAttribute(attn_kernel,
                         cudaFuncAttributeMaxDynamicSharedMemorySize,
                         smem_bytes);
    dim3 agrid(S_ / 64, B_ * NH_);
    attn_kernel<<<agrid, 256, smem_bytes>>>(amask, out);
}

// round 4
// speedup vs baseline: 2.5280x; 2.4661x over previous
#include <cuda_runtime.h>
#include <cuda_bf16.h>
#include <cstdint>

// Problem constants
#define B_   4
#define S_   2048
#define H_   1024
#define NH_  16
#define HD_  64
#define MROWS (B_ * S_)        // 8192

// ---------------------------------------------------------------------------
// Scratch (device globals; no allocation allowed)
// ---------------------------------------------------------------------------
__device__ __nv_bfloat16 g_xh[(size_t)MROWS * H_];
__device__ __nv_bfloat16 g_xl[(size_t)MROWS * H_];
__device__ __nv_bfloat16 g_wh[3][(size_t)H_ * H_];
__device__ __nv_bfloat16 g_wl[3][(size_t)H_ * H_];
// Q,K: [bh][s][d]    V: transposed [bh][d][s]
__device__ __nv_bfloat16 g_qh[(size_t)B_ * NH_ * S_ * HD_];
__device__ __nv_bfloat16 g_ql[(size_t)B_ * NH_ * S_ * HD_];
__device__ __nv_bfloat16 g_kh[(size_t)B_ * NH_ * S_ * HD_];
__device__ __nv_bfloat16 g_kl[(size_t)B_ * NH_ * S_ * HD_];
__device__ __nv_bfloat16 g_vth[(size_t)B_ * NH_ * S_ * HD_];
__device__ __nv_bfloat16 g_vtl[(size_t)B_ * NH_ * S_ * HD_];

// ---------------------------------------------------------------------------
// helpers
// ---------------------------------------------------------------------------
__device__ __forceinline__ void mma_bf16(float* d, const uint32_t* a, const uint32_t* b) {
    asm volatile(
        "mma.sync.aligned.m16n8k16.row.col.f32.bf16.bf16.f32 "
        "{%0,%1,%2,%3},{%4,%5,%6,%7},{%8,%9},{%0,%1,%2,%3};"
        : "+f"(d[0]), "+f"(d[1]), "+f"(d[2]), "+f"(d[3])
        : "r"(a[0]), "r"(a[1]), "r"(a[2]), "r"(a[3]), "r"(b[0]), "r"(b[1]));
}

// split two floats into packed bf16 hi-pair and lo-pair (low half = first elem)
__device__ __forceinline__ void split2(float a, float b, uint32_t& hi, uint32_t& lo) {
    __nv_bfloat16 ha = __float2bfloat16_rn(a);
    __nv_bfloat16 hb = __float2bfloat16_rn(b);
    __nv_bfloat16 la = __float2bfloat16_rn(a - __bfloat162float(ha));
    __nv_bfloat16 lb = __float2bfloat16_rn(b - __bfloat162float(hb));
    __nv_bfloat162 hv; hv.x = ha; hv.y = hb;
    __nv_bfloat162 lv; lv.x = la; lv.y = lb;
    hi = *(uint32_t*)&hv;
    lo = *(uint32_t*)&lv;
}

// FMA-pipe exp (valid x <= 0)
__device__ __forceinline__ float fexp(float x) {
    float y = x * 1.4426950408889634f;
    y = fmaxf(y, -126.0f);
    int n = __float2int_rn(y);
    float f = y - (float)n;
    float p =            1.535336188319500e-4f;
    p = fmaf(p, f, 1.339887440266574e-3f);
    p = fmaf(p, f, 9.618437357674640e-3f);
    p = fmaf(p, f, 5.550332471162809e-2f);
    p = fmaf(p, f, 2.402264791363012e-1f);
    p = fmaf(p, f, 6.931472028550421e-1f);
    p = fmaf(p, f, 1.0f);
    return __int_as_float(__float_as_int(p) + (n << 23));
}

// ---------------------------------------------------------------------------
// Kernel 0: fp32 -> bf16 hi/lo split prepass.
// which: 0 = X, 1..3 = Wq/Wk/Wv
// ---------------------------------------------------------------------------
__global__ void split_kernel(const float* __restrict__ src, int which, int n4)
{
    int i = blockIdx.x * blockDim.x + threadIdx.x;
    if (i >= n4) return;
    __nv_bfloat16* dh;
    __nv_bfloat16* dl;
    if (which == 0) { dh = g_xh; dl = g_xl; }
    else            { dh = g_wh[which - 1]; dl = g_wl[which - 1]; }
    float4 v = ((const float4*)src)[i];
    uint32_t h0, l0, h1, l1;
    split2(v.x, v.y, h0, l0);
    split2(v.z, v.w, h1, l1);
    uint32_t* dh32 = (uint32_t*)dh;
    uint32_t* dl32 = (uint32_t*)dl;
    dh32[i * 2] = h0; dh32[i * 2 + 1] = h1;
    dl32[i * 2] = l0; dl32[i * 2 + 1] = l1;
}

// ---------------------------------------------------------------------------
// Kernel 1: QKV projection, bf16 split (3 MMA terms), m16n8k16.
// BM=128, BN=64, BK=32, 256 thr = 8 warps (4m x 2n), warp tile 32x32.
// out = X @ W^T + b, stored split-bf16; V stored transposed [bh][d][s].
// ---------------------------------------------------------------------------
#define GSTR 40      // smem k-stride in bf16 elems (80B)

__global__ __launch_bounds__(256, 2)
void qkv_kernel(const float* __restrict__ bq,
                const float* __restrict__ bk,
                const float* __restrict__ bv)
{
    extern __shared__ __nv_bfloat16 sg[];
    __nv_bfloat16* sAh = sg;            // [2][128][GSTR]
    __nv_bfloat16* sAl = sg + 10240;
    __nv_bfloat16* sBh = sg + 20480;    // [2][64][GSTR]
    __nv_bfloat16* sBl = sg + 25600;

    const int z = blockIdx.z;
    const __nv_bfloat16* __restrict__ Bh_g = g_wh[z];
    const __nv_bfloat16* __restrict__ Bl_g = g_wl[z];
    const float* __restrict__ bias = (z == 0) ? bq : (z == 1) ? bk : bv;

    const int n0 = blockIdx.x * 64;
    const int m0 = blockIdx.y * 128;
    const int tid  = threadIdx.x;
    const int lane = tid & 31;
    const int w    = tid >> 5;
    const int wm = (w >> 1) * 32;
    const int wn = (w & 1) * 32;
    const int g = lane >> 2;
    const int t = lane & 3;

    // loader indices
    const int rA0 = tid >> 2;           // rows for A (i=0): 0..63; i=1: +64
    const int bA  = tid & 3;            // k-block (8 elems)
    const int rB  = tid >> 2;           // 0..63
    const int bB  = tid & 3;

    float acc[2][4][4] = {};

    uint4 rah[2], ral[2], rbh, rbl;
    // prologue: load kt=0
    #pragma unroll
    for (int i = 0; i < 2; ++i) {
        const int r = rA0 + i * 64;
        rah[i] = *(const uint4*)&g_xh[(size_t)(m0 + r) * H_ + bA * 8];
        ral[i] = *(const uint4*)&g_xl[(size_t)(m0 + r) * H_ + bA * 8];
    }
    rbh = *(const uint4*)&Bh_g[(size_t)(n0 + rB) * H_ + bB * 8];
    rbl = *(const uint4*)&Bl_g[(size_t)(n0 + rB) * H_ + bB * 8];
    #pragma unroll
    for (int i = 0; i < 2; ++i) {
        const int r = rA0 + i * 64;
        *(uint4*)&sAh[r * GSTR + bA * 8] = rah[i];
        *(uint4*)&sAl[r * GSTR + bA * 8] = ral[i];
    }
    *(uint4*)&sBh[rB * GSTR + bB * 8] = rbh;
    *(uint4*)&sBl[rB * GSTR + bB * 8] = rbl;
    __syncthreads();

    const int NKT = H_ / 32;  // 32
    for (int kt = 0; kt < NKT; ++kt) {
        const int st = kt & 1;
        if (kt < NKT - 1) {
            const int k0 = (kt + 1) * 32;
            #pragma unroll
            for (int i = 0; i < 2; ++i) {
                const int r = rA0 + i * 64;
                rah[i] = *(const uint4*)&g_xh[(size_t)(m0 + r) * H_ + k0 + bA * 8];
                ral[i] = *(const uint4*)&g_xl[(size_t)(m0 + r) * H_ + k0 + bA * 8];
            }
            rbh = *(const uint4*)&Bh_g[(size_t)(n0 + rB) * H_ + k0 + bB * 8];
            rbl = *(const uint4*)&Bl_g[(size_t)(n0 + rB) * H_ + k0 + bB * 8];
        }

        const __nv_bfloat16* Ah = sAh + st * 5120;
        const __nv_bfloat16* Al = sAl + st * 5120;
        const __nv_bfloat16* Bh = sBh + st * 2560;
        const __nv_bfloat16* Bl = sBl + st * 2560;

        #pragma unroll
        for (int ks = 0; ks < 2; ++ks) {
            const int kc = ks * 16 + 2 * t;
            uint32_t ah[2][4], al[2][4];
            #pragma unroll
            for (int mt = 0; mt < 2; ++mt) {
                const int m = wm + mt * 16 + g;
                ah[mt][0] = *(const uint32_t*)&Ah[m * GSTR + kc];
                ah[mt][1] = *(const uint32_t*)&Ah[(m + 8) * GSTR + kc];
                ah[mt][2] = *(const uint32_t*)&Ah[m * GSTR + kc + 8];
                ah[mt][3] = *(const uint32_t*)&Ah[(m + 8) * GSTR + kc + 8];
                al[mt][0] = *(const uint32_t*)&Al[m * GSTR + kc];
                al[mt][1] = *(const uint32_t*)&Al[(m + 8) * GSTR + kc];
                al[mt][2] = *(const uint32_t*)&Al[m * GSTR + kc + 8];
                al[mt][3] = *(const uint32_t*)&Al[(m + 8) * GSTR + kc + 8];
            }
            uint32_t bh2[4][2], bl2[4][2];
            #pragma unroll
            for (int nt = 0; nt < 4; ++nt) {
                const int n = wn + nt * 8 + g;
                bh2[nt][0] = *(const uint32_t*)&Bh[n * GSTR + kc];
                bh2[nt][1] = *(const uint32_t*)&Bh[n * GSTR + kc + 8];
                bl2[nt][0] = *(const uint32_t*)&Bl[n * GSTR + kc];
                bl2[nt][1] = *(const uint32_t*)&Bl[n * GSTR + kc + 8];
            }
            #pragma unroll
            for (int mt = 0; mt < 2; ++mt)
                #pragma unroll
                for (int nt = 0; nt < 4; ++nt) {
                    mma_bf16(acc[mt][nt], ah[mt], bh2[nt]);
                    mma_bf16(acc[mt][nt], ah[mt], bl2[nt]);
                    mma_bf16(acc[mt][nt], al[mt], bh2[nt]);
                }
        }

        if (kt < NKT - 1) {
            const int sn = st ^ 1;
            #pragma unroll
            for (int i = 0; i < 2; ++i) {
                const int r = rA0 + i * 64;
                *(uint4*)&sAh[sn * 5120 + r * GSTR + bA * 8] = rah[i];
                *(uint4*)&sAl[sn * 5120 + r * GSTR + bA * 8] = ral[i];
            }
            *(uint4*)&sBh[sn * 2560 + rB * GSTR + bB * 8] = rbh;
            *(uint4*)&sBl[sn * 2560 + rB * GSTR + bB * 8] = rbl;
        }
        __syncthreads();
    }

    // epilogue
    const int h    = blockIdx.x;          // BN == HD
    const int bidx = m0 >> 11;
    const int bh_i = bidx * NH_ + h;
    const int sbase = (m0 & (S_ - 1));
    #pragma unroll
    for (int mt = 0; mt < 2; ++mt) {
        #pragma unroll
        for (int nt = 0; nt < 4; ++nt) {
            const int c = wn + nt * 8 + 2 * t;
            const float2 bi = *(const float2*)&bias[n0 + c];
            const int s0 = sbase + wm + mt * 16 + g;
            const float v0 = acc[mt][nt][0] + bi.x;
            const float v1 = acc[mt][nt][1] + bi.y;
            const float v2 = acc[mt][nt][2] + bi.x;
            const float v3 = acc[mt][nt][3] + bi.y;
            if (z < 2) {
                __nv_bfloat16* dh = (z == 0) ? g_qh : g_kh;
                __nv_bfloat16* dl = (z == 0) ? g_ql : g_kl;
                uint32_t h01, l01, h23, l23;
                split2(v0, v1, h01, l01);
                split2(v2, v3, h23, l23);
                *(uint32_t*)&dh[((size_t)bh_i * S_ + s0) * HD_ + c]     = h01;
                *(uint32_t*)&dl[((size_t)bh_i * S_ + s0) * HD_ + c]     = l01;
                *(uint32_t*)&dh[((size_t)bh_i * S_ + s0 + 8) * HD_ + c] = h23;
                *(uint32_t*)&dl[((size_t)bh_i * S_ + s0 + 8) * HD_ + c] = l23;
            } else {
                // V transposed: [bh][d][s]
                #pragma unroll
                for (int e = 0; e < 4; ++e) {
                    const float v = (e == 0) ? v0 : (e == 1) ? v1 : (e == 2) ? v2 : v3;
                    const int d = c + (e & 1);
                    const int s = s0 + ((e >> 1) * 8);
                    __nv_bfloat16 hv = __float2bfloat16_rn(v);
                    __nv_bfloat16 lv = __float2bfloat16_rn(v - __bfloat162float(hv));
                    g_vth[((size_t)bh_i * HD_ + d) * S_ + s] = hv;
                    g_vtl[((size_t)bh_i * HD_ + d) * S_ + s] = lv;
                }
            }
        }
    }
}

// ---------------------------------------------------------------------------
// Kernel 2: causal flash attention on tensor cores (bf16 split, 3 terms).
// CTA: 128 q rows x (64-col kv tiles), 8 warps each own 16 q rows.
// ---------------------------------------------------------------------------
#define QSTR 72      // smem stride (bf16 elems), 144B

__global__ __launch_bounds__(256)
void attn_kernel(const float* __restrict__ amask, float* __restrict__ out)
{
    extern __shared__ __nv_bfloat16 smb[];
    __nv_bfloat16* sQh = smb;             // [128][QSTR]
    __nv_bfloat16* sQl = smb + 9216;
    __nv_bfloat16* sKh = smb + 18432;     // [64][QSTR]
    __nv_bfloat16* sKl = smb + 23040;
    __nv_bfloat16* sVh = smb + 27648;     // [64][QSTR] rows = d
    __nv_bfloat16* sVl = smb + 32256;
    float* sAm = (float*)(smb + 36864);   // [64]

    const int qt = 15 - (int)blockIdx.x;  // heavy tiles first
    const int bh = blockIdx.y;
    const int b  = bh >> 4;
    const int h  = bh & 15;
    const int q0 = qt * 128;
    const int tid  = threadIdx.x;
    const int lane = tid & 31;
    const int w    = tid >> 5;
    const int g = lane >> 2;
    const int t = lane & 3;

    // load Q tile (128 x 64, hi+lo)
    #pragma unroll
    for (int i = 0; i < 4; ++i) {
        const int idx = i * 256 + tid;
        const int r = idx >> 3, bk2 = idx & 7;
        *(uint4*)&sQh[r * QSTR + bk2 * 8] =
            *(const uint4*)&g_qh[((size_t)bh * S_ + q0 + r) * HD_ + bk2 * 8];
        *(uint4*)&sQl[r * QSTR + bk2 * 8] =
            *(const uint4*)&g_ql[((size_t)bh * S_ + q0 + r) * HD_ + bk2 * 8];
    }

    float o[8][4] = {};
    float m0r = -1e30f, m1r = -1e30f;
    float l0r = 0.f, l1r = 0.f;
    const int i0 = q0 + w * 16 + g;
    const int i1 = i0 + 8;

    const int nkv = 2 * qt + 2;
    for (int kt = 0; kt < nkv; ++kt) {
        const int j0 = kt * 64;
        __syncthreads();
        #pragma unroll
        for (int i = 0; i < 2; ++i) {
            const int idx = i * 256 + tid;
            const int r = idx >> 3, bk2 = idx & 7;
            *(uint4*)&sKh[r * QSTR + bk2 * 8] =
                *(const uint4*)&g_kh[((size_t)bh * S_ + j0 + r) * HD_ + bk2 * 8];
            *(uint4*)&sKl[r * QSTR + bk2 * 8] =
                *(const uint4*)&g_kl[((size_t)bh * S_ + j0 + r) * HD_ + bk2 * 8];
            *(uint4*)&sVh[r * QSTR + bk2 * 8] =
                *(const uint4*)&g_vth[((size_t)bh * HD_ + r) * S_ + j0 + bk2 * 8];
            *(uint4*)&sVl[r * QSTR + bk2 * 8] =
                *(const uint4*)&g_vtl[((size_t)bh * HD_ + r) * S_ + j0 + bk2 * 8];
        }
        if (tid < 16)
            *(float4*)&sAm[tid * 4] = *(const float4*)&amask[(size_t)b * S_ + j0 + tid * 4];
        __syncthreads();

        // warps whose rows are all < j0 contribute nothing (fully masked)
        if (j0 > q0 + w * 16 + 15) continue;

        // ---- S = Q @ K^T ----
        float s[8][4] = {};
        #pragma unroll
        for (int ks = 0; ks < 4; ++ks) {
            const int kc = ks * 16 + 2 * t;
            const int qr = w * 16 + g;
            uint32_t qh4[4], ql4[4];
            qh4[0] = *(const uint32_t*)&sQh[qr * QSTR + kc];
            qh4[1] = *(const uint32_t*)&sQh[(qr + 8) * QSTR + kc];
            qh4[2] = *(const uint32_t*)&sQh[qr * QSTR + kc + 8];
            qh4[3] = *(const uint32_t*)&sQh[(qr + 8) * QSTR + kc + 8];
            ql4[0] = *(const uint32_t*)&sQl[qr * QSTR + kc];
            ql4[1] = *(const uint32_t*)&sQl[(qr + 8) * QSTR + kc];
            ql4[2] = *(const uint32_t*)&sQl[qr * QSTR + kc + 8];
            ql4[3] = *(const uint32_t*)&sQl[(qr + 8) * QSTR + kc + 8];
            #pragma unroll
            for (int ntj = 0; ntj < 8; ++ntj) {
                const int kr = ntj * 8 + g;
                uint32_t kb[2], kbl[2];
                kb[0]  = *(const uint32_t*)&sKh[kr * QSTR + kc];
                kb[1]  = *(const uint32_t*)&sKh[kr * QSTR + kc + 8];
                kbl[0] = *(const uint32_t*)&sKl[kr * QSTR + kc];
                kbl[1] = *(const uint32_t*)&sKl[kr * QSTR + kc + 8];
                mma_bf16(s[ntj], qh4, kb);
                mma_bf16(s[ntj], qh4, kbl);
                mma_bf16(s[ntj], ql4, kb);
            }
        }

        // ---- mask + online softmax ----
        const bool needm = (j0 + 63 > q0 + w * 16);
        float rm0 = -1e30f, rm1 = -1e30f;
        #pragma unroll
        for (int ntj = 0; ntj < 8; ++ntj) {
            const float2 am = *(const float2*)&sAm[ntj * 8 + 2 * t];
            const int j = j0 + ntj * 8 + 2 * t;
            float v0 = (s[ntj][0] + am.x) * 0.125f;
            float v1 = (s[ntj][1] + am.y) * 0.125f;
            float v2 = (s[ntj][2] + am.x) * 0.125f;
            float v3 = (s[ntj][3] + am.y) * 0.125f;
            if (needm) {
                if (j     > i0) v0 = -1e30f;
                if (j + 1 > i0) v1 = -1e30f;
                if (j     > i1) v2 = -1e30f;
                if (j + 1 > i1) v3 = -1e30f;
            }
            s[ntj][0] = v0; s[ntj][1] = v1; s[ntj][2] = v2; s[ntj][3] = v3;
            rm0 = fmaxf(rm0, fmaxf(v0, v1));
            rm1 = fmaxf(rm1, fmaxf(v2, v3));
        }
        rm0 = fmaxf(rm0, __shfl_xor_sync(0xffffffffu, rm0, 1));
        rm0 = fmaxf(rm0, __shfl_xor_sync(0xffffffffu, rm0, 2));
        rm1 = fmaxf(rm1, __shfl_xor_sync(0xffffffffu, rm1, 1));
        rm1 = fmaxf(rm1, __shfl_xor_sync(0xffffffffu, rm1, 2));

        const float mn0 = fmaxf(m0r, rm0);
        const float mn1 = fmaxf(m1r, rm1);
        const float c0 = fexp(m0r - mn0);
        const float c1 = fexp(m1r - mn1);
        m0r = mn0; m1r = mn1;

        float rs0 = 0.f, rs1 = 0.f;
        #pragma unroll
        for (int ntj = 0; ntj < 8; ++ntj) {
            float p0 = fexp(s[ntj][0] - mn0);
            float p1 = fexp(s[ntj][1] - mn0);
            float p2 = fexp(s[ntj][2] - mn1);
            float p3 = fexp(s[ntj][3] - mn1);
            s[ntj][0] = p0; s[ntj][1] = p1; s[ntj][2] = p2; s[ntj][3] = p3;
            rs0 += p0 + p1;
            rs1 += p2 + p3;
        }
        rs0 += __shfl_xor_sync(0xffffffffu, rs0, 1);
        rs0 += __shfl_xor_sync(0xffffffffu, rs0, 2);
        rs1 += __shfl_xor_sync(0xffffffffu, rs1, 1);
        rs1 += __shfl_xor_sync(0xffffffffu, rs1, 2);
        l0r = l0r * c0 + rs0;
        l1r = l1r * c1 + rs1;
        #pragma unroll
        for (int ntd = 0; ntd < 8; ++ntd) {
            o[ntd][0] *= c0; o[ntd][1] *= c0;
            o[ntd][2] *= c1; o[ntd][3] *= c1;
        }

        // ---- pack P to A-fragments (hi/lo) — C layout == A layout ----
        uint32_t pah[4][4], pal[4][4];
        #pragma unroll
        for (int ks = 0; ks < 4; ++ks) {
            split2(s[2 * ks][0],     s[2 * ks][1],     pah[ks][0], pal[ks][0]);
            split2(s[2 * ks][2],     s[2 * ks][3],     pah[ks][1], pal[ks][1]);
            split2(s[2 * ks + 1][0], s[2 * ks + 1][1], pah[ks][2], pal[ks][2]);
            split2(s[2 * ks + 1][2], s[2 * ks + 1][3], pah[ks][3], pal[ks][3]);
        }

        // ---- O += P @ V ----
        #pragma unroll
        for (int ks = 0; ks < 4; ++ks) {
            const int kc = ks * 16 + 2 * t;
            #pragma unroll
            for (int ntd = 0; ntd < 8; ++ntd) {
                const int vr = ntd * 8 + g;
                uint32_t vb[2], vbl[2];
                vb[0]  = *(const uint32_t*)&sVh[vr * QSTR + kc];
                vb[1]  = *(const uint32_t*)&sVh[vr * QSTR + kc + 8];
                vbl[0] = *(const uint32_t*)&sVl[vr * QSTR + kc];
                vbl[1] = *(const uint32_t*)&sVl[vr * QSTR + kc + 8];
                mma_bf16(o[ntd], pah[ks], vb);
                mma_bf16(o[ntd], pah[ks], vbl);
                mma_bf16(o[ntd], pal[ks], vb);
            }
        }
    }

    // epilogue: normalize, store [b][s][h*64+d]
    const float inv0 = 1.0f / l0r;
    const float inv1 = 1.0f / l1r;
    #pragma unroll
    for (int ntd = 0; ntd < 8; ++ntd) {
        const int d = h * HD_ + ntd * 8 + 2 * t;
        float2 r0 = make_float2(o[ntd][0] * inv0, o[ntd][1] * inv0);
        float2 r1 = make_float2(o[ntd][2] * inv1, o[ntd][3] * inv1);
        *(float2*)&out[((size_t)b * S_ + i0) * H_ + d] = r0;
        *(float2*)&out[((size_t)b * S_ + i1) * H_ + d] = r1;
    }
}

// ---------------------------------------------------------------------------
// Launch
// ---------------------------------------------------------------------------
extern "C" void kernel_launch(void* const* d_in, const int* in_sizes, int n_in,
                              void* d_out, int out_size)
{
    const float* hidden = (const float*)d_in[0];
    const float* amask  = (const float*)d_in[1];
    const float* Wq = (const float*)d_in[2];
    const float* bq = (const float*)d_in[3];
    const float* Wk = (const float*)d_in[4];
    const float* bk = (const float*)d_in[5];
    const float* Wv = (const float*)d_in[6];
    const float* bv = (const float*)d_in[7];
    float* out = (float*)d_out;

    // prepass splits
    split_kernel<<<(MROWS * H_ / 4 + 255) / 256, 256>>>(hidden, 0, MROWS * H_ / 4);
    split_kernel<<<(H_ * H_ / 4 + 255) / 256, 256>>>(Wq, 1, H_ * H_ / 4);
    split_kernel<<<(H_ * H_ / 4 + 255) / 256, 256>>>(Wk, 2, H_ * H_ / 4);
    split_kernel<<<(H_ * H_ / 4 + 255) / 256, 256>>>(Wv, 3, H_ * H_ / 4);

    // QKV projection
    const int gsm = 61440;
    cudaFuncSetAttribute(qkv_kernel, cudaFuncAttributeMaxDynamicSharedMemorySize, gsm);
    dim3 ggrid(H_ / 64, MROWS / 128, 3);
    qkv_kernel<<<ggrid, 256, gsm>>>(bq, bk, bv);

    // attention
    const int asm_ = 73984;
    cudaFuncSetAttribute(attn_kernel, cudaFuncAttributeMaxDynamicSharedMemorySize, asm_);
    dim3 agrid(S_ / 128, B_ * NH_);
    attn_kernel<<<agrid, 256, asm_>>>(amask, out);
}

// round 6
// speedup vs baseline: 2.7174x; 1.0749x over previous
#include <cuda_runtime.h>
#include <cuda_bf16.h>
#include <cstdint>

// Problem constants
#define B_   4
#define S_   2048
#define H_   1024
#define NH_  16
#define HD_  64
#define MROWS (B_ * S_)        // 8192

// ---------------------------------------------------------------------------
// Scratch (device globals; no allocation allowed)
// ---------------------------------------------------------------------------
__device__ __nv_bfloat16 g_xh[(size_t)MROWS * H_];
__device__ __nv_bfloat16 g_xl[(size_t)MROWS * H_];
__device__ __nv_bfloat16 g_wh[3][(size_t)H_ * H_];
__device__ __nv_bfloat16 g_wl[3][(size_t)H_ * H_];
// Q,K: [bh][s][d]    V: transposed [bh][d][s]
__device__ __nv_bfloat16 g_qh[(size_t)B_ * NH_ * S_ * HD_];
__device__ __nv_bfloat16 g_ql[(size_t)B_ * NH_ * S_ * HD_];
__device__ __nv_bfloat16 g_kh[(size_t)B_ * NH_ * S_ * HD_];
__device__ __nv_bfloat16 g_kl[(size_t)B_ * NH_ * S_ * HD_];
__device__ __nv_bfloat16 g_vth[(size_t)B_ * NH_ * S_ * HD_];
__device__ __nv_bfloat16 g_vtl[(size_t)B_ * NH_ * S_ * HD_];

// ---------------------------------------------------------------------------
// helpers
// ---------------------------------------------------------------------------
__device__ __forceinline__ void mma_bf16(float* d, const uint32_t* a, const uint32_t* b) {
    asm volatile(
        "mma.sync.aligned.m16n8k16.row.col.f32.bf16.bf16.f32 "
        "{%0,%1,%2,%3},{%4,%5,%6,%7},{%8,%9},{%0,%1,%2,%3};"
        : "+f"(d[0]), "+f"(d[1]), "+f"(d[2]), "+f"(d[3])
        : "r"(a[0]), "r"(a[1]), "r"(a[2]), "r"(a[3]), "r"(b[0]), "r"(b[1]));
}

__device__ __forceinline__ void ldsm4(uint32_t* r, uint32_t addr) {
    asm volatile(
        "ldmatrix.sync.aligned.m8n8.x4.shared.b16 {%0,%1,%2,%3}, [%4];"
        : "=r"(r[0]), "=r"(r[1]), "=r"(r[2]), "=r"(r[3]) : "r"(addr));
}

__device__ __forceinline__ uint32_t smem_u32(const void* p) {
    uint32_t a;
    asm("{ .reg .u64 tmp; cvta.to.shared.u64 tmp, %1; cvt.u32.u64 %0, tmp; }"
        : "=r"(a) : "l"(p));
    return a;
}

#define CP16(dst, src) \
    asm volatile("cp.async.cg.shared.global [%0], [%1], 16;" \
                 :: "r"(dst), "l"(src) : "memory")
#define CP_COMMIT() asm volatile("cp.async.commit_group;" ::: "memory")
#define CP_WAIT0()  asm volatile("cp.async.wait_group 0;" ::: "memory")

__device__ __forceinline__ void split2(float a, float b, uint32_t& hi, uint32_t& lo) {
    __nv_bfloat16 ha = __float2bfloat16_rn(a);
    __nv_bfloat16 hb = __float2bfloat16_rn(b);
    __nv_bfloat16 la = __float2bfloat16_rn(a - __bfloat162float(ha));
    __nv_bfloat16 lb = __float2bfloat16_rn(b - __bfloat162float(hb));
    __nv_bfloat162 hv; hv.x = ha; hv.y = hb;
    __nv_bfloat162 lv; lv.x = la; lv.y = lb;
    hi = *(uint32_t*)&hv;
    lo = *(uint32_t*)&lv;
}

// FMA-pipe exp (valid x <= 0)
__device__ __forceinline__ float fexp(float x) {
    float y = x * 1.4426950408889634f;
    y = fmaxf(y, -126.0f);
    int n = __float2int_rn(y);
    float f = y - (float)n;
    float p =            1.535336188319500e-4f;
    p = fmaf(p, f, 1.339887440266574e-3f);
    p = fmaf(p, f, 9.618437357674640e-3f);
    p = fmaf(p, f, 5.550332471162809e-2f);
    p = fmaf(p, f, 2.402264791363012e-1f);
    p = fmaf(p, f, 6.931472028550421e-1f);
    p = fmaf(p, f, 1.0f);
    return __int_as_float(__float_as_int(p) + (n << 23));
}

// ---------------------------------------------------------------------------
// Kernel 0: fp32 -> bf16 hi/lo split prepass.
// ---------------------------------------------------------------------------
__global__ void split_kernel(const float* __restrict__ src, int which, int n4)
{
    int i = blockIdx.x * blockDim.x + threadIdx.x;
    if (i >= n4) return;
    __nv_bfloat16* dh;
    __nv_bfloat16* dl;
    if (which == 0) { dh = g_xh; dl = g_xl; }
    else            { dh = g_wh[which - 1]; dl = g_wl[which - 1]; }
    float4 v = ((const float4*)src)[i];
    uint32_t h0, l0, h1, l1;
    split2(v.x, v.y, h0, l0);
    split2(v.z, v.w, h1, l1);
    uint32_t* dh32 = (uint32_t*)dh;
    uint32_t* dl32 = (uint32_t*)dl;
    dh32[i * 2] = h0; dh32[i * 2 + 1] = h1;
    dl32[i * 2] = l0; dl32[i * 2 + 1] = l1;
}

// ---------------------------------------------------------------------------
// Kernel 1: QKV projection, bf16 3-term split on mma.m16n8k16.
// CTA 128x128, BK=32, 8 warps (4m x 2n), warp tile 32x64.
// cp.async double-buffered; fragments via ldmatrix.x4.
// smem layout per buffer (bytes): Ah@0 Al@10240 Bh@20480 Bl@30720 (128x40 bf16)
// ---------------------------------------------------------------------------
#define GSTR 40
#define GBUF_B 40960
#define QKV_SMEM (2 * GBUF_B)

__global__ __launch_bounds__(256, 2)
void qkv_kernel(const float* __restrict__ bq,
                const float* __restrict__ bk,
                const float* __restrict__ bv)
{
    extern __shared__ char smem[];
    const uint32_t sb = smem_u32(smem);
    const int tid  = threadIdx.x;
    const int lane = tid & 31;
    const int w    = tid >> 5;
    const int wm = (w >> 1) * 32;
    const int wn = (w & 1) * 64;
    const int g = lane >> 2;
    const int t = lane & 3;
    const int lr16 = lane & 15;
    const int lk8  = (lane >> 4) * 8;

    const int z  = blockIdx.z;
    const int n0 = blockIdx.x * 128;
    const int m0 = blockIdx.y * 128;
    const __nv_bfloat16* __restrict__ Wh = g_wh[z];
    const __nv_bfloat16* __restrict__ Wl = g_wl[z];
    const float* __restrict__ bias = (z == 0) ? bq : (z == 1) ? bk : bv;

    auto issue = [&](int ck, int bsel) {
        const int k0 = ck * 32;
        const uint32_t bb = sb + bsel * GBUF_B;
        #pragma unroll
        for (int i = 0; i < 2; ++i) {
            const int idx = i * 256 + tid;
            const int r = idx >> 2, c = idx & 3;
            const uint32_t doff = (uint32_t)(r * GSTR + c * 8) * 2;
            CP16(bb + doff,         (const char*)&g_xh[(size_t)(m0 + r) * H_ + k0 + c * 8]);
            CP16(bb + 10240 + doff, (const char*)&g_xl[(size_t)(m0 + r) * H_ + k0 + c * 8]);
            CP16(bb + 20480 + doff, (const char*)&Wh[(size_t)(n0 + r) * H_ + k0 + c * 8]);
            CP16(bb + 30720 + doff, (const char*)&Wl[(size_t)(n0 + r) * H_ + k0 + c * 8]);
        }
    };

    float acc[2][8][4] = {};

    issue(0, 0);
    CP_COMMIT();

    const int NCH = H_ / 32;  // 32
    for (int ck = 0; ck < NCH; ++ck) {
        const int bsel = ck & 1;
        CP_WAIT0();
        __syncthreads();
        if (ck + 1 < NCH) issue(ck + 1, bsel ^ 1);
        CP_COMMIT();

        const uint32_t bb = sb + bsel * GBUF_B;
        #pragma unroll
        for (int ks = 0; ks < 2; ++ks) {
            const uint32_t kc = ks * 16 + lk8;
            uint32_t ah[2][4], al[2][4];
            #pragma unroll
            for (int mt = 0; mt < 2; ++mt) {
                const uint32_t aoff = (uint32_t)((wm + mt * 16 + lr16) * GSTR + kc) * 2;
                ldsm4(ah[mt], bb + aoff);
                ldsm4(al[mt], bb + 10240 + aoff);
            }
            #pragma unroll
            for (int np = 0; np < 4; ++np) {
                const uint32_t boff = (uint32_t)((wn + np * 16 + lr16) * GSTR + kc) * 2;
                uint32_t bh4[4], bl4[4];
                ldsm4(bh4, bb + 20480 + boff);
                ldsm4(bl4, bb + 30720 + boff);
                uint32_t be_h[2] = {bh4[0], bh4[2]};
                uint32_t bo_h[2] = {bh4[1], bh4[3]};
                uint32_t be_l[2] = {bl4[0], bl4[2]};
                uint32_t bo_l[2] = {bl4[1], bl4[3]};
                #pragma unroll
                for (int mt = 0; mt < 2; ++mt) {
                    mma_bf16(acc[mt][2 * np],     ah[mt], be_h);
                    mma_bf16(acc[mt][2 * np],     ah[mt], be_l);
                    mma_bf16(acc[mt][2 * np],     al[mt], be_h);
                    mma_bf16(acc[mt][2 * np + 1], ah[mt], bo_h);
                    mma_bf16(acc[mt][2 * np + 1], ah[mt], bo_l);
                    mma_bf16(acc[mt][2 * np + 1], al[mt], bo_h);
                }
            }
        }
    }

    // epilogue: bias + split + head-major store
    const int bidx  = m0 >> 11;
    const int sbase = (m0 & (S_ - 1));
    #pragma unroll
    for (int mt = 0; mt < 2; ++mt) {
        #pragma unroll
        for (int nt = 0; nt < 8; ++nt) {
            const int nloc = wn + nt * 8 + 2 * t;
            const int d    = nloc & 63;
            const int hh   = (n0 + nloc) >> 6;
            const int bh_i = bidx * NH_ + hh;
            const float2 bi = *(const float2*)&bias[n0 + nloc];
            const int s0 = sbase + wm + mt * 16 + g;
            const float v0 = acc[mt][nt][0] + bi.x;
            const float v1 = acc[mt][nt][1] + bi.y;
            const float v2 = acc[mt][nt][2] + bi.x;
            const float v3 = acc[mt][nt][3] + bi.y;
            if (z < 2) {
                __nv_bfloat16* dh = (z == 0) ? g_qh : g_kh;
                __nv_bfloat16* dl = (z == 0) ? g_ql : g_kl;
                uint32_t h01, l01, h23, l23;
                split2(v0, v1, h01, l01);
                split2(v2, v3, h23, l23);
                *(uint32_t*)&dh[((size_t)bh_i * S_ + s0) * HD_ + d]     = h01;
                *(uint32_t*)&dl[((size_t)bh_i * S_ + s0) * HD_ + d]     = l01;
                *(uint32_t*)&dh[((size_t)bh_i * S_ + s0 + 8) * HD_ + d] = h23;
                *(uint32_t*)&dl[((size_t)bh_i * S_ + s0 + 8) * HD_ + d] = l23;
            } else {
                #pragma unroll
                for (int e = 0; e < 4; ++e) {
                    const float v = (e == 0) ? v0 : (e == 1) ? v1 : (e == 2) ? v2 : v3;
                    const int dd = d + (e & 1);
                    const int ss = s0 + ((e >> 1) * 8);
                    __nv_bfloat16 hv = __float2bfloat16_rn(v);
                    __nv_bfloat16 lv = __float2bfloat16_rn(v - __bfloat162float(hv));
                    g_vth[((size_t)bh_i * HD_ + dd) * S_ + ss] = hv;
                    g_vtl[((size_t)bh_i * HD_ + dd) * S_ + ss] = lv;
                }
            }
        }
    }
}

// ---------------------------------------------------------------------------
// Kernel 2: causal flash attention (bf16 3-term split mma).
// CTA: 128 q rows; KV tiles of 64; 8 warps x 16 q rows.
// cp.async double-buffered KV; ldmatrix fragments.
// smem (bytes): Qh@0 Ql@18432 | KVbuf[2]@36864 (Kh 0/Kl 9216/Vh 18432/Vl 27648,
// each 64x72 bf16) | amask[2][64] @110592.  Total 111104.
// ---------------------------------------------------------------------------
#define QSTR 72
#define ATT_QH 0u
#define ATT_QL 18432u
#define ATT_KV0 36864u
#define ATT_KVSZ 36864u
#define ATT_AM 110592u
#define ATT_SMEM 111104

__global__ __launch_bounds__(256, 2)
void attn_kernel(const float* __restrict__ amask, float* __restrict__ out)
{
    extern __shared__ char smem[];
    const uint32_t sb = smem_u32(smem);
    const int qt = 15 - (int)blockIdx.x;  // heavy tiles first
    const int bh = blockIdx.y;
    const int b  = bh >> 4;
    const int h  = bh & 15;
    const int q0 = qt * 128;
    const int tid  = threadIdx.x;
    const int lane = tid & 31;
    const int w    = tid >> 5;
    const int g = lane >> 2;
    const int t = lane & 3;
    const int lr16 = lane & 15;
    const int lk8  = (lane >> 4) * 8;

    float* sAm = (float*)(smem + ATT_AM);

    // Q tile: 128 x 64 hi+lo, plain loads (consumed after first sync)
    #pragma unroll
    for (int i = 0; i < 4; ++i) {
        const int idx = i * 256 + tid;
        const int r = idx >> 3, c = idx & 7;
        *(uint4*)(smem + ATT_QH + (r * QSTR + c * 8) * 2) =
            *(const uint4*)&g_qh[((size_t)bh * S_ + q0 + r) * HD_ + c * 8];
        *(uint4*)(smem + ATT_QL + (r * QSTR + c * 8) * 2) =
            *(const uint4*)&g_ql[((size_t)bh * S_ + q0 + r) * HD_ + c * 8];
    }

    auto issue_kv = [&](int kt, int bsel) {
        const int j0 = kt * 64;
        const uint32_t kb = sb + ATT_KV0 + bsel * ATT_KVSZ;
        #pragma unroll
        for (int i = 0; i < 2; ++i) {
            const int idx = i * 256 + tid;
            const int r = idx >> 3, c = idx & 7;
            const uint32_t doff = (uint32_t)(r * QSTR + c * 8) * 2;
            CP16(kb + doff,
                 (const char*)&g_kh[((size_t)bh * S_ + j0 + r) * HD_ + c * 8]);
            CP16(kb + 9216 + doff,
                 (const char*)&g_kl[((size_t)bh * S_ + j0 + r) * HD_ + c * 8]);
            CP16(kb + 18432 + doff,
                 (const char*)&g_vth[((size_t)bh * HD_ + r) * S_ + j0 + c * 8]);
            CP16(kb + 27648 + doff,
                 (const char*)&g_vtl[((size_t)bh * HD_ + r) * S_ + j0 + c * 8]);
        }
    };

    issue_kv(0, 0);
    CP_COMMIT();
    if (tid < 16)
        *(float4*)&sAm[tid * 4] = *(const float4*)&amask[(size_t)b * S_ + tid * 4];

    float o[8][4] = {};
    float m0r = -1e30f, m1r = -1e30f;
    float l0r = 0.f, l1r = 0.f;
    const int i0 = q0 + w * 16 + g;
    const int i1 = i0 + 8;

    const int nkv = 2 * qt + 2;
    for (int kt = 0; kt < nkv; ++kt) {
        const int j0 = kt * 64;
        const int bsel = kt & 1;
        CP_WAIT0();
        __syncthreads();
        if (kt + 1 < nkv) {
            issue_kv(kt + 1, bsel ^ 1);
            if (tid < 16)
                *(float4*)&sAm[((kt + 1) & 1) * 64 + tid * 4] =
                    *(const float4*)&amask[(size_t)b * S_ + (j0 + 64) + tid * 4];
        }
        CP_COMMIT();

        if (j0 > q0 + w * 16 + 15) continue;  // fully masked for this warp

        const uint32_t kb = sb + ATT_KV0 + bsel * ATT_KVSZ;
        const float* am = sAm + bsel * 64;

        // ---- S = Q @ K^T ----
        float s[8][4] = {};
        #pragma unroll
        for (int ks = 0; ks < 4; ++ks) {
            const uint32_t kc = ks * 16 + lk8;
            uint32_t qh4[4], ql4[4];
            const uint32_t qoff = (uint32_t)((w * 16 + lr16) * QSTR + kc) * 2;
            ldsm4(qh4, sb + ATT_QH + qoff);
            ldsm4(ql4, sb + ATT_QL + qoff);
            #pragma unroll
            for (int p = 0; p < 4; ++p) {
                const uint32_t koff = (uint32_t)((p * 16 + lr16) * QSTR + kc) * 2;
                uint32_t kh4[4], kl4[4];
                ldsm4(kh4, kb + koff);
                ldsm4(kl4, kb + 9216 + koff);
                uint32_t be_h[2] = {kh4[0], kh4[2]};
                uint32_t bo_h[2] = {kh4[1], kh4[3]};
                uint32_t be_l[2] = {kl4[0], kl4[2]};
                uint32_t bo_l[2] = {kl4[1], kl4[3]};
                mma_bf16(s[2 * p],     qh4, be_h);
                mma_bf16(s[2 * p],     qh4, be_l);
                mma_bf16(s[2 * p],     ql4, be_h);
                mma_bf16(s[2 * p + 1], qh4, bo_h);
                mma_bf16(s[2 * p + 1], qh4, bo_l);
                mma_bf16(s[2 * p + 1], ql4, bo_h);
            }
        }

        // ---- mask + online softmax ----
        const bool needm = (j0 + 63 > q0 + w * 16);
        float rm0 = -1e30f, rm1 = -1e30f;
        #pragma unroll
        for (int ntj = 0; ntj < 8; ++ntj) {
            const float2 amv = *(const float2*)&am[ntj * 8 + 2 * t];
            const int j = j0 + ntj * 8 + 2 * t;
            float v0 = (s[ntj][0] + amv.x) * 0.125f;
            float v1 = (s[ntj][1] + amv.y) * 0.125f;
            float v2 = (s[ntj][2] + amv.x) * 0.125f;
            float v3 = (s[ntj][3] + amv.y) * 0.125f;
            if (needm) {
                if (j     > i0) v0 = -1e30f;
                if (j + 1 > i0) v1 = -1e30f;
                if (j     > i1) v2 = -1e30f;
                if (j + 1 > i1) v3 = -1e30f;
            }
            s[ntj][0] = v0; s[ntj][1] = v1; s[ntj][2] = v2; s[ntj][3] = v3;
            rm0 = fmaxf(rm0, fmaxf(v0, v1));
            rm1 = fmaxf(rm1, fmaxf(v2, v3));
        }
        rm0 = fmaxf(rm0, __shfl_xor_sync(0xffffffffu, rm0, 1));
        rm0 = fmaxf(rm0, __shfl_xor_sync(0xffffffffu, rm0, 2));
        rm1 = fmaxf(rm1, __shfl_xor_sync(0xffffffffu, rm1, 1));
        rm1 = fmaxf(rm1, __shfl_xor_sync(0xffffffffu, rm1, 2));

        const float mn0 = fmaxf(m0r, rm0);
        const float mn1 = fmaxf(m1r, rm1);
        const float c0 = fexp(m0r - mn0);
        const float c1 = fexp(m1r - mn1);
        m0r = mn0; m1r = mn1;

        float rs0 = 0.f, rs1 = 0.f;
        #pragma unroll
        for (int ntj = 0; ntj < 8; ++ntj) {
            float p0 = fexp(s[ntj][0] - mn0);
            float p1 = fexp(s[ntj][1] - mn0);
            float p2 = fexp(s[ntj][2] - mn1);
            float p3 = fexp(s[ntj][3] - mn1);
            s[ntj][0] = p0; s[ntj][1] = p1; s[ntj][2] = p2; s[ntj][3] = p3;
            rs0 += p0 + p1;
            rs1 += p2 + p3;
        }
        rs0 += __shfl_xor_sync(0xffffffffu, rs0, 1);
        rs0 += __shfl_xor_sync(0xffffffffu, rs0, 2);
        rs1 += __shfl_xor_sync(0xffffffffu, rs1, 1);
        rs1 += __shfl_xor_sync(0xffffffffu, rs1, 2);
        l0r = l0r * c0 + rs0;
        l1r = l1r * c1 + rs1;
        #pragma unroll
        for (int ntd = 0; ntd < 8; ++ntd) {
            o[ntd][0] *= c0; o[ntd][1] *= c0;
            o[ntd][2] *= c1; o[ntd][3] *= c1;
        }

        // ---- pack P into A-fragments (C layout == A layout) ----
        uint32_t pah[4][4], pal[4][4];
        #pragma unroll
        for (int ks = 0; ks < 4; ++ks) {
            split2(s[2 * ks][0],     s[2 * ks][1],     pah[ks][0], pal[ks][0]);
            split2(s[2 * ks][2],     s[2 * ks][3],     pah[ks][1], pal[ks][1]);
            split2(s[2 * ks + 1][0], s[2 * ks + 1][1], pah[ks][2], pal[ks][2]);
            split2(s[2 * ks + 1][2], s[2 * ks + 1][3], pah[ks][3], pal[ks][3]);
        }

        // ---- O += P @ V ----
        #pragma unroll
        for (int ks = 0; ks < 4; ++ks) {
            const uint32_t kc = ks * 16 + lk8;
            #pragma unroll
            for (int p = 0; p < 4; ++p) {
                const uint32_t voff = (uint32_t)((p * 16 + lr16) * QSTR + kc) * 2;
                uint32_t vh4[4], vl4[4];
                ldsm4(vh4, kb + 18432 + voff);
                ldsm4(vl4, kb + 27648 + voff);
                uint32_t be_h[2] = {vh4[0], vh4[2]};
                uint32_t bo_h[2] = {vh4[1], vh4[3]};
                uint32_t be_l[2] = {vl4[0], vl4[2]};
                uint32_t bo_l[2] = {vl4[1], vl4[3]};
                mma_bf16(o[2 * p],     pah[ks], be_h);
                mma_bf16(o[2 * p],     pah[ks], be_l);
                mma_bf16(o[2 * p],     pal[ks], be_h);
                mma_bf16(o[2 * p + 1], pah[ks], bo_h);
                mma_bf16(o[2 * p + 1], pah[ks], bo_l);
                mma_bf16(o[2 * p + 1], pal[ks], bo_h);
            }
        }
    }

    // epilogue
    const float inv0 = 1.0f / l0r;
    const float inv1 = 1.0f / l1r;
    #pragma unroll
    for (int ntd = 0; ntd < 8; ++ntd) {
        const int d = h * HD_ + ntd * 8 + 2 * t;
        float2 r0 = make_float2(o[ntd][0] * inv0, o[ntd][1] * inv0);
        float2 r1 = make_float2(o[ntd][2] * inv1, o[ntd][3] * inv1);
        *(float2*)&out[((size_t)b * S_ + i0) * H_ + d] = r0;
        *(float2*)&out[((size_t)b * S_ + i1) * H_ + d] = r1;
    }
}

// ---------------------------------------------------------------------------
// Launch
// ---------------------------------------------------------------------------
extern "C" void kernel_launch(void* const* d_in, const int* in_sizes, int n_in,
                              void* d_out, int out_size)
{
    const float* hidden = (const float*)d_in[0];
    const float* amask  = (const float*)d_in[1];
    const float* Wq = (const float*)d_in[2];
    const float* bq = (const float*)d_in[3];
    const float* Wk = (const float*)d_in[4];
    const float* bk = (const float*)d_in[5];
    const float* Wv = (const float*)d_in[6];
    const float* bv = (const float*)d_in[7];
    float* out = (float*)d_out;

    // prepass splits
    split_kernel<<<(MROWS * H_ / 4 + 255) / 256, 256>>>(hidden, 0, MROWS * H_ / 4);
    split_kernel<<<(H_ * H_ / 4 + 255) / 256, 256>>>(Wq, 1, H_ * H_ / 4);
    split_kernel<<<(H_ * H_ / 4 + 255) / 256, 256>>>(Wk, 2, H_ * H_ / 4);
    split_kernel<<<(H_ * H_ / 4 + 255) / 256, 256>>>(Wv, 3, H_ * H_ / 4);

    // QKV projection: grid (8 n-tiles, 64 m-tiles, 3)
    cudaFuncSetAttribute(qkv_kernel,
                         cudaFuncAttributeMaxDynamicSharedMemorySize, QKV_SMEM);
    dim3 ggrid(H_ / 128, MROWS / 128, 3);
    qkv_kernel<<<ggrid, 256, QKV_SMEM>>>(bq, bk, bv);

    // attention: grid (16 q-tiles, 64 bh)
    cudaFuncSetAttribute(attn_kernel,
                         cudaFuncAttributeMaxDynamicSharedMemorySize, ATT_SMEM);
    dim3 agrid(S_ / 128, B_ * NH_);
    attn_kernel<<<agrid, 256, ATT_SMEM>>>(amask, out);
}

// round 7
// speedup vs baseline: 4.0763x; 1.5001x over previous
#include <cuda_runtime.h>
#include <cuda_fp16.h>
#include <cstdint>

// Problem constants
#define B_   4
#define S_   2048
#define H_   1024
#define NH_  16
#define HD_  64
#define MROWS (B_ * S_)        // 8192

// ---------------------------------------------------------------------------
// Scratch (device globals). fp16 2-term scheme:
//  A-side operands are split (hi+lo), B-side operands single fp16.
//  QK: A=Q(split), B=K(single).  PV: A=P(split), B=V(single).
//  QKV GEMM: A=X(split), B=W(single).
// ---------------------------------------------------------------------------
__device__ __half g_xh[(size_t)MROWS * H_];
__device__ __half g_xl[(size_t)MROWS * H_];
__device__ __half g_wh[3][(size_t)H_ * H_];
// Q split: [bh][s][d]; K single: [bh][s][d]; V single transposed: [bh][d][s]
__device__ __half g_qh[(size_t)B_ * NH_ * S_ * HD_];
__device__ __half g_ql[(size_t)B_ * NH_ * S_ * HD_];
__device__ __half g_kh[(size_t)B_ * NH_ * S_ * HD_];
__device__ __half g_vth[(size_t)B_ * NH_ * S_ * HD_];

// ---------------------------------------------------------------------------
// helpers
// ---------------------------------------------------------------------------
__device__ __forceinline__ void mma_f16(float* d, const uint32_t* a, const uint32_t* b) {
    asm volatile(
        "mma.sync.aligned.m16n8k16.row.col.f32.f16.f16.f32 "
        "{%0,%1,%2,%3},{%4,%5,%6,%7},{%8,%9},{%0,%1,%2,%3};"
        : "+f"(d[0]), "+f"(d[1]), "+f"(d[2]), "+f"(d[3])
        : "r"(a[0]), "r"(a[1]), "r"(a[2]), "r"(a[3]), "r"(b[0]), "r"(b[1]));
}

__device__ __forceinline__ void ldsm4(uint32_t* r, uint32_t addr) {
    asm volatile(
        "ldmatrix.sync.aligned.m8n8.x4.shared.b16 {%0,%1,%2,%3}, [%4];"
        : "=r"(r[0]), "=r"(r[1]), "=r"(r[2]), "=r"(r[3]) : "r"(addr));
}

__device__ __forceinline__ uint32_t smem_u32(const void* p) {
    uint32_t a;
    asm("{ .reg .u64 tmp; cvta.to.shared.u64 tmp, %1; cvt.u32.u64 %0, tmp; }"
        : "=r"(a) : "l"(p));
    return a;
}

#define CP16(dst, src) \
    asm volatile("cp.async.cg.shared.global [%0], [%1], 16;" \
                 :: "r"(dst), "l"(src) : "memory")
#define CP_COMMIT() asm volatile("cp.async.commit_group;" ::: "memory")
#define CP_WAIT0()  asm volatile("cp.async.wait_group 0;" ::: "memory")

// split two fp32 into packed fp16 hi-pair + lo-pair
__device__ __forceinline__ void split2h(float a, float b, uint32_t& hi, uint32_t& lo) {
    __half ha = __float2half_rn(a);
    __half hb = __float2half_rn(b);
    __half la = __float2half_rn(a - __half2float(ha));
    __half lb = __float2half_rn(b - __half2float(hb));
    __half2 hv; hv.x = ha; hv.y = hb;
    __half2 lv; lv.x = la; lv.y = lb;
    hi = *(uint32_t*)&hv;
    lo = *(uint32_t*)&lv;
}

// ---------------------------------------------------------------------------
// Kernel 0: split prepass. which==0: X -> (xh, xl). which 1..3: W -> wh only.
// ---------------------------------------------------------------------------
__global__ void split_kernel(const float* __restrict__ src, int which, int n4)
{
    int i = blockIdx.x * blockDim.x + threadIdx.x;
    if (i >= n4) return;
    float4 v = ((const float4*)src)[i];
    if (which == 0) {
        uint32_t h0, l0, h1, l1;
        split2h(v.x, v.y, h0, l0);
        split2h(v.z, v.w, h1, l1);
        ((uint32_t*)g_xh)[i * 2] = h0; ((uint32_t*)g_xh)[i * 2 + 1] = h1;
        ((uint32_t*)g_xl)[i * 2] = l0; ((uint32_t*)g_xl)[i * 2 + 1] = l1;
    } else {
        __half* dh = g_wh[which - 1];
        __half2 a; a.x = __float2half_rn(v.x); a.y = __float2half_rn(v.y);
        __half2 b; b.x = __float2half_rn(v.z); b.y = __float2half_rn(v.w);
        ((uint32_t*)dh)[i * 2]     = *(uint32_t*)&a;
        ((uint32_t*)dh)[i * 2 + 1] = *(uint32_t*)&b;
    }
}

// ---------------------------------------------------------------------------
// Kernel 1: QKV projection, fp16 2-term split mma.m16n8k16.
// CTA 128x128, BK=32, 8 warps (4m x 2n), warp tile 32x64.
// smem per buffer: Xh@0, Xl@10240, Wh@20480 (each 128 x 40 halves)
// ---------------------------------------------------------------------------
#define GSTR 40
#define GBUF_B 30720
#define QKV_SMEM (2 * GBUF_B)

__global__ __launch_bounds__(256, 2)
void qkv_kernel(const float* __restrict__ bq,
                const float* __restrict__ bk,
                const float* __restrict__ bv)
{
    extern __shared__ char smem[];
    const uint32_t sb = smem_u32(smem);
    const int tid  = threadIdx.x;
    const int lane = tid & 31;
    const int w    = tid >> 5;
    const int wm = (w >> 1) * 32;
    const int wn = (w & 1) * 64;
    const int g = lane >> 2;
    const int t = lane & 3;
    const int lr16 = lane & 15;
    const int lk8  = (lane >> 4) * 8;

    const int z  = blockIdx.z;
    const int n0 = blockIdx.x * 128;
    const int m0 = blockIdx.y * 128;
    const __half* __restrict__ Wh = g_wh[z];
    const float* __restrict__ bias = (z == 0) ? bq : (z == 1) ? bk : bv;

    auto issue = [&](int ck, int bsel) {
        const int k0 = ck * 32;
        const uint32_t bb = sb + bsel * GBUF_B;
        #pragma unroll
        for (int i = 0; i < 2; ++i) {
            const int idx = i * 256 + tid;
            const int r = idx >> 2, c = idx & 3;
            const uint32_t doff = (uint32_t)(r * GSTR + c * 8) * 2;
            CP16(bb + doff,         (const char*)&g_xh[(size_t)(m0 + r) * H_ + k0 + c * 8]);
            CP16(bb + 10240 + doff, (const char*)&g_xl[(size_t)(m0 + r) * H_ + k0 + c * 8]);
            CP16(bb + 20480 + doff, (const char*)&Wh[(size_t)(n0 + r) * H_ + k0 + c * 8]);
        }
    };

    float acc[2][8][4] = {};

    issue(0, 0);
    CP_COMMIT();

    const int NCH = H_ / 32;  // 32
    for (int ck = 0; ck < NCH; ++ck) {
        const int bsel = ck & 1;
        CP_WAIT0();
        __syncthreads();
        if (ck + 1 < NCH) issue(ck + 1, bsel ^ 1);
        CP_COMMIT();

        const uint32_t bb = sb + bsel * GBUF_B;
        #pragma unroll
        for (int ks = 0; ks < 2; ++ks) {
            const uint32_t kc = ks * 16 + lk8;
            uint32_t ah[2][4], al[2][4];
            #pragma unroll
            for (int mt = 0; mt < 2; ++mt) {
                const uint32_t aoff = (uint32_t)((wm + mt * 16 + lr16) * GSTR + kc) * 2;
                ldsm4(ah[mt], bb + aoff);
                ldsm4(al[mt], bb + 10240 + aoff);
            }
            #pragma unroll
            for (int np = 0; np < 4; ++np) {
                const uint32_t boff = (uint32_t)((wn + np * 16 + lr16) * GSTR + kc) * 2;
                uint32_t bh4[4];
                ldsm4(bh4, bb + 20480 + boff);
                uint32_t be[2] = {bh4[0], bh4[2]};
                uint32_t bo[2] = {bh4[1], bh4[3]};
                #pragma unroll
                for (int mt = 0; mt < 2; ++mt) {
                    mma_f16(acc[mt][2 * np],     ah[mt], be);
                    mma_f16(acc[mt][2 * np],     al[mt], be);
                    mma_f16(acc[mt][2 * np + 1], ah[mt], bo);
                    mma_f16(acc[mt][2 * np + 1], al[mt], bo);
                }
            }
        }
    }

    // epilogue: bias + store (Q split fp16; K single fp16; V single fp16 transposed)
    const int bidx  = m0 >> 11;
    const int sbase = (m0 & (S_ - 1));
    #pragma unroll
    for (int mt = 0; mt < 2; ++mt) {
        #pragma unroll
        for (int nt = 0; nt < 8; ++nt) {
            const int nloc = wn + nt * 8 + 2 * t;
            const int d    = nloc & 63;
            const int hh   = (n0 + nloc) >> 6;
            const int bh_i = bidx * NH_ + hh;
            const float2 bi = *(const float2*)&bias[n0 + nloc];
            const int s0 = sbase + wm + mt * 16 + g;
            const float v0 = acc[mt][nt][0] + bi.x;
            const float v1 = acc[mt][nt][1] + bi.y;
            const float v2 = acc[mt][nt][2] + bi.x;
            const float v3 = acc[mt][nt][3] + bi.y;
            if (z == 0) {
                uint32_t h01, l01, h23, l23;
                split2h(v0, v1, h01, l01);
                split2h(v2, v3, h23, l23);
                *(uint32_t*)&g_qh[((size_t)bh_i * S_ + s0) * HD_ + d]     = h01;
                *(uint32_t*)&g_ql[((size_t)bh_i * S_ + s0) * HD_ + d]     = l01;
                *(uint32_t*)&g_qh[((size_t)bh_i * S_ + s0 + 8) * HD_ + d] = h23;
                *(uint32_t*)&g_ql[((size_t)bh_i * S_ + s0 + 8) * HD_ + d] = l23;
            } else if (z == 1) {
                __half2 a; a.x = __float2half_rn(v0); a.y = __float2half_rn(v1);
                __half2 c; c.x = __float2half_rn(v2); c.y = __float2half_rn(v3);
                *(uint32_t*)&g_kh[((size_t)bh_i * S_ + s0) * HD_ + d]     = *(uint32_t*)&a;
                *(uint32_t*)&g_kh[((size_t)bh_i * S_ + s0 + 8) * HD_ + d] = *(uint32_t*)&c;
            } else {
                g_vth[((size_t)bh_i * HD_ + d)     * S_ + s0]     = __float2half_rn(v0);
                g_vth[((size_t)bh_i * HD_ + d + 1) * S_ + s0]     = __float2half_rn(v1);
                g_vth[((size_t)bh_i * HD_ + d)     * S_ + s0 + 8] = __float2half_rn(v2);
                g_vth[((size_t)bh_i * HD_ + d + 1) * S_ + s0 + 8] = __float2half_rn(v3);
            }
        }
    }
}

// ---------------------------------------------------------------------------
// Kernel 2: causal flash attention, fp16 2-term split.
// CTA: 128 q rows; KV tiles of 64; 8 warps x 16 q rows.
// smem (bytes): Qh@0(18432) Ql@18432 | KVbuf[2]@36864 (Kh@0 9216, Vh@9216),
// amask[2][64]@73728. Total 74240.
// ---------------------------------------------------------------------------
#define QSTR 72
#define ATT_QH 0u
#define ATT_QL 18432u
#define ATT_KV0 36864u
#define ATT_KVSZ 18432u
#define ATT_AM 73728u
#define ATT_SMEM 74240

__global__ __launch_bounds__(256, 2)
void attn_kernel(const float* __restrict__ amask, float* __restrict__ out)
{
    extern __shared__ char smem[];
    const uint32_t sb = smem_u32(smem);
    const int qt = 15 - (int)blockIdx.x;  // heavy tiles first
    const int bh = blockIdx.y;
    const int b  = bh >> 4;
    const int h  = bh & 15;
    const int q0 = qt * 128;
    const int tid  = threadIdx.x;
    const int lane = tid & 31;
    const int w    = tid >> 5;
    const int g = lane >> 2;
    const int t = lane & 3;
    const int lr16 = lane & 15;
    const int lk8  = (lane >> 4) * 8;

    float* sAm = (float*)(smem + ATT_AM);

    // Q tile: 128 x 64 hi+lo
    #pragma unroll
    for (int i = 0; i < 4; ++i) {
        const int idx = i * 256 + tid;
        const int r = idx >> 3, c = idx & 7;
        *(uint4*)(smem + ATT_QH + (r * QSTR + c * 8) * 2) =
            *(const uint4*)&g_qh[((size_t)bh * S_ + q0 + r) * HD_ + c * 8];
        *(uint4*)(smem + ATT_QL + (r * QSTR + c * 8) * 2) =
            *(const uint4*)&g_ql[((size_t)bh * S_ + q0 + r) * HD_ + c * 8];
    }

    auto issue_kv = [&](int kt, int bsel) {
        const int j0 = kt * 64;
        const uint32_t kb = sb + ATT_KV0 + bsel * ATT_KVSZ;
        #pragma unroll
        for (int i = 0; i < 2; ++i) {
            const int idx = i * 256 + tid;
            const int r = idx >> 3, c = idx & 7;
            const uint32_t doff = (uint32_t)(r * QSTR + c * 8) * 2;
            CP16(kb + doff,
                 (const char*)&g_kh[((size_t)bh * S_ + j0 + r) * HD_ + c * 8]);
            CP16(kb + 9216 + doff,
                 (const char*)&g_vth[((size_t)bh * HD_ + r) * S_ + j0 + c * 8]);
        }
    };

    issue_kv(0, 0);
    CP_COMMIT();
    if (tid < 16)
        *(float4*)&sAm[tid * 4] = *(const float4*)&amask[(size_t)b * S_ + tid * 4];

    float o[8][4] = {};
    float m0r = -1e30f, m1r = -1e30f;
    float l0r = 0.f, l1r = 0.f;
    const int i0 = q0 + w * 16 + g;
    const int i1 = i0 + 8;

    const int nkv = 2 * qt + 2;
    for (int kt = 0; kt < nkv; ++kt) {
        const int j0 = kt * 64;
        const int bsel = kt & 1;
        CP_WAIT0();
        __syncthreads();
        if (kt + 1 < nkv) {
            issue_kv(kt + 1, bsel ^ 1);
            if (tid < 16)
                *(float4*)&sAm[((kt + 1) & 1) * 64 + tid * 4] =
                    *(const float4*)&amask[(size_t)b * S_ + (j0 + 64) + tid * 4];
        }
        CP_COMMIT();

        if (j0 > q0 + w * 16 + 15) continue;  // fully masked for this warp

        const uint32_t kb = sb + ATT_KV0 + bsel * ATT_KVSZ;
        const float* am = sAm + bsel * 64;

        // ---- S = Q @ K^T (2-term fp16) ----
        float s[8][4] = {};
        #pragma unroll
        for (int ks = 0; ks < 4; ++ks) {
            const uint32_t kc = ks * 16 + lk8;
            uint32_t qh4[4], ql4[4];
            const uint32_t qoff = (uint32_t)((w * 16 + lr16) * QSTR + kc) * 2;
            ldsm4(qh4, sb + ATT_QH + qoff);
            ldsm4(ql4, sb + ATT_QL + qoff);
            #pragma unroll
            for (int p = 0; p < 4; ++p) {
                const uint32_t koff = (uint32_t)((p * 16 + lr16) * QSTR + kc) * 2;
                uint32_t kh4[4];
                ldsm4(kh4, kb + koff);
                uint32_t be[2] = {kh4[0], kh4[2]};
                uint32_t bo[2] = {kh4[1], kh4[3]};
                mma_f16(s[2 * p],     qh4, be);
                mma_f16(s[2 * p],     ql4, be);
                mma_f16(s[2 * p + 1], qh4, bo);
                mma_f16(s[2 * p + 1], ql4, bo);
            }
        }

        // ---- mask + online softmax (MUFU exp) ----
        const bool needm = (j0 + 63 > q0 + w * 16);
        float rm0 = -1e30f, rm1 = -1e30f;
        #pragma unroll
        for (int ntj = 0; ntj < 8; ++ntj) {
            const float2 amv = *(const float2*)&am[ntj * 8 + 2 * t];
            const int j = j0 + ntj * 8 + 2 * t;
            float v0 = (s[ntj][0] + amv.x) * 0.125f;
            float v1 = (s[ntj][1] + amv.y) * 0.125f;
            float v2 = (s[ntj][2] + amv.x) * 0.125f;
            float v3 = (s[ntj][3] + amv.y) * 0.125f;
            if (needm) {
                if (j     > i0) v0 = -1e30f;
                if (j + 1 > i0) v1 = -1e30f;
                if (j     > i1) v2 = -1e30f;
                if (j + 1 > i1) v3 = -1e30f;
            }
            s[ntj][0] = v0; s[ntj][1] = v1; s[ntj][2] = v2; s[ntj][3] = v3;
            rm0 = fmaxf(rm0, fmaxf(v0, v1));
            rm1 = fmaxf(rm1, fmaxf(v2, v3));
        }
        rm0 = fmaxf(rm0, __shfl_xor_sync(0xffffffffu, rm0, 1));
        rm0 = fmaxf(rm0, __shfl_xor_sync(0xffffffffu, rm0, 2));
        rm1 = fmaxf(rm1, __shfl_xor_sync(0xffffffffu, rm1, 1));
        rm1 = fmaxf(rm1, __shfl_xor_sync(0xffffffffu, rm1, 2));

        const float mn0 = fmaxf(m0r, rm0);
        const float mn1 = fmaxf(m1r, rm1);
        const float c0 = __expf(m0r - mn0);
        const float c1 = __expf(m1r - mn1);
        m0r = mn0; m1r = mn1;

        float rs0 = 0.f, rs1 = 0.f;
        #pragma unroll
        for (int ntj = 0; ntj < 8; ++ntj) {
            float p0 = __expf(s[ntj][0] - mn0);
            float p1 = __expf(s[ntj][1] - mn0);
            float p2 = __expf(s[ntj][2] - mn1);
            float p3 = __expf(s[ntj][3] - mn1);
            s[ntj][0] = p0; s[ntj][1] = p1; s[ntj][2] = p2; s[ntj][3] = p3;
            rs0 += p0 + p1;
            rs1 += p2 + p3;
        }
        rs0 += __shfl_xor_sync(0xffffffffu, rs0, 1);
        rs0 += __shfl_xor_sync(0xffffffffu, rs0, 2);
        rs1 += __shfl_xor_sync(0xffffffffu, rs1, 1);
        rs1 += __shfl_xor_sync(0xffffffffu, rs1, 2);
        l0r = l0r * c0 + rs0;
        l1r = l1r * c1 + rs1;
        #pragma unroll
        for (int ntd = 0; ntd < 8; ++ntd) {
            o[ntd][0] *= c0; o[ntd][1] *= c0;
            o[ntd][2] *= c1; o[ntd][3] *= c1;
        }

        // ---- pack P into A-fragments (C layout == A layout), fp16 split ----
        uint32_t pah[4][4], pal[4][4];
        #pragma unroll
        for (int ks = 0; ks < 4; ++ks) {
            split2h(s[2 * ks][0],     s[2 * ks][1],     pah[ks][0], pal[ks][0]);
            split2h(s[2 * ks][2],     s[2 * ks][3],     pah[ks][1], pal[ks][1]);
            split2h(s[2 * ks + 1][0], s[2 * ks + 1][1], pah[ks][2], pal[ks][2]);
            split2h(s[2 * ks + 1][2], s[2 * ks + 1][3], pah[ks][3], pal[ks][3]);
        }

        // ---- O += P @ V (2-term fp16) ----
        #pragma unroll
        for (int ks = 0; ks < 4; ++ks) {
            const uint32_t kc = ks * 16 + lk8;
            #pragma unroll
            for (int p = 0; p < 4; ++p) {
                const uint32_t voff = (uint32_t)((p * 16 + lr16) * QSTR + kc) * 2;
                uint32_t vh4[4];
                ldsm4(vh4, kb + 9216 + voff);
                uint32_t be[2] = {vh4[0], vh4[2]};
                uint32_t bo[2] = {vh4[1], vh4[3]};
                mma_f16(o[2 * p],     pah[ks], be);
                mma_f16(o[2 * p],     pal[ks], be);
                mma_f16(o[2 * p + 1], pah[ks], bo);
                mma_f16(o[2 * p + 1], pal[ks], bo);
            }
        }
    }

    // epilogue
    const float inv0 = 1.0f / l0r;
    const float inv1 = 1.0f / l1r;
    #pragma unroll
    for (int ntd = 0; ntd < 8; ++ntd) {
        const int d = h * HD_ + ntd * 8 + 2 * t;
        float2 r0 = make_float2(o[ntd][0] * inv0, o[ntd][1] * inv0);
        float2 r1 = make_float2(o[ntd][2] * inv1, o[ntd][3] * inv1);
        *(float2*)&out[((size_t)b * S_ + i0) * H_ + d] = r0;
        *(float2*)&out[((size_t)b * S_ + i1) * H_ + d] = r1;
    }
}

// ---------------------------------------------------------------------------
// Launch
// ---------------------------------------------------------------------------
extern "C" void kernel_launch(void* const* d_in, const int* in_sizes, int n_in,
                              void* d_out, int out_size)
{
    const float* hidden = (const float*)d_in[0];
    const float* amask  = (const float*)d_in[1];
    const float* Wq = (const float*)d_in[2];
    const float* bq = (const float*)d_in[3];
    const float* Wk = (const float*)d_in[4];
    const float* bk = (const float*)d_in[5];
    const float* Wv = (const float*)d_in[6];
    const float* bv = (const float*)d_in[7];
    float* out = (float*)d_out;

    // prepass splits
    split_kernel<<<(MROWS * H_ / 4 + 255) / 256, 256>>>(hidden, 0, MROWS * H_ / 4);
    split_kernel<<<(H_ * H_ / 4 + 255) / 256, 256>>>(Wq, 1, H_ * H_ / 4);
    split_kernel<<<(H_ * H_ / 4 + 255) / 256, 256>>>(Wk, 2, H_ * H_ / 4);
    split_kernel<<<(H_ * H_ / 4 + 255) / 256, 256>>>(Wv, 3, H_ * H_ / 4);

    // QKV projection: grid (8 n-tiles, 64 m-tiles, 3)
    cudaFuncSetAttribute(qkv_kernel,
                         cudaFuncAttributeMaxDynamicSharedMemorySize, QKV_SMEM);
    dim3 ggrid(H_ / 128, MROWS / 128, 3);
    qkv_kernel<<<ggrid, 256, QKV_SMEM>>>(bq, bk, bv);

    // attention: grid (16 q-tiles, 64 bh)
    cudaFuncSetAttribute(attn_kernel,
                         cudaFuncAttributeMaxDynamicSharedMemorySize, ATT_SMEM);
    dim3 agrid(S_ / 128, B_ * NH_);
    attn_kernel<<<agrid, 256, ATT_SMEM>>>(amask, out);
}

// round 9
// speedup vs baseline: 5.8730x; 1.4408x over previous
#include <cuda_runtime.h>
#include <cuda_fp16.h>
#include <cstdint>

// Problem constants
#define B_   4
#define S_   2048
#define H_   1024
#define NH_  16
#define HD_  64
#define MROWS (B_ * S_)        // 8192

// ---------------------------------------------------------------------------
// Scratch (device globals). fp16 single-precision operands everywhere except
// P (split in registers for the PV product).
// ---------------------------------------------------------------------------
__device__ __half g_xh[(size_t)MROWS * H_];
__device__ __half g_wh[3][(size_t)H_ * H_];
// Q,K single: [bh][s][d]; V single transposed: [bh][d][s]
__device__ __half g_qh[(size_t)B_ * NH_ * S_ * HD_];
__device__ __half g_kh[(size_t)B_ * NH_ * S_ * HD_];
__device__ __half g_vth[(size_t)B_ * NH_ * S_ * HD_];

// ---------------------------------------------------------------------------
// helpers
// ---------------------------------------------------------------------------
__device__ __forceinline__ void mma_f16(float* d, const uint32_t* a, const uint32_t* b) {
    asm volatile(
        "mma.sync.aligned.m16n8k16.row.col.f32.f16.f16.f32 "
        "{%0,%1,%2,%3},{%4,%5,%6,%7},{%8,%9},{%0,%1,%2,%3};"
        : "+f"(d[0]), "+f"(d[1]), "+f"(d[2]), "+f"(d[3])
        : "r"(a[0]), "r"(a[1]), "r"(a[2]), "r"(a[3]), "r"(b[0]), "r"(b[1]));
}

__device__ __forceinline__ void ldsm4(uint32_t* r, uint32_t addr) {
    asm volatile(
        "ldmatrix.sync.aligned.m8n8.x4.shared.b16 {%0,%1,%2,%3}, [%4];"
        : "=r"(r[0]), "=r"(r[1]), "=r"(r[2]), "=r"(r[3]) : "r"(addr));
}

__device__ __forceinline__ uint32_t smem_u32(const void* p) {
    uint32_t a;
    asm("{ .reg .u64 tmp; cvta.to.shared.u64 tmp, %1; cvt.u32.u64 %0, tmp; }"
        : "=r"(a) : "l"(p));
    return a;
}

#define CP16(dst, src) \
    asm volatile("cp.async.cg.shared.global [%0], [%1], 16;" \
                 :: "r"(dst), "l"(src) : "memory")
#define CP_COMMIT() asm volatile("cp.async.commit_group;" ::: "memory")
#define CP_WAIT0()  asm volatile("cp.async.wait_group 0;" ::: "memory")

// split two fp32 into packed fp16 hi-pair + lo-pair
__device__ __forceinline__ void split2h(float a, float b, uint32_t& hi, uint32_t& lo) {
    __half ha = __float2half_rn(a);
    __half hb = __float2half_rn(b);
    __half la = __float2half_rn(a - __half2float(ha));
    __half lb = __float2half_rn(b - __half2float(hb));
    __half2 hv; hv.x = ha; hv.y = hb;
    __half2 lv; lv.x = la; lv.y = lb;
    hi = *(uint32_t*)&hv;
    lo = *(uint32_t*)&lv;
}

// ---------------------------------------------------------------------------
// Kernel 0: fp32 -> fp16 round prepass. which==0: X; 1..3: Wq/Wk/Wv.
// ---------------------------------------------------------------------------
__global__ void split_kernel(const float* __restrict__ src, int which, int n4)
{
    int i = blockIdx.x * blockDim.x + threadIdx.x;
    if (i >= n4) return;
    float4 v = ((const float4*)src)[i];
    __half* dh = (which == 0) ? g_xh : g_wh[which - 1];
    __half2 a; a.x = __float2half_rn(v.x); a.y = __float2half_rn(v.y);
    __half2 b; b.x = __float2half_rn(v.z); b.y = __float2half_rn(v.w);
    ((uint32_t*)dh)[i * 2]     = *(uint32_t*)&a;
    ((uint32_t*)dh)[i * 2 + 1] = *(uint32_t*)&b;
}

// ---------------------------------------------------------------------------
// Kernel 1: QKV projection, single-term fp16 HGEMM (fp32 accum).
// CTA 128x128, BK=32, 8 warps (4m x 2n), warp tile 32x64.
// smem per buffer: Xh@0, Wh@10240 (each 128 x 40 halves = 10240 B)
// ---------------------------------------------------------------------------
#define GSTR 40
#define GBUF_B 20480
#define QKV_SMEM (2 * GBUF_B)

__global__ __launch_bounds__(256, 2)
void qkv_kernel(const float* __restrict__ bq,
                const float* __restrict__ bk,
                const float* __restrict__ bv)
{
    extern __shared__ char smem[];
    const uint32_t sb = smem_u32(smem);
    const int tid  = threadIdx.x;
    const int lane = tid & 31;
    const int w    = tid >> 5;
    const int wm = (w >> 1) * 32;
    const int wn = (w & 1) * 64;
    const int g = lane >> 2;
    const int t = lane & 3;
    const int lr16 = lane & 15;
    const int lk8  = (lane >> 4) * 8;

    const int z  = blockIdx.z;
    const int n0 = blockIdx.x * 128;
    const int m0 = blockIdx.y * 128;
    const __half* __restrict__ Wh = g_wh[z];
    const float* __restrict__ bias = (z == 0) ? bq : (z == 1) ? bk : bv;

    auto issue = [&](int ck, int bsel) {
        const int k0 = ck * 32;
        const uint32_t bb = sb + bsel * GBUF_B;
        #pragma unroll
        for (int i = 0; i < 2; ++i) {
            const int idx = i * 256 + tid;
            const int r = idx >> 2, c = idx & 3;
            const uint32_t doff = (uint32_t)(r * GSTR + c * 8) * 2;
            CP16(bb + doff,         (const char*)&g_xh[(size_t)(m0 + r) * H_ + k0 + c * 8]);
            CP16(bb + 10240 + doff, (const char*)&Wh[(size_t)(n0 + r) * H_ + k0 + c * 8]);
        }
    };

    float acc[2][8][4] = {};

    issue(0, 0);
    CP_COMMIT();

    const int NCH = H_ / 32;  // 32
    for (int ck = 0; ck < NCH; ++ck) {
        const int bsel = ck & 1;
        CP_WAIT0();
        __syncthreads();
        if (ck + 1 < NCH) issue(ck + 1, bsel ^ 1);
        CP_COMMIT();

        const uint32_t bb = sb + bsel * GBUF_B;
        #pragma unroll
        for (int ks = 0; ks < 2; ++ks) {
            const uint32_t kc = ks * 16 + lk8;
            uint32_t ah[2][4];
            #pragma unroll
            for (int mt = 0; mt < 2; ++mt) {
                const uint32_t aoff = (uint32_t)((wm + mt * 16 + lr16) * GSTR + kc) * 2;
                ldsm4(ah[mt], bb + aoff);
            }
            #pragma unroll
            for (int np = 0; np < 4; ++np) {
                const uint32_t boff = (uint32_t)((wn + np * 16 + lr16) * GSTR + kc) * 2;
                uint32_t bh4[4];
                ldsm4(bh4, bb + 10240 + boff);
                uint32_t be[2] = {bh4[0], bh4[2]};
                uint32_t bo[2] = {bh4[1], bh4[3]};
                #pragma unroll
                for (int mt = 0; mt < 2; ++mt) {
                    mma_f16(acc[mt][2 * np],     ah[mt], be);
                    mma_f16(acc[mt][2 * np + 1], ah[mt], bo);
                }
            }
        }
    }

    // epilogue: bias + store (Q,K single fp16 head-major; V single transposed)
    const int bidx  = m0 >> 11;
    const int sbase = (m0 & (S_ - 1));
    #pragma unroll
    for (int mt = 0; mt < 2; ++mt) {
        #pragma unroll
        for (int nt = 0; nt < 8; ++nt) {
            const int nloc = wn + nt * 8 + 2 * t;
            const int d    = nloc & 63;
            const int hh   = (n0 + nloc) >> 6;
            const int bh_i = bidx * NH_ + hh;
            const float2 bi = *(const float2*)&bias[n0 + nloc];
            const int s0 = sbase + wm + mt * 16 + g;
            const float v0 = acc[mt][nt][0] + bi.x;
            const float v1 = acc[mt][nt][1] + bi.y;
            const float v2 = acc[mt][nt][2] + bi.x;
            const float v3 = acc[mt][nt][3] + bi.y;
            if (z < 2) {
                __half* dst = (z == 0) ? g_qh : g_kh;
                __half2 a; a.x = __float2half_rn(v0); a.y = __float2half_rn(v1);
                __half2 c; c.x = __float2half_rn(v2); c.y = __float2half_rn(v3);
                *(uint32_t*)&dst[((size_t)bh_i * S_ + s0) * HD_ + d]     = *(uint32_t*)&a;
                *(uint32_t*)&dst[((size_t)bh_i * S_ + s0 + 8) * HD_ + d] = *(uint32_t*)&c;
            } else {
                g_vth[((size_t)bh_i * HD_ + d)     * S_ + s0]     = __float2half_rn(v0);
                g_vth[((size_t)bh_i * HD_ + d + 1) * S_ + s0]     = __float2half_rn(v1);
                g_vth[((size_t)bh_i * HD_ + d)     * S_ + s0 + 8] = __float2half_rn(v2);
                g_vth[((size_t)bh_i * HD_ + d + 1) * S_ + s0 + 8] = __float2half_rn(v3);
            }
        }
    }
}

// ---------------------------------------------------------------------------
// Kernel 2: causal flash attention. QK single-term fp16; PV 2-term (P split).
// CTA: 128 q rows; KV tiles of 64; 8 warps x 16 q rows.
// smem (bytes): Q@0 (128 x 72 halves = 18432) |
//   KVbuf[2] @18432 (each: K 9216 + V 9216 = 18432) |
//   amask[2][64] @55296.  Total 55808.
// ---------------------------------------------------------------------------
#define QSTR 72
#define ATT_Q 0u
#define ATT_KV0 18432u
#define ATT_KVSZ 18432u
#define ATT_AM 55296u
#define ATT_SMEM 55808

__global__ __launch_bounds__(256, 2)
void attn_kernel(const float* __restrict__ amask, float* __restrict__ out)
{
    extern __shared__ char smem[];
    const uint32_t sb = smem_u32(smem);
    const int qt = 15 - (int)blockIdx.x;  // heavy tiles first
    const int bh = blockIdx.y;
    const int b  = bh >> 4;
    const int h  = bh & 15;
    const int q0 = qt * 128;
    const int tid  = threadIdx.x;
    const int lane = tid & 31;
    const int w    = tid >> 5;
    const int g = lane >> 2;
    const int t = lane & 3;
    const int lr16 = lane & 15;
    const int lk8  = (lane >> 4) * 8;

    float* sAm = (float*)(smem + ATT_AM);

    // Q tile: 128 x 64 single fp16 (18432 bytes)
    #pragma unroll
    for (int i = 0; i < 2; ++i) {
        const int idx = i * 256 + tid;
        const int r = idx >> 2, c = idx & 3;
        *(uint4*)(smem + ATT_Q + (r * QSTR + c * 16) * 2) =
            *(const uint4*)&g_qh[((size_t)bh * S_ + q0 + r) * HD_ + c * 16];
        *(uint4*)(smem + ATT_Q + (r * QSTR + c * 16 + 8) * 2) =
            *(const uint4*)&g_qh[((size_t)bh * S_ + q0 + r) * HD_ + c * 16 + 8];
    }

    auto issue_kv = [&](int kt, int bsel) {
        const int j0 = kt * 64;
        const uint32_t kb = sb + ATT_KV0 + bsel * ATT_KVSZ;
        #pragma unroll
        for (int i = 0; i < 2; ++i) {
            const int idx = i * 256 + tid;
            const int r = idx >> 3, c = idx & 7;
            const uint32_t doff = (uint32_t)(r * QSTR + c * 8) * 2;
            CP16(kb + doff,
                 (const char*)&g_kh[((size_t)bh * S_ + j0 + r) * HD_ + c * 8]);
            CP16(kb + 9216 + doff,
                 (const char*)&g_vth[((size_t)bh * HD_ + r) * S_ + j0 + c * 8]);
        }
    };

    issue_kv(0, 0);
    CP_COMMIT();
    if (tid < 16)
        *(float4*)&sAm[tid * 4] = *(const float4*)&amask[(size_t)b * S_ + tid * 4];

    float o[8][4] = {};
    float m0r = -1e30f, m1r = -1e30f;
    float l0r = 0.f, l1r = 0.f;
    const int i0 = q0 + w * 16 + g;
    const int i1 = i0 + 8;

    const int nkv = 2 * qt + 2;
    for (int kt = 0; kt < nkv; ++kt) {
        const int j0 = kt * 64;
        const int bsel = kt & 1;
        CP_WAIT0();
        __syncthreads();
        if (kt + 1 < nkv) {
            issue_kv(kt + 1, bsel ^ 1);
            if (tid < 16)
                *(float4*)&sAm[((kt + 1) & 1) * 64 + tid * 4] =
                    *(const float4*)&amask[(size_t)b * S_ + (j0 + 64) + tid * 4];
        }
        CP_COMMIT();

        if (j0 > q0 + w * 16 + 15) continue;  // fully masked for this warp

        const uint32_t kb = sb + ATT_KV0 + bsel * ATT_KVSZ;
        const float* am = sAm + bsel * 64;

        // ---- S = Q @ K^T (single-term fp16) ----
        float s[8][4] = {};
        #pragma unroll
        for (int ks = 0; ks < 4; ++ks) {
            const uint32_t kc = ks * 16 + lk8;
            uint32_t q4[4];
            const uint32_t qoff = (uint32_t)((w * 16 + lr16) * QSTR + kc) * 2;
            ldsm4(q4, sb + ATT_Q + qoff);
            #pragma unroll
            for (int p = 0; p < 4; ++p) {
                const uint32_t koff = (uint32_t)((p * 16 + lr16) * QSTR + kc) * 2;
                uint32_t kh4[4];
                ldsm4(kh4, kb + koff);
                uint32_t be[2] = {kh4[0], kh4[2]};
                uint32_t bo[2] = {kh4[1], kh4[3]};
                mma_f16(s[2 * p],     q4, be);
                mma_f16(s[2 * p + 1], q4, bo);
            }
        }

        // ---- mask + online softmax (MUFU exp) ----
        const bool needm = (j0 + 63 > q0 + w * 16);
        float rm0 = -1e30f, rm1 = -1e30f;
        #pragma unroll
        for (int ntj = 0; ntj < 8; ++ntj) {
            const float2 amv = *(const float2*)&am[ntj * 8 + 2 * t];
            const int j = j0 + ntj * 8 + 2 * t;
            float v0 = (s[ntj][0] + amv.x) * 0.125f;
            float v1 = (s[ntj][1] + amv.y) * 0.125f;
            float v2 = (s[ntj][2] + amv.x) * 0.125f;
            float v3 = (s[ntj][3] + amv.y) * 0.125f;
            if (needm) {
                if (j     > i0) v0 = -1e30f;
                if (j + 1 > i0) v1 = -1e30f;
                if (j     > i1) v2 = -1e30f;
                if (j + 1 > i1) v3 = -1e30f;
            }
            s[ntj][0] = v0; s[ntj][1] = v1; s[ntj][2] = v2; s[ntj][3] = v3;
            rm0 = fmaxf(rm0, fmaxf(v0, v1));
            rm1 = fmaxf(rm1, fmaxf(v2, v3));
        }
        rm0 = fmaxf(rm0, __shfl_xor_sync(0xffffffffu, rm0, 1));
        rm0 = fmaxf(rm0, __shfl_xor_sync(0xffffffffu, rm0, 2));
        rm1 = fmaxf(rm1, __shfl_xor_sync(0xffffffffu, rm1, 1));
        rm1 = fmaxf(rm1, __shfl_xor_sync(0xffffffffu, rm1, 2));

        const float mn0 = fmaxf(m0r, rm0);
        const float mn1 = fmaxf(m1r, rm1);
        const float c0 = __expf(m0r - mn0);
        const float c1 = __expf(m1r - mn1);
        m0r = mn0; m1r = mn1;

        float rs0 = 0.f, rs1 = 0.f;
        #pragma unroll
        for (int ntj = 0; ntj < 8; ++ntj) {
            float p0 = __expf(s[ntj][0] - mn0);
            float p1 = __expf(s[ntj][1] - mn0);
            float p2 = __expf(s[ntj][2] - mn1);
            float p3 = __expf(s[ntj][3] - mn1);
            s[ntj][0] = p0; s[ntj][1] = p1; s[ntj][2] = p2; s[ntj][3] = p3;
            rs0 += p0 + p1;
            rs1 += p2 + p3;
        }
        rs0 += __shfl_xor_sync(0xffffffffu, rs0, 1);
        rs0 += __shfl_xor_sync(0xffffffffu, rs0, 2);
        rs1 += __shfl_xor_sync(0xffffffffu, rs1, 1);
        rs1 += __shfl_xor_sync(0xffffffffu, rs1, 2);
        l0r = l0r * c0 + rs0;
        l1r = l1r * c1 + rs1;
        #pragma unroll
        for (int ntd = 0; ntd < 8; ++ntd) {
            o[ntd][0] *= c0; o[ntd][1] *= c0;
            o[ntd][2] *= c1; o[ntd][3] *= c1;
        }

        // ---- pack P into A-fragments (C layout == A layout), fp16 split ----
        uint32_t pah[4][4], pal[4][4];
        #pragma unroll
        for (int ks = 0; ks < 4; ++ks) {
            split2h(s[2 * ks][0],     s[2 * ks][1],     pah[ks][0], pal[ks][0]);
            split2h(s[2 * ks][2],     s[2 * ks][3],     pah[ks][1], pal[ks][1]);
            split2h(s[2 * ks + 1][0], s[2 * ks + 1][1], pah[ks][2], pal[ks][2]);
            split2h(s[2 * ks + 1][2], s[2 * ks + 1][3], pah[ks][3], pal[ks][3]);
        }

        // ---- O += P @ V (2-term: P split, V single) ----
        #pragma unroll
        for (int ks = 0; ks < 4; ++ks) {
            const uint32_t kc = ks * 16 + lk8;
            #pragma unroll
            for (int p = 0; p < 4; ++p) {
                const uint32_t voff = (uint32_t)((p * 16 + lr16) * QSTR + kc) * 2;
                uint32_t vh4[4];
                ldsm4(vh4, kb + 9216 + voff);
                uint32_t be[2] = {vh4[0], vh4[2]};
                uint32_t bo[2] = {vh4[1], vh4[3]};
                mma_f16(o[2 * p],     pah[ks], be);
                mma_f16(o[2 * p],     pal[ks], be);
                mma_f16(o[2 * p + 1], pah[ks], bo);
                mma_f16(o[2 * p + 1], pal[ks], bo);
            }
        }
    }

    // epilogue
    const float inv0 = 1.0f / l0r;
    const float inv1 = 1.0f / l1r;
    #pragma unroll
    for (int ntd = 0; ntd < 8; ++ntd) {
        const int d = h * HD_ + ntd * 8 + 2 * t;
        float2 r0 = make_float2(o[ntd][0] * inv0, o[ntd][1] * inv0);
        float2 r1 = make_float2(o[ntd][2] * inv1, o[ntd][3] * inv1);
        *(float2*)&out[((size_t)b * S_ + i0) * H_ + d] = r0;
        *(float2*)&out[((size_t)b * S_ + i1) * H_ + d] = r1;
    }
}

// ---------------------------------------------------------------------------
// Launch
// ---------------------------------------------------------------------------
extern "C" void kernel_launch(void* const* d_in, const int* in_sizes, int n_in,
                              void* d_out, int out_size)
{
    const float* hidden = (const float*)d_in[0];
    const float* amask  = (const float*)d_in[1];
    const float* Wq = (const float*)d_in[2];
    const float* bq = (const float*)d_in[3];
    const float* Wk = (const float*)d_in[4];
    const float* bk = (const float*)d_in[5];
    const float* Wv = (const float*)d_in[6];
    const float* bv = (const float*)d_in[7];
    float* out = (float*)d_out;

    // prepass rounds
    split_kernel<<<(MROWS * H_ / 4 + 255) / 256, 256>>>(hidden, 0, MROWS * H_ / 4);
    split_kernel<<<(H_ * H_ / 4 + 255) / 256, 256>>>(Wq, 1, H_ * H_ / 4);
    split_kernel<<<(H_ * H_ / 4 + 255) / 256, 256>>>(Wk, 2, H_ * H_ / 4);
    split_kernel<<<(H_ * H_ / 4 + 255) / 256, 256>>>(Wv, 3, H_ * H_ / 4);

    // QKV projection: grid (8 n-tiles, 64 m-tiles, 3)
    cudaFuncSetAttribute(qkv_kernel,
                         cudaFuncAttributeMaxDynamicSharedMemorySize, QKV_SMEM);
    dim3 ggrid(H_ / 128, MROWS / 128, 3);
    qkv_kernel<<<ggrid, 256, QKV_SMEM>>>(bq, bk, bv);

    // attention: grid (16 q-tiles, 64 bh)
    cudaFuncSetAttribute(attn_kernel,
                         cudaFuncAttributeMaxDynamicSharedMemorySize, ATT_SMEM);
    dim3 agrid(S_ / 128, B_ * NH_);
    attn_kernel<<<agrid, 256, ATT_SMEM>>>(amask, out);
}

// round 10
// speedup vs baseline: 6.7830x; 1.1550x over previous
#include <cuda_runtime.h>
#include <cuda_fp16.h>
#include <cstdint>

// Problem constants
#define B_   4
#define S_   2048
#define H_   1024
#define NH_  16
#define HD_  64
#define MROWS (B_ * S_)        // 8192

// ---------------------------------------------------------------------------
// Scratch (device globals). All operands single fp16, fp32 accumulation.
// ---------------------------------------------------------------------------
__device__ __half g_xh[(size_t)MROWS * H_];
__device__ __half g_wh[3][(size_t)H_ * H_];
// Q,K: [bh][s][d]; V transposed: [bh][d][s]
__device__ __half g_qh[(size_t)B_ * NH_ * S_ * HD_];
__device__ __half g_kh[(size_t)B_ * NH_ * S_ * HD_];
__device__ __half g_vth[(size_t)B_ * NH_ * S_ * HD_];

// ---------------------------------------------------------------------------
// helpers
// ---------------------------------------------------------------------------
__device__ __forceinline__ void mma_f16(float* d, const uint32_t* a, const uint32_t* b) {
    asm volatile(
        "mma.sync.aligned.m16n8k16.row.col.f32.f16.f16.f32 "
        "{%0,%1,%2,%3},{%4,%5,%6,%7},{%8,%9},{%0,%1,%2,%3};"
        : "+f"(d[0]), "+f"(d[1]), "+f"(d[2]), "+f"(d[3])
        : "r"(a[0]), "r"(a[1]), "r"(a[2]), "r"(a[3]), "r"(b[0]), "r"(b[1]));
}

__device__ __forceinline__ void ldsm4(uint32_t* r, uint32_t addr) {
    asm volatile(
        "ldmatrix.sync.aligned.m8n8.x4.shared.b16 {%0,%1,%2,%3}, [%4];"
        : "=r"(r[0]), "=r"(r[1]), "=r"(r[2]), "=r"(r[3]) : "r"(addr));
}

__device__ __forceinline__ uint32_t smem_u32(const void* p) {
    uint32_t a;
    asm("{ .reg .u64 tmp; cvta.to.shared.u64 tmp, %1; cvt.u32.u64 %0, tmp; }"
        : "=r"(a) : "l"(p));
    return a;
}

#define CP16(dst, src) \
    asm volatile("cp.async.cg.shared.global [%0], [%1], 16;" \
                 :: "r"(dst), "l"(src) : "memory")
#define CP_COMMIT() asm volatile("cp.async.commit_group;" ::: "memory")
#define CP_WAIT0()  asm volatile("cp.async.wait_group 0;" ::: "memory")

__device__ __forceinline__ uint32_t pack2h(float a, float b) {
    __half2 v; v.x = __float2half_rn(a); v.y = __float2half_rn(b);
    return *(uint32_t*)&v;
}

// ---------------------------------------------------------------------------
// Kernel 0a: X fp32 -> fp16.   Kernel 0b: W fp32 -> fp16 (z = 0..2).
// ---------------------------------------------------------------------------
__global__ void split_x_kernel(const float* __restrict__ src, int n4)
{
    int i = blockIdx.x * blockDim.x + threadIdx.x;
    if (i >= n4) return;
    float4 v = ((const float4*)src)[i];
    ((uint32_t*)g_xh)[i * 2]     = pack2h(v.x, v.y);
    ((uint32_t*)g_xh)[i * 2 + 1] = pack2h(v.z, v.w);
}

__global__ void split_w_kernel(const float* __restrict__ w0,
                               const float* __restrict__ w1,
                               const float* __restrict__ w2, int n4)
{
    int i = blockIdx.x * blockDim.x + threadIdx.x;
    if (i >= n4) return;
    const int z = blockIdx.y;
    const float* src = (z == 0) ? w0 : (z == 1) ? w1 : w2;
    float4 v = ((const float4*)src)[i];
    ((uint32_t*)g_wh[z])[i * 2]     = pack2h(v.x, v.y);
    ((uint32_t*)g_wh[z])[i * 2 + 1] = pack2h(v.z, v.w);
}

// ---------------------------------------------------------------------------
// Kernel 1: QKV projection, single-term fp16 HGEMM (fp32 accum).
// CTA 128x128, BK=32, 8 warps (4m x 2n), warp tile 32x64.
// smem per buffer: Xh@0, Wh@10240 (each 128 x 40 halves = 10240 B)
// ---------------------------------------------------------------------------
#define GSTR 40
#define GBUF_B 20480
#define QKV_SMEM (2 * GBUF_B)

__global__ __launch_bounds__(256, 2)
void qkv_kernel(const float* __restrict__ bq,
                const float* __restrict__ bk,
                const float* __restrict__ bv)
{
    extern __shared__ char smem[];
    const uint32_t sb = smem_u32(smem);
    const int tid  = threadIdx.x;
    const int lane = tid & 31;
    const int w    = tid >> 5;
    const int wm = (w >> 1) * 32;
    const int wn = (w & 1) * 64;
    const int g = lane >> 2;
    const int t = lane & 3;
    const int lr16 = lane & 15;
    const int lk8  = (lane >> 4) * 8;

    const int z  = blockIdx.z;
    const int n0 = blockIdx.x * 128;
    const int m0 = blockIdx.y * 128;
    const __half* __restrict__ Wh = g_wh[z];
    const float* __restrict__ bias = (z == 0) ? bq : (z == 1) ? bk : bv;

    auto issue = [&](int ck, int bsel) {
        const int k0 = ck * 32;
        const uint32_t bb = sb + bsel * GBUF_B;
        #pragma unroll
        for (int i = 0; i < 2; ++i) {
            const int idx = i * 256 + tid;
            const int r = idx >> 2, c = idx & 3;
            const uint32_t doff = (uint32_t)(r * GSTR + c * 8) * 2;
            CP16(bb + doff,         (const char*)&g_xh[(size_t)(m0 + r) * H_ + k0 + c * 8]);
            CP16(bb + 10240 + doff, (const char*)&Wh[(size_t)(n0 + r) * H_ + k0 + c * 8]);
        }
    };

    float acc[2][8][4] = {};

    issue(0, 0);
    CP_COMMIT();

    const int NCH = H_ / 32;  // 32
    for (int ck = 0; ck < NCH; ++ck) {
        const int bsel = ck & 1;
        CP_WAIT0();
        __syncthreads();
        if (ck + 1 < NCH) issue(ck + 1, bsel ^ 1);
        CP_COMMIT();

        const uint32_t bb = sb + bsel * GBUF_B;
        #pragma unroll
        for (int ks = 0; ks < 2; ++ks) {
            const uint32_t kc = ks * 16 + lk8;
            uint32_t ah[2][4];
            #pragma unroll
            for (int mt = 0; mt < 2; ++mt) {
                const uint32_t aoff = (uint32_t)((wm + mt * 16 + lr16) * GSTR + kc) * 2;
                ldsm4(ah[mt], bb + aoff);
            }
            #pragma unroll
            for (int np = 0; np < 4; ++np) {
                const uint32_t boff = (uint32_t)((wn + np * 16 + lr16) * GSTR + kc) * 2;
                uint32_t bh4[4];
                ldsm4(bh4, bb + 10240 + boff);
                uint32_t be[2] = {bh4[0], bh4[2]};
                uint32_t bo[2] = {bh4[1], bh4[3]};
                #pragma unroll
                for (int mt = 0; mt < 2; ++mt) {
                    mma_f16(acc[mt][2 * np],     ah[mt], be);
                    mma_f16(acc[mt][2 * np + 1], ah[mt], bo);
                }
            }
        }
    }

    // epilogue: bias + store (Q,K head-major; V transposed)
    const int bidx  = m0 >> 11;
    const int sbase = (m0 & (S_ - 1));
    #pragma unroll
    for (int mt = 0; mt < 2; ++mt) {
        #pragma unroll
        for (int nt = 0; nt < 8; ++nt) {
            const int nloc = wn + nt * 8 + 2 * t;
            const int d    = nloc & 63;
            const int hh   = (n0 + nloc) >> 6;
            const int bh_i = bidx * NH_ + hh;
            const float2 bi = *(const float2*)&bias[n0 + nloc];
            const int s0 = sbase + wm + mt * 16 + g;
            const float v0 = acc[mt][nt][0] + bi.x;
            const float v1 = acc[mt][nt][1] + bi.y;
            const float v2 = acc[mt][nt][2] + bi.x;
            const float v3 = acc[mt][nt][3] + bi.y;
            if (z < 2) {
                __half* dst = (z == 0) ? g_qh : g_kh;
                *(uint32_t*)&dst[((size_t)bh_i * S_ + s0) * HD_ + d]     = pack2h(v0, v1);
                *(uint32_t*)&dst[((size_t)bh_i * S_ + s0 + 8) * HD_ + d] = pack2h(v2, v3);
            } else {
                g_vth[((size_t)bh_i * HD_ + d)     * S_ + s0]     = __float2half_rn(v0);
                g_vth[((size_t)bh_i * HD_ + d + 1) * S_ + s0]     = __float2half_rn(v1);
                g_vth[((size_t)bh_i * HD_ + d)     * S_ + s0 + 8] = __float2half_rn(v2);
                g_vth[((size_t)bh_i * HD_ + d + 1) * S_ + s0 + 8] = __float2half_rn(v3);
            }
        }
    }
}

// ---------------------------------------------------------------------------
// Kernel 2: causal flash attention. QK and PV single-term fp16 (fp32 accum).
// CTA: 128 q rows; KV tiles of 64; 8 warps x 16 q rows.
// smem (bytes): Q@0 (128 x 72 halves = 18432) |
//   KVbuf[2] @18432 (each: K 9216 + V 9216) | amask[2][64] @55296. Total 55808.
// ---------------------------------------------------------------------------
#define QSTR 72
#define ATT_Q 0u
#define ATT_KV0 18432u
#define ATT_KVSZ 18432u
#define ATT_AM 55296u
#define ATT_SMEM 55808

__global__ __launch_bounds__(256, 2)
void attn_kernel(const float* __restrict__ amask, float* __restrict__ out)
{
    extern __shared__ char smem[];
    const uint32_t sb = smem_u32(smem);
    const int qt = 15 - (int)blockIdx.x;  // heavy tiles first
    const int bh = blockIdx.y;
    const int b  = bh >> 4;
    const int h  = bh & 15;
    const int q0 = qt * 128;
    const int tid  = threadIdx.x;
    const int lane = tid & 31;
    const int w    = tid >> 5;
    const int g = lane >> 2;
    const int t = lane & 3;
    const int lr16 = lane & 15;
    const int lk8  = (lane >> 4) * 8;

    float* sAm = (float*)(smem + ATT_AM);

    // Q tile: 128 x 64 fp16 (18432 bytes)
    #pragma unroll
    for (int i = 0; i < 2; ++i) {
        const int idx = i * 256 + tid;
        const int r = idx >> 2, c = idx & 3;
        *(uint4*)(smem + ATT_Q + (r * QSTR + c * 16) * 2) =
            *(const uint4*)&g_qh[((size_t)bh * S_ + q0 + r) * HD_ + c * 16];
        *(uint4*)(smem + ATT_Q + (r * QSTR + c * 16 + 8) * 2) =
            *(const uint4*)&g_qh[((size_t)bh * S_ + q0 + r) * HD_ + c * 16 + 8];
    }

    auto issue_kv = [&](int kt, int bsel) {
        const int j0 = kt * 64;
        const uint32_t kb = sb + ATT_KV0 + bsel * ATT_KVSZ;
        #pragma unroll
        for (int i = 0; i < 2; ++i) {
            const int idx = i * 256 + tid;
            const int r = idx >> 3, c = idx & 7;
            const uint32_t doff = (uint32_t)(r * QSTR + c * 8) * 2;
            CP16(kb + doff,
                 (const char*)&g_kh[((size_t)bh * S_ + j0 + r) * HD_ + c * 8]);
            CP16(kb + 9216 + doff,
                 (const char*)&g_vth[((size_t)bh * HD_ + r) * S_ + j0 + c * 8]);
        }
    };

    issue_kv(0, 0);
    CP_COMMIT();
    if (tid < 16)
        *(float4*)&sAm[tid * 4] = *(const float4*)&amask[(size_t)b * S_ + tid * 4];

    // hoist Q fragments (kt-invariant) — safe after this sync
    __syncthreads();
    uint32_t q4[4][4];
    #pragma unroll
    for (int ks = 0; ks < 4; ++ks) {
        const uint32_t kc = ks * 16 + lk8;
        const uint32_t qoff = (uint32_t)((w * 16 + lr16) * QSTR + kc) * 2;
        ldsm4(q4[ks], sb + ATT_Q + qoff);
    }

    float o[8][4] = {};
    float m0r = -1e30f, m1r = -1e30f;
    float l0r = 0.f, l1r = 0.f;
    const int i0 = q0 + w * 16 + g;
    const int i1 = i0 + 8;

    const int nkv = 2 * qt + 2;
    for (int kt = 0; kt < nkv; ++kt) {
        const int j0 = kt * 64;
        const int bsel = kt & 1;
        CP_WAIT0();
        __syncthreads();
        if (kt + 1 < nkv) {
            issue_kv(kt + 1, bsel ^ 1);
            if (tid < 16)
                *(float4*)&sAm[((kt + 1) & 1) * 64 + tid * 4] =
                    *(const float4*)&amask[(size_t)b * S_ + (j0 + 64) + tid * 4];
        }
        CP_COMMIT();

        if (j0 > q0 + w * 16 + 15) continue;  // fully masked for this warp

        const uint32_t kb = sb + ATT_KV0 + bsel * ATT_KVSZ;
        const float* am = sAm + bsel * 64;

        // ---- S = Q @ K^T (single-term fp16) ----
        float s[8][4] = {};
        #pragma unroll
        for (int ks = 0; ks < 4; ++ks) {
            const uint32_t kc = ks * 16 + lk8;
            #pragma unroll
            for (int p = 0; p < 4; ++p) {
                const uint32_t koff = (uint32_t)((p * 16 + lr16) * QSTR + kc) * 2;
                uint32_t kh4[4];
                ldsm4(kh4, kb + koff);
                uint32_t be[2] = {kh4[0], kh4[2]};
                uint32_t bo[2] = {kh4[1], kh4[3]};
                mma_f16(s[2 * p],     q4[ks], be);
                mma_f16(s[2 * p + 1], q4[ks], bo);
            }
        }

        // ---- mask + online softmax (MUFU exp) ----
        const bool needm = (j0 + 63 > q0 + w * 16);
        float rm0 = -1e30f, rm1 = -1e30f;
        #pragma unroll
        for (int ntj = 0; ntj < 8; ++ntj) {
            const float2 amv = *(const float2*)&am[ntj * 8 + 2 * t];
            const int j = j0 + ntj * 8 + 2 * t;
            float v0 = (s[ntj][0] + amv.x) * 0.125f;
            float v1 = (s[ntj][1] + amv.y) * 0.125f;
            float v2 = (s[ntj][2] + amv.x) * 0.125f;
            float v3 = (s[ntj][3] + amv.y) * 0.125f;
            if (needm) {
                if (j     > i0) v0 = -1e30f;
                if (j + 1 > i0) v1 = -1e30f;
                if (j     > i1) v2 = -1e30f;
                if (j + 1 > i1) v3 = -1e30f;
            }
            s[ntj][0] = v0; s[ntj][1] = v1; s[ntj][2] = v2; s[ntj][3] = v3;
            rm0 = fmaxf(rm0, fmaxf(v0, v1));
            rm1 = fmaxf(rm1, fmaxf(v2, v3));
        }
        rm0 = fmaxf(rm0, __shfl_xor_sync(0xffffffffu, rm0, 1));
        rm0 = fmaxf(rm0, __shfl_xor_sync(0xffffffffu, rm0, 2));
        rm1 = fmaxf(rm1, __shfl_xor_sync(0xffffffffu, rm1, 1));
        rm1 = fmaxf(rm1, __shfl_xor_sync(0xffffffffu, rm1, 2));

        const float mn0 = fmaxf(m0r, rm0);
        const float mn1 = fmaxf(m1r, rm1);
        const float c0 = __expf(m0r - mn0);
        const float c1 = __expf(m1r - mn1);
        m0r = mn0; m1r = mn1;

        float rs0 = 0.f, rs1 = 0.f;
        #pragma unroll
        for (int ntj = 0; ntj < 8; ++ntj) {
            float p0 = __expf(s[ntj][0] - mn0);
            float p1 = __expf(s[ntj][1] - mn0);
            float p2 = __expf(s[ntj][2] - mn1);
            float p3 = __expf(s[ntj][3] - mn1);
            s[ntj][0] = p0; s[ntj][1] = p1; s[ntj][2] = p2; s[ntj][3] = p3;
            rs0 += p0 + p1;
            rs1 += p2 + p3;
        }
        rs0 += __shfl_xor_sync(0xffffffffu, rs0, 1);
        rs0 += __shfl_xor_sync(0xffffffffu, rs0, 2);
        rs1 += __shfl_xor_sync(0xffffffffu, rs1, 1);
        rs1 += __shfl_xor_sync(0xffffffffu, rs1, 2);
        l0r = l0r * c0 + rs0;
        l1r = l1r * c1 + rs1;
        #pragma unroll
        for (int ntd = 0; ntd < 8; ++ntd) {
            o[ntd][0] *= c0; o[ntd][1] *= c0;
            o[ntd][2] *= c1; o[ntd][3] *= c1;
        }

        // ---- pack P into fp16 A-fragments (C layout == A layout) ----
        uint32_t pa[4][4];
        #pragma unroll
        for (int ks = 0; ks < 4; ++ks) {
            pa[ks][0] = pack2h(s[2 * ks][0],     s[2 * ks][1]);
            pa[ks][1] = pack2h(s[2 * ks][2],     s[2 * ks][3]);
            pa[ks][2] = pack2h(s[2 * ks + 1][0], s[2 * ks + 1][1]);
            pa[ks][3] = pack2h(s[2 * ks + 1][2], s[2 * ks + 1][3]);
        }

        // ---- O += P @ V (single-term fp16) ----
        #pragma unroll
        for (int ks = 0; ks < 4; ++ks) {
            const uint32_t kc = ks * 16 + lk8;
            #pragma unroll
            for (int p = 0; p < 4; ++p) {
                const uint32_t voff = (uint32_t)((p * 16 + lr16) * QSTR + kc) * 2;
                uint32_t vh4[4];
                ldsm4(vh4, kb + 9216 + voff);
                uint32_t be[2] = {vh4[0], vh4[2]};
                uint32_t bo[2] = {vh4[1], vh4[3]};
                mma_f16(o[2 * p],     pa[ks], be);
                mma_f16(o[2 * p + 1], pa[ks], bo);
            }
        }
    }

    // epilogue
    const float inv0 = 1.0f / l0r;
    const float inv1 = 1.0f / l1r;
    #pragma unroll
    for (int ntd = 0; ntd < 8; ++ntd) {
        const int d = h * HD_ + ntd * 8 + 2 * t;
        float2 r0 = make_float2(o[ntd][0] * inv0, o[ntd][1] * inv0);
        float2 r1 = make_float2(o[ntd][2] * inv1, o[ntd][3] * inv1);
        *(float2*)&out[((size_t)b * S_ + i0) * H_ + d] = r0;
        *(float2*)&out[((size_t)b * S_ + i1) * H_ + d] = r1;
    }
}

// ---------------------------------------------------------------------------
// Launch
// ---------------------------------------------------------------------------
extern "C" void kernel_launch(void* const* d_in, const int* in_sizes, int n_in,
                              void* d_out, int out_size)
{
    const float* hidden = (const float*)d_in[0];
    const float* amask  = (const float*)d_in[1];
    const float* Wq = (const float*)d_in[2];
    const float* bq = (const float*)d_in[3];
    const float* Wk = (const float*)d_in[4];
    const float* bk = (const float*)d_in[5];
    const float* Wv = (const float*)d_in[6];
    const float* bv = (const float*)d_in[7];
    float* out = (float*)d_out;

    // prepass rounds (2 launches)
    const int nx4 = MROWS * H_ / 4;
    const int nw4 = H_ * H_ / 4;
    split_x_kernel<<<(nx4 + 255) / 256, 256>>>(hidden, nx4);
    dim3 wgrid((nw4 + 255) / 256, 3);
    split_w_kernel<<<wgrid, 256>>>(Wq, Wk, Wv, nw4);

    // QKV projection: grid (8 n-tiles, 64 m-tiles, 3)
    cudaFuncSetAttribute(qkv_kernel,
                         cudaFuncAttributeMaxDynamicSharedMemorySize, QKV_SMEM);
    dim3 ggrid(H_ / 128, MROWS / 128, 3);
    qkv_kernel<<<ggrid, 256, QKV_SMEM>>>(bq, bk, bv);

    // attention: grid (16 q-tiles, 64 bh)
    cudaFuncSetAttribute(attn_kernel,
                         cudaFuncAttributeMaxDynamicSharedMemorySize, ATT_SMEM);
    dim3 agrid(S_ / 128, B_ * NH_);
    attn_kernel<<<agrid, 256, ATT_SMEM>>>(amask, out);
}

// round 11
// speedup vs baseline: 7.1823x; 1.0589x over previous
#include <cuda_runtime.h>
#include <cuda_fp16.h>
#include <cstdint>

// Problem constants
#define B_   4
#define S_   2048
#define H_   1024
#define NH_  16
#define HD_  64
#define MROWS (B_ * S_)        // 8192

// softmax folded scale: 1/8 * log2(e)
#define QSCALE 0.18033688011112042f

// ---------------------------------------------------------------------------
// Scratch (device globals). All operands single fp16, fp32 accumulation.
// Q is pre-scaled by QSCALE. Q,K,V all [bh][s][d].
// ---------------------------------------------------------------------------
__device__ __half g_xh[(size_t)MROWS * H_];
__device__ __half g_wh[3][(size_t)H_ * H_];
__device__ __half g_qh[(size_t)B_ * NH_ * S_ * HD_];
__device__ __half g_kh[(size_t)B_ * NH_ * S_ * HD_];
__device__ __half g_vh[(size_t)B_ * NH_ * S_ * HD_];

// ---------------------------------------------------------------------------
// helpers
// ---------------------------------------------------------------------------
__device__ __forceinline__ void mma_f16(float* d, const uint32_t* a, const uint32_t* b) {
    asm volatile(
        "mma.sync.aligned.m16n8k16.row.col.f32.f16.f16.f32 "
        "{%0,%1,%2,%3},{%4,%5,%6,%7},{%8,%9},{%0,%1,%2,%3};"
        : "+f"(d[0]), "+f"(d[1]), "+f"(d[2]), "+f"(d[3])
        : "r"(a[0]), "r"(a[1]), "r"(a[2]), "r"(a[3]), "r"(b[0]), "r"(b[1]));
}

__device__ __forceinline__ void ldsm4(uint32_t* r, uint32_t addr) {
    asm volatile(
        "ldmatrix.sync.aligned.m8n8.x4.shared.b16 {%0,%1,%2,%3}, [%4];"
        : "=r"(r[0]), "=r"(r[1]), "=r"(r[2]), "=r"(r[3]) : "r"(addr));
}

__device__ __forceinline__ void ldsm4t(uint32_t* r, uint32_t addr) {
    asm volatile(
        "ldmatrix.sync.aligned.m8n8.x4.trans.shared.b16 {%0,%1,%2,%3}, [%4];"
        : "=r"(r[0]), "=r"(r[1]), "=r"(r[2]), "=r"(r[3]) : "r"(addr));
}

__device__ __forceinline__ float ex2(float x) {
    float r;
    asm("ex2.approx.f32 %0, %1;" : "=f"(r) : "f"(x));
    return r;
}

__device__ __forceinline__ uint32_t smem_u32(const void* p) {
    uint32_t a;
    asm("{ .reg .u64 tmp; cvta.to.shared.u64 tmp, %1; cvt.u32.u64 %0, tmp; }"
        : "=r"(a) : "l"(p));
    return a;
}

#define CP16(dst, src) \
    asm volatile("cp.async.cg.shared.global [%0], [%1], 16;" \
                 :: "r"(dst), "l"(src) : "memory")
#define CP_COMMIT() asm volatile("cp.async.commit_group;" ::: "memory")
#define CP_WAIT0()  asm volatile("cp.async.wait_group 0;" ::: "memory")

__device__ __forceinline__ uint32_t pack2h(float a, float b) {
    __half2 v = __floats2half2_rn(a, b);
    return *(uint32_t*)&v;
}

// ---------------------------------------------------------------------------
// Kernel 0a: X fp32 -> fp16.   Kernel 0b: W fp32 -> fp16 (z = 0..2).
// ---------------------------------------------------------------------------
__global__ void split_x_kernel(const float* __restrict__ src, int n4)
{
    int i = blockIdx.x * blockDim.x + threadIdx.x;
    if (i >= n4) return;
    float4 v = ((const float4*)src)[i];
    ((uint32_t*)g_xh)[i * 2]     = pack2h(v.x, v.y);
    ((uint32_t*)g_xh)[i * 2 + 1] = pack2h(v.z, v.w);
}

__global__ void split_w_kernel(const float* __restrict__ w0,
                               const float* __restrict__ w1,
                               const float* __restrict__ w2, int n4)
{
    int i = blockIdx.x * blockDim.x + threadIdx.x;
    if (i >= n4) return;
    const int z = blockIdx.y;
    const float* src = (z == 0) ? w0 : (z == 1) ? w1 : w2;
    float4 v = ((const float4*)src)[i];
    ((uint32_t*)g_wh[z])[i * 2]     = pack2h(v.x, v.y);
    ((uint32_t*)g_wh[z])[i * 2 + 1] = pack2h(v.z, v.w);
}

// ---------------------------------------------------------------------------
// Kernel 1: QKV projection, single-term fp16 HGEMM (fp32 accum).
// CTA 128x128, BK=32, 8 warps (4m x 2n), warp tile 32x64.
// Q stored pre-scaled by QSCALE; all outputs [bh][s][d], vectorized stores.
// ---------------------------------------------------------------------------
#define GSTR 40
#define GBUF_B 20480
#define QKV_SMEM (2 * GBUF_B)

__global__ __launch_bounds__(256, 2)
void qkv_kernel(const float* __restrict__ bq,
                const float* __restrict__ bk,
                const float* __restrict__ bv)
{
    extern __shared__ char smem[];
    const uint32_t sb = smem_u32(smem);
    const int tid  = threadIdx.x;
    const int lane = tid & 31;
    const int w    = tid >> 5;
    const int wm = (w >> 1) * 32;
    const int wn = (w & 1) * 64;
    const int g = lane >> 2;
    const int t = lane & 3;
    const int lr16 = lane & 15;
    const int lk8  = (lane >> 4) * 8;

    const int z  = blockIdx.z;
    const int n0 = blockIdx.x * 128;
    const int m0 = blockIdx.y * 128;
    const __half* __restrict__ Wh = g_wh[z];
    const float* __restrict__ bias = (z == 0) ? bq : (z == 1) ? bk : bv;

    auto issue = [&](int ck, int bsel) {
        const int k0 = ck * 32;
        const uint32_t bb = sb + bsel * GBUF_B;
        #pragma unroll
        for (int i = 0; i < 2; ++i) {
            const int idx = i * 256 + tid;
            const int r = idx >> 2, c = idx & 3;
            const uint32_t doff = (uint32_t)(r * GSTR + c * 8) * 2;
            CP16(bb + doff,         (const char*)&g_xh[(size_t)(m0 + r) * H_ + k0 + c * 8]);
            CP16(bb + 10240 + doff, (const char*)&Wh[(size_t)(n0 + r) * H_ + k0 + c * 8]);
        }
    };

    float acc[2][8][4] = {};

    issue(0, 0);
    CP_COMMIT();

    const int NCH = H_ / 32;  // 32
    for (int ck = 0; ck < NCH; ++ck) {
        const int bsel = ck & 1;
        CP_WAIT0();
        __syncthreads();
        if (ck + 1 < NCH) issue(ck + 1, bsel ^ 1);
        CP_COMMIT();

        const uint32_t bb = sb + bsel * GBUF_B;
        #pragma unroll
        for (int ks = 0; ks < 2; ++ks) {
            const uint32_t kc = ks * 16 + lk8;
            uint32_t ah[2][4];
            #pragma unroll
            for (int mt = 0; mt < 2; ++mt) {
                const uint32_t aoff = (uint32_t)((wm + mt * 16 + lr16) * GSTR + kc) * 2;
                ldsm4(ah[mt], bb + aoff);
            }
            #pragma unroll
            for (int np = 0; np < 4; ++np) {
                const uint32_t boff = (uint32_t)((wn + np * 16 + lr16) * GSTR + kc) * 2;
                uint32_t bh4[4];
                ldsm4(bh4, bb + 10240 + boff);
                uint32_t be[2] = {bh4[0], bh4[2]};
                uint32_t bo[2] = {bh4[1], bh4[3]};
                #pragma unroll
                for (int mt = 0; mt < 2; ++mt) {
                    mma_f16(acc[mt][2 * np],     ah[mt], be);
                    mma_f16(acc[mt][2 * np + 1], ah[mt], bo);
                }
            }
        }
    }

    // epilogue: bias (+QSCALE for Q) + vectorized head-major store
    const int bidx  = m0 >> 11;
    const int sbase = (m0 & (S_ - 1));
    __half* dst = (z == 0) ? g_qh : (z == 1) ? g_kh : g_vh;
    const float sc = (z == 0) ? QSCALE : 1.0f;
    #pragma unroll
    for (int mt = 0; mt < 2; ++mt) {
        #pragma unroll
        for (int nt = 0; nt < 8; ++nt) {
            const int nloc = wn + nt * 8 + 2 * t;
            const int d    = nloc & 63;
            const int hh   = (n0 + nloc) >> 6;
            const int bh_i = bidx * NH_ + hh;
            const float2 bi = *(const float2*)&bias[n0 + nloc];
            const int s0 = sbase + wm + mt * 16 + g;
            const float v0 = (acc[mt][nt][0] + bi.x) * sc;
            const float v1 = (acc[mt][nt][1] + bi.y) * sc;
            const float v2 = (acc[mt][nt][2] + bi.x) * sc;
            const float v3 = (acc[mt][nt][3] + bi.y) * sc;
            *(uint32_t*)&dst[((size_t)bh_i * S_ + s0) * HD_ + d]     = pack2h(v0, v1);
            *(uint32_t*)&dst[((size_t)bh_i * S_ + s0 + 8) * HD_ + d] = pack2h(v2, v3);
        }
    }
}

// ---------------------------------------------------------------------------
// Kernel 2: causal flash attention, base-2 softmax (Q pre-scaled).
// CTA: 128 q rows; KV tiles of 64; 8 warps x 16 q rows.
// V loaded [s][d] like K; PV B-fragments via ldmatrix.trans.
// smem (bytes): Q@0 (18432) | KVbuf[2] @18432 (K 9216 + V 9216 each) |
//   amask2[2][64] @55296.  Total 55808.
// ---------------------------------------------------------------------------
#define QSTR 72
#define ATT_Q 0u
#define ATT_KV0 18432u
#define ATT_KVSZ 18432u
#define ATT_AM 55296u
#define ATT_SMEM 55808

__global__ __launch_bounds__(256, 2)
void attn_kernel(const float* __restrict__ amask, float* __restrict__ out)
{
    extern __shared__ char smem[];
    const uint32_t sb = smem_u32(smem);
    const int qt = 15 - (int)blockIdx.x;  // heavy tiles first
    const int bh = blockIdx.y;
    const int b  = bh >> 4;
    const int h  = bh & 15;
    const int q0 = qt * 128;
    const int tid  = threadIdx.x;
    const int lane = tid & 31;
    const int w    = tid >> 5;
    const int g = lane >> 2;
    const int t = lane & 3;
    const int lr16 = lane & 15;
    const int lk8  = (lane >> 4) * 8;

    float* sAm = (float*)(smem + ATT_AM);

    // Q tile: 128 x 64 fp16 (pre-scaled by QSCALE)
    #pragma unroll
    for (int i = 0; i < 2; ++i) {
        const int idx = i * 256 + tid;
        const int r = idx >> 2, c = idx & 3;
        *(uint4*)(smem + ATT_Q + (r * QSTR + c * 16) * 2) =
            *(const uint4*)&g_qh[((size_t)bh * S_ + q0 + r) * HD_ + c * 16];
        *(uint4*)(smem + ATT_Q + (r * QSTR + c * 16 + 8) * 2) =
            *(const uint4*)&g_qh[((size_t)bh * S_ + q0 + r) * HD_ + c * 16 + 8];
    }

    auto issue_kv = [&](int kt, int bsel) {
        const int j0 = kt * 64;
        const uint32_t kb = sb + ATT_KV0 + bsel * ATT_KVSZ;
        #pragma unroll
        for (int i = 0; i < 2; ++i) {
            const int idx = i * 256 + tid;
            const int r = idx >> 3, c = idx & 7;
            const uint32_t doff = (uint32_t)(r * QSTR + c * 8) * 2;
            CP16(kb + doff,
                 (const char*)&g_kh[((size_t)bh * S_ + j0 + r) * HD_ + c * 8]);
            CP16(kb + 9216 + doff,
                 (const char*)&g_vh[((size_t)bh * S_ + j0 + r) * HD_ + c * 8]);
        }
    };

    auto stage_am = [&](int j0, int bsel) {
        if (tid < 16) {
            float4 a = *(const float4*)&amask[(size_t)b * S_ + j0 + tid * 4];
            a.x *= QSCALE; a.y *= QSCALE; a.z *= QSCALE; a.w *= QSCALE;
            *(float4*)&sAm[bsel * 64 + tid * 4] = a;
        }
    };

    issue_kv(0, 0);
    CP_COMMIT();
    stage_am(0, 0);

    // hoist Q fragments (kt-invariant) — safe after this sync
    __syncthreads();
    uint32_t q4[4][4];
    #pragma unroll
    for (int ks = 0; ks < 4; ++ks) {
        const uint32_t kc = ks * 16 + lk8;
        const uint32_t qoff = (uint32_t)((w * 16 + lr16) * QSTR + kc) * 2;
        ldsm4(q4[ks], sb + ATT_Q + qoff);
    }

    float o[8][4] = {};
    float m0r = -1e30f, m1r = -1e30f;
    float l0r = 0.f, l1r = 0.f;
    const int i0 = q0 + w * 16 + g;
    const int i1 = i0 + 8;

    const int nkv = 2 * qt + 2;
    for (int kt = 0; kt < nkv; ++kt) {
        const int j0 = kt * 64;
        const int bsel = kt & 1;
        CP_WAIT0();
        __syncthreads();
        if (kt + 1 < nkv) {
            issue_kv(kt + 1, bsel ^ 1);
            stage_am(j0 + 64, bsel ^ 1);
        }
        CP_COMMIT();

        if (j0 > q0 + w * 16 + 15) continue;  // fully masked for this warp

        const uint32_t kb = sb + ATT_KV0 + bsel * ATT_KVSZ;
        const float* am = sAm + bsel * 64;

        // ---- S = Q @ K^T (base-2 scaled via Q) ----
        float s[8][4] = {};
        #pragma unroll
        for (int ks = 0; ks < 4; ++ks) {
            const uint32_t kc = ks * 16 + lk8;
            #pragma unroll
            for (int p = 0; p < 4; ++p) {
                const uint32_t koff = (uint32_t)((p * 16 + lr16) * QSTR + kc) * 2;
                uint32_t kh4[4];
                ldsm4(kh4, kb + koff);
                uint32_t be[2] = {kh4[0], kh4[2]};
                uint32_t bo[2] = {kh4[1], kh4[3]};
                mma_f16(s[2 * p],     q4[ks], be);
                mma_f16(s[2 * p + 1], q4[ks], bo);
            }
        }

        // ---- mask + online softmax (base-2) ----
        float rm0 = -1e30f, rm1 = -1e30f;
        if (j0 + 63 > q0 + w * 16) {  // diagonal tiles: causal masking needed
            #pragma unroll
            for (int ntj = 0; ntj < 8; ++ntj) {
                const float2 amv = *(const float2*)&am[ntj * 8 + 2 * t];
                const int j = j0 + ntj * 8 + 2 * t;
                float v0 = s[ntj][0] + amv.x;
                float v1 = s[ntj][1] + amv.y;
                float v2 = s[ntj][2] + amv.x;
                float v3 = s[ntj][3] + amv.y;
                if (j     > i0) v0 = -1e30f;
                if (j + 1 > i0) v1 = -1e30f;
                if (j     > i1) v2 = -1e30f;
                if (j + 1 > i1) v3 = -1e30f;
                s[ntj][0] = v0; s[ntj][1] = v1; s[ntj][2] = v2; s[ntj][3] = v3;
                rm0 = fmaxf(rm0, fmaxf(v0, v1));
                rm1 = fmaxf(rm1, fmaxf(v2, v3));
            }
        } else {
            #pragma unroll
            for (int ntj = 0; ntj < 8; ++ntj) {
                const float2 amv = *(const float2*)&am[ntj * 8 + 2 * t];
                float v0 = s[ntj][0] + amv.x;
                float v1 = s[ntj][1] + amv.y;
                float v2 = s[ntj][2] + amv.x;
                float v3 = s[ntj][3] + amv.y;
                s[ntj][0] = v0; s[ntj][1] = v1; s[ntj][2] = v2; s[ntj][3] = v3;
                rm0 = fmaxf(rm0, fmaxf(v0, v1));
                rm1 = fmaxf(rm1, fmaxf(v2, v3));
            }
        }
        rm0 = fmaxf(rm0, __shfl_xor_sync(0xffffffffu, rm0, 1));
        rm0 = fmaxf(rm0, __shfl_xor_sync(0xffffffffu, rm0, 2));
        rm1 = fmaxf(rm1, __shfl_xor_sync(0xffffffffu, rm1, 1));
        rm1 = fmaxf(rm1, __shfl_xor_sync(0xffffffffu, rm1, 2));

        const float mn0 = fmaxf(m0r, rm0);
        const float mn1 = fmaxf(m1r, rm1);
        const float c0 = ex2(m0r - mn0);
        const float c1 = ex2(m1r - mn1);
        m0r = mn0; m1r = mn1;

        float rs0 = 0.f, rs1 = 0.f;
        #pragma unroll
        for (int ntj = 0; ntj < 8; ++ntj) {
            float p0 = ex2(s[ntj][0] - mn0);
            float p1 = ex2(s[ntj][1] - mn0);
            float p2 = ex2(s[ntj][2] - mn1);
            float p3 = ex2(s[ntj][3] - mn1);
            s[ntj][0] = p0; s[ntj][1] = p1; s[ntj][2] = p2; s[ntj][3] = p3;
            rs0 += p0 + p1;
            rs1 += p2 + p3;
        }
        rs0 += __shfl_xor_sync(0xffffffffu, rs0, 1);
        rs0 += __shfl_xor_sync(0xffffffffu, rs0, 2);
        rs1 += __shfl_xor_sync(0xffffffffu, rs1, 1);
        rs1 += __shfl_xor_sync(0xffffffffu, rs1, 2);
        l0r = l0r * c0 + rs0;
        l1r = l1r * c1 + rs1;
        #pragma unroll
        for (int ntd = 0; ntd < 8; ++ntd) {
            o[ntd][0] *= c0; o[ntd][1] *= c0;
            o[ntd][2] *= c1; o[ntd][3] *= c1;
        }

        // ---- pack P into fp16 A-fragments (C layout == A layout) ----
        uint32_t pa[4][4];
        #pragma unroll
        for (int ks = 0; ks < 4; ++ks) {
            pa[ks][0] = pack2h(s[2 * ks][0],     s[2 * ks][1]);
            pa[ks][1] = pack2h(s[2 * ks][2],     s[2 * ks][3]);
            pa[ks][2] = pack2h(s[2 * ks + 1][0], s[2 * ks + 1][1]);
            pa[ks][3] = pack2h(s[2 * ks + 1][2], s[2 * ks + 1][3]);
        }

        // ---- O += P @ V (V in [s][d]; B-fragments via ldmatrix.trans) ----
        #pragma unroll
        for (int ks = 0; ks < 4; ++ks) {
            #pragma unroll
            for (int p = 0; p < 4; ++p) {
                const uint32_t voff =
                    (uint32_t)((ks * 16 + lr16) * QSTR + p * 16 + lk8) * 2;
                uint32_t v4[4];
                ldsm4t(v4, kb + 9216 + voff);
                uint32_t b0[2] = {v4[0], v4[1]};
                uint32_t b1[2] = {v4[2], v4[3]};
                mma_f16(o[2 * p],     pa[ks], b0);
                mma_f16(o[2 * p + 1], pa[ks], b1);
            }
        }
    }

    // epilogue
    const float inv0 = 1.0f / l0r;
    const float inv1 = 1.0f / l1r;
    #pragma unroll
    for (int ntd = 0; ntd < 8; ++ntd) {
        const int d = h * HD_ + ntd * 8 + 2 * t;
        float2 r0 = make_float2(o[ntd][0] * inv0, o[ntd][1] * inv0);
        float2 r1 = make_float2(o[ntd][2] * inv1, o[ntd][3] * inv1);
        *(float2*)&out[((size_t)b * S_ + i0) * H_ + d] = r0;
        *(float2*)&out[((size_t)b * S_ + i1) * H_ + d] = r1;
    }
}

// ---------------------------------------------------------------------------
// Launch
// ---------------------------------------------------------------------------
extern "C" void kernel_launch(void* const* d_in, const int* in_sizes, int n_in,
                              void* d_out, int out_size)
{
    const float* hidden = (const float*)d_in[0];
    const float* amask  = (const float*)d_in[1];
    const float* Wq = (const float*)d_in[2];
    const float* bq = (const float*)d_in[3];
    const float* Wk = (const float*)d_in[4];
    const float* bk = (const float*)d_in[5];
    const float* Wv = (const float*)d_in[6];
    const float* bv = (const float*)d_in[7];
    float* out = (float*)d_out;

    // prepass rounds (2 launches)
    const int nx4 = MROWS * H_ / 4;
    const int nw4 = H_ * H_ / 4;
    split_x_kernel<<<(nx4 + 255) / 256, 256>>>(hidden, nx4);
    dim3 wgrid((nw4 + 255) / 256, 3);
    split_w_kernel<<<wgrid, 256>>>(Wq, Wk, Wv, nw4);

    // QKV projection: grid (8 n-tiles, 64 m-tiles, 3)
    cudaFuncSetAttribute(qkv_kernel,
                         cudaFuncAttributeMaxDynamicSharedMemorySize, QKV_SMEM);
    dim3 ggrid(H_ / 128, MROWS / 128, 3);
    qkv_kernel<<<ggrid, 256, QKV_SMEM>>>(bq, bk, bv);

    // attention: grid (16 q-tiles, 64 bh)
    cudaFuncSetAttribute(attn_kernel,
                         cudaFuncAttributeMaxDynamicSharedMemorySize, ATT_SMEM);
    dim3 agrid(S_ / 128, B_ * NH_);
    attn_kernel<<<agrid, 256, ATT_SMEM>>>(amask, out);
}

// round 12
// speedup vs baseline: 7.3868x; 1.0285x over previous
#include <cuda_runtime.h>
#include <cuda_fp16.h>
#include <cstdint>

// Problem constants
#define B_   4
#define S_   2048
#define H_   1024
#define NH_  16
#define HD_  64
#define MROWS (B_ * S_)        // 8192

// softmax folded scale: 1/8 * log2(e)
#define QSCALE 0.18033688011112042f

// ---------------------------------------------------------------------------
// Scratch (device globals). All operands single fp16, fp32 accumulation.
// Q is pre-scaled by QSCALE. Q,K,V all [bh][s][d].
// ---------------------------------------------------------------------------
__device__ __half g_xh[(size_t)MROWS * H_];
__device__ __half g_wh[3][(size_t)H_ * H_];
__device__ __half g_qh[(size_t)B_ * NH_ * S_ * HD_];
__device__ __half g_kh[(size_t)B_ * NH_ * S_ * HD_];
__device__ __half g_vh[(size_t)B_ * NH_ * S_ * HD_];

// ---------------------------------------------------------------------------
// helpers
// ---------------------------------------------------------------------------
__device__ __forceinline__ void mma_f16(float* d, const uint32_t* a, const uint32_t* b) {
    asm volatile(
        "mma.sync.aligned.m16n8k16.row.col.f32.f16.f16.f32 "
        "{%0,%1,%2,%3},{%4,%5,%6,%7},{%8,%9},{%0,%1,%2,%3};"
        : "+f"(d[0]), "+f"(d[1]), "+f"(d[2]), "+f"(d[3])
        : "r"(a[0]), "r"(a[1]), "r"(a[2]), "r"(a[3]), "r"(b[0]), "r"(b[1]));
}

__device__ __forceinline__ void ldsm4(uint32_t* r, uint32_t addr) {
    asm volatile(
        "ldmatrix.sync.aligned.m8n8.x4.shared.b16 {%0,%1,%2,%3}, [%4];"
        : "=r"(r[0]), "=r"(r[1]), "=r"(r[2]), "=r"(r[3]) : "r"(addr));
}

__device__ __forceinline__ void ldsm4t(uint32_t* r, uint32_t addr) {
    asm volatile(
        "ldmatrix.sync.aligned.m8n8.x4.trans.shared.b16 {%0,%1,%2,%3}, [%4];"
        : "=r"(r[0]), "=r"(r[1]), "=r"(r[2]), "=r"(r[3]) : "r"(addr));
}

__device__ __forceinline__ float ex2(float x) {
    float r;
    asm("ex2.approx.f32 %0, %1;" : "=f"(r) : "f"(x));
    return r;
}

__device__ __forceinline__ uint32_t ex2h2(uint32_t x) {
    uint32_t r;
    asm("ex2.approx.f16x2 %0, %1;" : "=r"(r) : "r"(x));
    return r;
}

__device__ __forceinline__ __half2 u2h(uint32_t x) {
    __half2 h;
    *(uint32_t*)&h = x;
    return h;
}

__device__ __forceinline__ uint32_t smem_u32(const void* p) {
    uint32_t a;
    asm("{ .reg .u64 tmp; cvta.to.shared.u64 tmp, %1; cvt.u32.u64 %0, tmp; }"
        : "=r"(a) : "l"(p));
    return a;
}

#define CP16(dst, src) \
    asm volatile("cp.async.cg.shared.global [%0], [%1], 16;" \
                 :: "r"(dst), "l"(src) : "memory")
#define CP_COMMIT() asm volatile("cp.async.commit_group;" ::: "memory")
#define CP_WAIT0()  asm volatile("cp.async.wait_group 0;" ::: "memory")

__device__ __forceinline__ uint32_t pack2h(float a, float b) {
    __half2 v = __floats2half2_rn(a, b);
    return *(uint32_t*)&v;
}

// ---------------------------------------------------------------------------
// Kernel 0a: X fp32 -> fp16.   Kernel 0b: W fp32 -> fp16 (z = 0..2).
// ---------------------------------------------------------------------------
__global__ void split_x_kernel(const float* __restrict__ src, int n4)
{
    int i = blockIdx.x * blockDim.x + threadIdx.x;
    if (i >= n4) return;
    float4 v = ((const float4*)src)[i];
    ((uint32_t*)g_xh)[i * 2]     = pack2h(v.x, v.y);
    ((uint32_t*)g_xh)[i * 2 + 1] = pack2h(v.z, v.w);
}

__global__ void split_w_kernel(const float* __restrict__ w0,
                               const float* __restrict__ w1,
                               const float* __restrict__ w2, int n4)
{
    int i = blockIdx.x * blockDim.x + threadIdx.x;
    if (i >= n4) return;
    const int z = blockIdx.y;
    const float* src = (z == 0) ? w0 : (z == 1) ? w1 : w2;
    float4 v = ((const float4*)src)[i];
    ((uint32_t*)g_wh[z])[i * 2]     = pack2h(v.x, v.y);
    ((uint32_t*)g_wh[z])[i * 2 + 1] = pack2h(v.z, v.w);
}

// ---------------------------------------------------------------------------
// Kernel 1: QKV projection, single-term fp16 HGEMM (fp32 accum).
// CTA 128x128, BK=32, 8 warps (4m x 2n), warp tile 32x64.
// Q stored pre-scaled by QSCALE; all outputs [bh][s][d], vectorized stores.
// ---------------------------------------------------------------------------
#define GSTR 40
#define GBUF_B 20480
#define QKV_SMEM (2 * GBUF_B)

__global__ __launch_bounds__(256, 2)
void qkv_kernel(const float* __restrict__ bq,
                const float* __restrict__ bk,
                const float* __restrict__ bv)
{
    extern __shared__ char smem[];
    const uint32_t sb = smem_u32(smem);
    const int tid  = threadIdx.x;
    const int lane = tid & 31;
    const int w    = tid >> 5;
    const int wm = (w >> 1) * 32;
    const int wn = (w & 1) * 64;
    const int g = lane >> 2;
    const int t = lane & 3;
    const int lr16 = lane & 15;
    const int lk8  = (lane >> 4) * 8;

    const int z  = blockIdx.z;
    const int n0 = blockIdx.x * 128;
    const int m0 = blockIdx.y * 128;
    const __half* __restrict__ Wh = g_wh[z];
    const float* __restrict__ bias = (z == 0) ? bq : (z == 1) ? bk : bv;

    auto issue = [&](int ck, int bsel) {
        const int k0 = ck * 32;
        const uint32_t bb = sb + bsel * GBUF_B;
        #pragma unroll
        for (int i = 0; i < 2; ++i) {
            const int idx = i * 256 + tid;
            const int r = idx >> 2, c = idx & 3;
            const uint32_t doff = (uint32_t)(r * GSTR + c * 8) * 2;
            CP16(bb + doff,         (const char*)&g_xh[(size_t)(m0 + r) * H_ + k0 + c * 8]);
            CP16(bb + 10240 + doff, (const char*)&Wh[(size_t)(n0 + r) * H_ + k0 + c * 8]);
        }
    };

    float acc[2][8][4] = {};

    issue(0, 0);
    CP_COMMIT();

    const int NCH = H_ / 32;  // 32
    for (int ck = 0; ck < NCH; ++ck) {
        const int bsel = ck & 1;
        CP_WAIT0();
        __syncthreads();
        if (ck + 1 < NCH) issue(ck + 1, bsel ^ 1);
        CP_COMMIT();

        const uint32_t bb = sb + bsel * GBUF_B;
        #pragma unroll
        for (int ks = 0; ks < 2; ++ks) {
            const uint32_t kc = ks * 16 + lk8;
            uint32_t ah[2][4];
            #pragma unroll
            for (int mt = 0; mt < 2; ++mt) {
                const uint32_t aoff = (uint32_t)((wm + mt * 16 + lr16) * GSTR + kc) * 2;
                ldsm4(ah[mt], bb + aoff);
            }
            #pragma unroll
            for (int np = 0; np < 4; ++np) {
                const uint32_t boff = (uint32_t)((wn + np * 16 + lr16) * GSTR + kc) * 2;
                uint32_t bh4[4];
                ldsm4(bh4, bb + 10240 + boff);
                uint32_t be[2] = {bh4[0], bh4[2]};
                uint32_t bo[2] = {bh4[1], bh4[3]};
                #pragma unroll
                for (int mt = 0; mt < 2; ++mt) {
                    mma_f16(acc[mt][2 * np],     ah[mt], be);
                    mma_f16(acc[mt][2 * np + 1], ah[mt], bo);
                }
            }
        }
    }

    // epilogue: bias (+QSCALE for Q) + vectorized head-major store
    const int bidx  = m0 >> 11;
    const int sbase = (m0 & (S_ - 1));
    __half* dst = (z == 0) ? g_qh : (z == 1) ? g_kh : g_vh;
    const float sc = (z == 0) ? QSCALE : 1.0f;
    #pragma unroll
    for (int mt = 0; mt < 2; ++mt) {
        #pragma unroll
        for (int nt = 0; nt < 8; ++nt) {
            const int nloc = wn + nt * 8 + 2 * t;
            const int d    = nloc & 63;
            const int hh   = (n0 + nloc) >> 6;
            const int bh_i = bidx * NH_ + hh;
            const float2 bi = *(const float2*)&bias[n0 + nloc];
            const int s0 = sbase + wm + mt * 16 + g;
            const float v0 = (acc[mt][nt][0] + bi.x) * sc;
            const float v1 = (acc[mt][nt][1] + bi.y) * sc;
            const float v2 = (acc[mt][nt][2] + bi.x) * sc;
            const float v3 = (acc[mt][nt][3] + bi.y) * sc;
            *(uint32_t*)&dst[((size_t)bh_i * S_ + s0) * HD_ + d]     = pack2h(v0, v1);
            *(uint32_t*)&dst[((size_t)bh_i * S_ + s0 + 8) * HD_ + d] = pack2h(v2, v3);
        }
    }
}

// ---------------------------------------------------------------------------
// Kernel 2: causal flash attention, base-2 softmax (Q pre-scaled).
// exp via ex2.approx.f16x2 fused with P packing; row sums via HADD2 tree.
// CTA: 128 q rows; KV tiles of 64; 8 warps x 16 q rows.
// ---------------------------------------------------------------------------
#define QSTR 72
#define ATT_Q 0u
#define ATT_KV0 18432u
#define ATT_KVSZ 18432u
#define ATT_AM 55296u
#define ATT_SMEM 55808

__global__ __launch_bounds__(256, 2)
void attn_kernel(const float* __restrict__ amask, float* __restrict__ out)
{
    extern __shared__ char smem[];
    const uint32_t sb = smem_u32(smem);
    const int qt = 15 - (int)blockIdx.x;  // heavy tiles first
    const int bh = blockIdx.y;
    const int b  = bh >> 4;
    const int h  = bh & 15;
    const int q0 = qt * 128;
    const int tid  = threadIdx.x;
    const int lane = tid & 31;
    const int w    = tid >> 5;
    const int g = lane >> 2;
    const int t = lane & 3;
    const int lr16 = lane & 15;
    const int lk8  = (lane >> 4) * 8;

    float* sAm = (float*)(smem + ATT_AM);

    // Q tile: 128 x 64 fp16 (pre-scaled by QSCALE)
    #pragma unroll
    for (int i = 0; i < 2; ++i) {
        const int idx = i * 256 + tid;
        const int r = idx >> 2, c = idx & 3;
        *(uint4*)(smem + ATT_Q + (r * QSTR + c * 16) * 2) =
            *(const uint4*)&g_qh[((size_t)bh * S_ + q0 + r) * HD_ + c * 16];
        *(uint4*)(smem + ATT_Q + (r * QSTR + c * 16 + 8) * 2) =
            *(const uint4*)&g_qh[((size_t)bh * S_ + q0 + r) * HD_ + c * 16 + 8];
    }

    auto issue_kv = [&](int kt, int bsel) {
        const int j0 = kt * 64;
        const uint32_t kb = sb + ATT_KV0 + bsel * ATT_KVSZ;
        #pragma unroll
        for (int i = 0; i < 2; ++i) {
            const int idx = i * 256 + tid;
            const int r = idx >> 3, c = idx & 7;
            const uint32_t doff = (uint32_t)(r * QSTR + c * 8) * 2;
            CP16(kb + doff,
                 (const char*)&g_kh[((size_t)bh * S_ + j0 + r) * HD_ + c * 8]);
            CP16(kb + 9216 + doff,
                 (const char*)&g_vh[((size_t)bh * S_ + j0 + r) * HD_ + c * 8]);
        }
    };

    auto stage_am = [&](int j0, int bsel) {
        if (tid < 16) {
            float4 a = *(const float4*)&amask[(size_t)b * S_ + j0 + tid * 4];
            a.x *= QSCALE; a.y *= QSCALE; a.z *= QSCALE; a.w *= QSCALE;
            *(float4*)&sAm[bsel * 64 + tid * 4] = a;
        }
    };

    issue_kv(0, 0);
    CP_COMMIT();
    stage_am(0, 0);

    // hoist Q fragments (kt-invariant) — safe after this sync
    __syncthreads();
    uint32_t q4[4][4];
    #pragma unroll
    for (int ks = 0; ks < 4; ++ks) {
        const uint32_t kc = ks * 16 + lk8;
        const uint32_t qoff = (uint32_t)((w * 16 + lr16) * QSTR + kc) * 2;
        ldsm4(q4[ks], sb + ATT_Q + qoff);
    }

    float o[8][4] = {};
    float m0r = -1e30f, m1r = -1e30f;
    float l0r = 0.f, l1r = 0.f;
    const int i0 = q0 + w * 16 + g;
    const int i1 = i0 + 8;

    const int nkv = 2 * qt + 2;
    for (int kt = 0; kt < nkv; ++kt) {
        const int j0 = kt * 64;
        const int bsel = kt & 1;
        CP_WAIT0();
        __syncthreads();
        if (kt + 1 < nkv) {
            issue_kv(kt + 1, bsel ^ 1);
            stage_am(j0 + 64, bsel ^ 1);
        }
        CP_COMMIT();

        if (j0 > q0 + w * 16 + 15) continue;  // fully masked for this warp

        const uint32_t kb = sb + ATT_KV0 + bsel * ATT_KVSZ;
        const float* am = sAm + bsel * 64;

        // ---- S = Q @ K^T (base-2 scaled via Q) ----
        float s[8][4] = {};
        #pragma unroll
        for (int ks = 0; ks < 4; ++ks) {
            const uint32_t kc = ks * 16 + lk8;
            #pragma unroll
            for (int p = 0; p < 4; ++p) {
                const uint32_t koff = (uint32_t)((p * 16 + lr16) * QSTR + kc) * 2;
                uint32_t kh4[4];
                ldsm4(kh4, kb + koff);
                uint32_t be[2] = {kh4[0], kh4[2]};
                uint32_t bo[2] = {kh4[1], kh4[3]};
                mma_f16(s[2 * p],     q4[ks], be);
                mma_f16(s[2 * p + 1], q4[ks], bo);
            }
        }

        // ---- mask + online softmax (base-2) ----
        float rm0 = -1e30f, rm1 = -1e30f;
        if (j0 + 63 > q0 + w * 16) {  // diagonal tiles: causal masking needed
            #pragma unroll
            for (int ntj = 0; ntj < 8; ++ntj) {
                const float2 amv = *(const float2*)&am[ntj * 8 + 2 * t];
                const int j = j0 + ntj * 8 + 2 * t;
                float v0 = s[ntj][0] + amv.x;
                float v1 = s[ntj][1] + amv.y;
                float v2 = s[ntj][2] + amv.x;
                float v3 = s[ntj][3] + amv.y;
                if (j     > i0) v0 = -1e30f;
                if (j + 1 > i0) v1 = -1e30f;
                if (j     > i1) v2 = -1e30f;
                if (j + 1 > i1) v3 = -1e30f;
                s[ntj][0] = v0; s[ntj][1] = v1; s[ntj][2] = v2; s[ntj][3] = v3;
                rm0 = fmaxf(rm0, fmaxf(v0, v1));
                rm1 = fmaxf(rm1, fmaxf(v2, v3));
            }
        } else {
            #pragma unroll
            for (int ntj = 0; ntj < 8; ++ntj) {
                const float2 amv = *(const float2*)&am[ntj * 8 + 2 * t];
                float v0 = s[ntj][0] + amv.x;
                float v1 = s[ntj][1] + amv.y;
                float v2 = s[ntj][2] + amv.x;
                float v3 = s[ntj][3] + amv.y;
                s[ntj][0] = v0; s[ntj][1] = v1; s[ntj][2] = v2; s[ntj][3] = v3;
                rm0 = fmaxf(rm0, fmaxf(v0, v1));
                rm1 = fmaxf(rm1, fmaxf(v2, v3));
            }
        }
        rm0 = fmaxf(rm0, __shfl_xor_sync(0xffffffffu, rm0, 1));
        rm0 = fmaxf(rm0, __shfl_xor_sync(0xffffffffu, rm0, 2));
        rm1 = fmaxf(rm1, __shfl_xor_sync(0xffffffffu, rm1, 1));
        rm1 = fmaxf(rm1, __shfl_xor_sync(0xffffffffu, rm1, 2));

        const float mn0 = fmaxf(m0r, rm0);
        const float mn1 = fmaxf(m1r, rm1);
        const float c0 = ex2(m0r - mn0);
        const float c1 = ex2(m1r - mn1);
        m0r = mn0; m1r = mn1;

        // ---- fused exp + P pack: pa = ex2h2(pack(s - mn)) ----
        uint32_t pa[4][4];
        #pragma unroll
        for (int ks = 0; ks < 4; ++ks) {
            pa[ks][0] = ex2h2(pack2h(s[2 * ks][0]     - mn0, s[2 * ks][1]     - mn0));
            pa[ks][1] = ex2h2(pack2h(s[2 * ks][2]     - mn1, s[2 * ks][3]     - mn1));
            pa[ks][2] = ex2h2(pack2h(s[2 * ks + 1][0] - mn0, s[2 * ks + 1][1] - mn0));
            pa[ks][3] = ex2h2(pack2h(s[2 * ks + 1][2] - mn1, s[2 * ks + 1][3] - mn1));
        }

        // ---- row sums via HADD2 trees ----
        __half2 a0 = __hadd2(__hadd2(u2h(pa[0][0]), u2h(pa[1][0])),
                             __hadd2(u2h(pa[2][0]), u2h(pa[3][0])));
        __half2 b0 = __hadd2(__hadd2(u2h(pa[0][2]), u2h(pa[1][2])),
                             __hadd2(u2h(pa[2][2]), u2h(pa[3][2])));
        float2 f0 = __half22float2(__hadd2(a0, b0));
        float rs0 = f0.x + f0.y;

        __half2 a1 = __hadd2(__hadd2(u2h(pa[0][1]), u2h(pa[1][1])),
                             __hadd2(u2h(pa[2][1]), u2h(pa[3][1])));
        __half2 b1 = __hadd2(__hadd2(u2h(pa[0][3]), u2h(pa[1][3])),
                             __hadd2(u2h(pa[2][3]), u2h(pa[3][3])));
        float2 f1 = __half22float2(__hadd2(a1, b1));
        float rs1 = f1.x + f1.y;

        rs0 += __shfl_xor_sync(0xffffffffu, rs0, 1);
        rs0 += __shfl_xor_sync(0xffffffffu, rs0, 2);
        rs1 += __shfl_xor_sync(0xffffffffu, rs1, 1);
        rs1 += __shfl_xor_sync(0xffffffffu, rs1, 2);
        l0r = l0r * c0 + rs0;
        l1r = l1r * c1 + rs1;
        #pragma unroll
        for (int ntd = 0; ntd < 8; ++ntd) {
            o[ntd][0] *= c0; o[ntd][1] *= c0;
            o[ntd][2] *= c1; o[ntd][3] *= c1;
        }

        // ---- O += P @ V (V in [s][d]; B-fragments via ldmatrix.trans) ----
        #pragma unroll
        for (int ks = 0; ks < 4; ++ks) {
            #pragma unroll
            for (int p = 0; p < 4; ++p) {
                const uint32_t voff =
                    (uint32_t)((ks * 16 + lr16) * QSTR + p * 16 + lk8) * 2;
                uint32_t v4[4];
                ldsm4t(v4, kb + 9216 + voff);
                uint32_t b0v[2] = {v4[0], v4[1]};
                uint32_t b1v[2] = {v4[2], v4[3]};
                mma_f16(o[2 * p],     pa[ks], b0v);
                mma_f16(o[2 * p + 1], pa[ks], b1v);
            }
        }
    }

    // epilogue
    const float inv0 = 1.0f / l0r;
    const float inv1 = 1.0f / l1r;
    #pragma unroll
    for (int ntd = 0; ntd < 8; ++ntd) {
        const int d = h * HD_ + ntd * 8 + 2 * t;
        float2 r0 = make_float2(o[ntd][0] * inv0, o[ntd][1] * inv0);
        float2 r1 = make_float2(o[ntd][2] * inv1, o[ntd][3] * inv1);
        *(float2*)&out[((size_t)b * S_ + i0) * H_ + d] = r0;
        *(float2*)&out[((size_t)b * S_ + i1) * H_ + d] = r1;
    }
}

// ---------------------------------------------------------------------------
// Launch
// ---------------------------------------------------------------------------
extern "C" void kernel_launch(void* const* d_in, const int* in_sizes, int n_in,
                              void* d_out, int out_size)
{
    const float* hidden = (const float*)d_in[0];
    const float* amask  = (const float*)d_in[1];
    const float* Wq = (const float*)d_in[2];
    const float* bq = (const float*)d_in[3];
    const float* Wk = (const float*)d_in[4];
    const float* bk = (const float*)d_in[5];
    const float* Wv = (const float*)d_in[6];
    const float* bv = (const float*)d_in[7];
    float* out = (float*)d_out;

    // prepass rounds (2 launches)
    const int nx4 = MROWS * H_ / 4;
    const int nw4 = H_ * H_ / 4;
    split_x_kernel<<<(nx4 + 255) / 256, 256>>>(hidden, nx4);
    dim3 wgrid((nw4 + 255) / 256, 3);
    split_w_kernel<<<wgrid, 256>>>(Wq, Wk, Wv, nw4);

    // QKV projection: grid (8 n-tiles, 64 m-tiles, 3)
    cudaFuncSetAttribute(qkv_kernel,
                         cudaFuncAttributeMaxDynamicSharedMemorySize, QKV_SMEM);
    dim3 ggrid(H_ / 128, MROWS / 128, 3);
    qkv_kernel<<<ggrid, 256, QKV_SMEM>>>(bq, bk, bv);

    // attention: grid (16 q-tiles, 64 bh)
    cudaFuncSetAttribute(attn_kernel,
                         cudaFuncAttributeMaxDynamicSharedMemorySize, ATT_SMEM);
    dim3 agrid(S_ / 128, B_ * NH_);
    attn_kernel<<<agrid, 256, ATT_SMEM>>>(amask, out);
}

// round 13
// speedup vs baseline: 7.6591x; 1.0369x over previous
#include <cuda_runtime.h>
#include <cuda_fp16.h>
#include <cstdint>

// Problem constants
#define B_   4
#define S_   2048
#define H_   1024
#define NH_  16
#define HD_  64
#define MROWS (B_ * S_)        // 8192

// softmax folded scale: 1/8 * log2(e)
#define QSCALE 0.18033688011112042f

// ---------------------------------------------------------------------------
// Scratch. All operands single fp16, fp32 accumulation. Q pre-scaled.
// ---------------------------------------------------------------------------
__device__ __half g_xh[(size_t)MROWS * H_];
__device__ __half g_wh[3][(size_t)H_ * H_];
__device__ __half g_qh[(size_t)B_ * NH_ * S_ * HD_];
__device__ __half g_kh[(size_t)B_ * NH_ * S_ * HD_];
__device__ __half g_vh[(size_t)B_ * NH_ * S_ * HD_];

// ---------------------------------------------------------------------------
// helpers
// ---------------------------------------------------------------------------
__device__ __forceinline__ void mma_f16(float* d, const uint32_t* a, const uint32_t* b) {
    asm volatile(
        "mma.sync.aligned.m16n8k16.row.col.f32.f16.f16.f32 "
        "{%0,%1,%2,%3},{%4,%5,%6,%7},{%8,%9},{%0,%1,%2,%3};"
        : "+f"(d[0]), "+f"(d[1]), "+f"(d[2]), "+f"(d[3])
        : "r"(a[0]), "r"(a[1]), "r"(a[2]), "r"(a[3]), "r"(b[0]), "r"(b[1]));
}

__device__ __forceinline__ void ldsm4(uint32_t* r, uint32_t addr) {
    asm volatile(
        "ldmatrix.sync.aligned.m8n8.x4.shared.b16 {%0,%1,%2,%3}, [%4];"
        : "=r"(r[0]), "=r"(r[1]), "=r"(r[2]), "=r"(r[3]) : "r"(addr));
}

__device__ __forceinline__ void ldsm4t(uint32_t* r, uint32_t addr) {
    asm volatile(
        "ldmatrix.sync.aligned.m8n8.x4.trans.shared.b16 {%0,%1,%2,%3}, [%4];"
        : "=r"(r[0]), "=r"(r[1]), "=r"(r[2]), "=r"(r[3]) : "r"(addr));
}

__device__ __forceinline__ float ex2(float x) {
    float r;
    asm("ex2.approx.f32 %0, %1;" : "=f"(r) : "f"(x));
    return r;
}

__device__ __forceinline__ uint32_t ex2h2(uint32_t x) {
    uint32_t r;
    asm("ex2.approx.f16x2 %0, %1;" : "=r"(r) : "r"(x));
    return r;
}

__device__ __forceinline__ __half2 u2h(uint32_t x) {
    __half2 h;
    *(uint32_t*)&h = x;
    return h;
}

__device__ __forceinline__ uint32_t smem_u32(const void* p) {
    uint32_t a;
    asm("{ .reg .u64 tmp; cvta.to.shared.u64 tmp, %1; cvt.u32.u64 %0, tmp; }"
        : "=r"(a) : "l"(p));
    return a;
}

#define CP16(dst, src) \
    asm volatile("cp.async.cg.shared.global [%0], [%1], 16;" \
                 :: "r"(dst), "l"(src) : "memory")
#define CP_COMMIT() asm volatile("cp.async.commit_group;" ::: "memory")
#define CP_WAIT0()  asm volatile("cp.async.wait_group 0;" ::: "memory")

__device__ __forceinline__ uint32_t pack2h(float a, float b) {
    __half2 v = __floats2half2_rn(a, b);
    return *(uint32_t*)&v;
}

// ---------------------------------------------------------------------------
// Kernel 0: merged fp32 -> fp16 prepass (X + Wq + Wk + Wv in one launch).
// ---------------------------------------------------------------------------
#define NX4 (MROWS * H_ / 4)   // 2097152/... = 2097152? (8192*1024/4 = 2097152)
#define NW4 (H_ * H_ / 4)      // 262144

__global__ void prep_kernel(const float* __restrict__ x,
                            const float* __restrict__ w0,
                            const float* __restrict__ w1,
                            const float* __restrict__ w2)
{
    int i = blockIdx.x * blockDim.x + threadIdx.x;
    const float* src;
    uint32_t* dst;
    int idx;
    if (i < NX4) {
        src = x; dst = (uint32_t*)g_xh; idx = i;
    } else {
        int j = i - NX4;
        int z = j / NW4;
        idx = j - z * NW4;
        src = (z == 0) ? w0 : (z == 1) ? w1 : w2;
        dst = (uint32_t*)g_wh[z];
    }
    float4 v = ((const float4*)src)[idx];
    dst[idx * 2]     = pack2h(v.x, v.y);
    dst[idx * 2 + 1] = pack2h(v.z, v.w);
}

// ---------------------------------------------------------------------------
// Kernel 1: QKV projection, single-term fp16 HGEMM (fp32 accum).
// CTA 128x128, BK=64 (half the barriers), 8 warps (4m x 2n), warp tile 32x64.
// smem per buffer: X@0, W@18432 (each 128 x 72 halves = 18432 B); 2 buffers.
// ---------------------------------------------------------------------------
#define GSTR 72
#define GMAT_B 18432
#define GBUF_B 36864
#define QKV_SMEM (2 * GBUF_B)

__global__ __launch_bounds__(256, 2)
void qkv_kernel(const float* __restrict__ bq,
                const float* __restrict__ bk,
                const float* __restrict__ bv)
{
    extern __shared__ char smem[];
    const uint32_t sb = smem_u32(smem);
    const int tid  = threadIdx.x;
    const int lane = tid & 31;
    const int w    = tid >> 5;
    const int wm = (w >> 1) * 32;
    const int wn = (w & 1) * 64;
    const int g = lane >> 2;
    const int t = lane & 3;
    const int lr16 = lane & 15;
    const int lk8  = (lane >> 4) * 8;

    const int z  = blockIdx.z;
    const int n0 = blockIdx.x * 128;
    const int m0 = blockIdx.y * 128;
    const __half* __restrict__ Wh = g_wh[z];
    const float* __restrict__ bias = (z == 0) ? bq : (z == 1) ? bk : bv;

    auto issue = [&](int ck, int bsel) {
        const int k0 = ck * 64;
        const uint32_t bb = sb + bsel * GBUF_B;
        #pragma unroll
        for (int i = 0; i < 4; ++i) {
            const int idx = i * 256 + tid;
            const int r = idx >> 3, c = idx & 7;
            const uint32_t doff = (uint32_t)(r * GSTR + c * 8) * 2;
            CP16(bb + doff,          (const char*)&g_xh[(size_t)(m0 + r) * H_ + k0 + c * 8]);
            CP16(bb + GMAT_B + doff, (const char*)&Wh[(size_t)(n0 + r) * H_ + k0 + c * 8]);
        }
    };

    float acc[2][8][4] = {};

    issue(0, 0);
    CP_COMMIT();

    const int NCH = H_ / 64;  // 16
    for (int ck = 0; ck < NCH; ++ck) {
        const int bsel = ck & 1;
        CP_WAIT0();
        __syncthreads();
        if (ck + 1 < NCH) issue(ck + 1, bsel ^ 1);
        CP_COMMIT();

        const uint32_t bb = sb + bsel * GBUF_B;
        #pragma unroll
        for (int ks = 0; ks < 4; ++ks) {
            const uint32_t kc = ks * 16 + lk8;
            uint32_t ah[2][4];
            #pragma unroll
            for (int mt = 0; mt < 2; ++mt) {
                const uint32_t aoff = (uint32_t)((wm + mt * 16 + lr16) * GSTR + kc) * 2;
                ldsm4(ah[mt], bb + aoff);
            }
            #pragma unroll
            for (int np = 0; np < 4; ++np) {
                const uint32_t boff = (uint32_t)((wn + np * 16 + lr16) * GSTR + kc) * 2;
                uint32_t bh4[4];
                ldsm4(bh4, bb + GMAT_B + boff);
                uint32_t be[2] = {bh4[0], bh4[2]};
                uint32_t bo[2] = {bh4[1], bh4[3]};
                #pragma unroll
                for (int mt = 0; mt < 2; ++mt) {
                    mma_f16(acc[mt][2 * np],     ah[mt], be);
                    mma_f16(acc[mt][2 * np + 1], ah[mt], bo);
                }
            }
        }
    }

    // epilogue: bias (+QSCALE for Q) + vectorized head-major store
    const int bidx  = m0 >> 11;
    const int sbase = (m0 & (S_ - 1));
    __half* dst = (z == 0) ? g_qh : (z == 1) ? g_kh : g_vh;
    const float sc = (z == 0) ? QSCALE : 1.0f;
    #pragma unroll
    for (int mt = 0; mt < 2; ++mt) {
        #pragma unroll
        for (int nt = 0; nt < 8; ++nt) {
            const int nloc = wn + nt * 8 + 2 * t;
            const int d    = nloc & 63;
            const int hh   = (n0 + nloc) >> 6;
            const int bh_i = bidx * NH_ + hh;
            const float2 bi = *(const float2*)&bias[n0 + nloc];
            const int s0 = sbase + wm + mt * 16 + g;
            const float v0 = (acc[mt][nt][0] + bi.x) * sc;
            const float v1 = (acc[mt][nt][1] + bi.y) * sc;
            const float v2 = (acc[mt][nt][2] + bi.x) * sc;
            const float v3 = (acc[mt][nt][3] + bi.y) * sc;
            *(uint32_t*)&dst[((size_t)bh_i * S_ + s0) * HD_ + d]     = pack2h(v0, v1);
            *(uint32_t*)&dst[((size_t)bh_i * S_ + s0 + 8) * HD_ + d] = pack2h(v2, v3);
        }
    }
}

// ---------------------------------------------------------------------------
// Kernel 2: causal flash attention, base-2 softmax (Q pre-scaled).
// KV staged in 128-row buffers (one barrier per 128 kv rows), processed as
// two 64-wide softmax halves. exp fused with P packing via ex2.approx.f16x2.
// smem: Q@0 (18432) | KVbuf[2]@18432, each 36864 (K 18432 + V 18432) |
//   amask[2][128]@92160 (1024).  Total 93184.
// ---------------------------------------------------------------------------
#define QSTR 72
#define ATT_Q 0u
#define ATT_KV0 18432u
#define ATT_KVSZ 36864u
#define ATT_V 18432u
#define ATT_AM 92160u
#define ATT_SMEM 93184

__global__ __launch_bounds__(256, 2)
void attn_kernel(const float* __restrict__ amask, float* __restrict__ out)
{
    extern __shared__ char smem[];
    const uint32_t sb = smem_u32(smem);
    const int qt = 15 - (int)blockIdx.x;  // heavy tiles first
    const int bh = blockIdx.y;
    const int b  = bh >> 4;
    const int h  = bh & 15;
    const int q0 = qt * 128;
    const int tid  = threadIdx.x;
    const int lane = tid & 31;
    const int w    = tid >> 5;
    const int g = lane >> 2;
    const int t = lane & 3;
    const int lr16 = lane & 15;
    const int lk8  = (lane >> 4) * 8;

    float* sAm = (float*)(smem + ATT_AM);

    // Q tile: 128 x 64 fp16 (pre-scaled by QSCALE)
    #pragma unroll
    for (int i = 0; i < 2; ++i) {
        const int idx = i * 256 + tid;
        const int r = idx >> 2, c = idx & 3;
        *(uint4*)(smem + ATT_Q + (r * QSTR + c * 16) * 2) =
            *(const uint4*)&g_qh[((size_t)bh * S_ + q0 + r) * HD_ + c * 16];
        *(uint4*)(smem + ATT_Q + (r * QSTR + c * 16 + 8) * 2) =
            *(const uint4*)&g_qh[((size_t)bh * S_ + q0 + r) * HD_ + c * 16 + 8];
    }

    // stage a full 128-row K/V buffer
    auto issue_kv = [&](int kt, int bsel) {
        const int j0 = kt * 128;
        const uint32_t kb = sb + ATT_KV0 + bsel * ATT_KVSZ;
        #pragma unroll
        for (int i = 0; i < 4; ++i) {
            const int idx = i * 256 + tid;
            const int r = idx >> 3, c = idx & 7;
            const uint32_t doff = (uint32_t)(r * QSTR + c * 8) * 2;
            CP16(kb + doff,
                 (const char*)&g_kh[((size_t)bh * S_ + j0 + r) * HD_ + c * 8]);
            CP16(kb + ATT_V + doff,
                 (const char*)&g_vh[((size_t)bh * S_ + j0 + r) * HD_ + c * 8]);
        }
    };

    auto stage_am = [&](int kt, int bsel) {
        if (tid < 32) {
            float4 a = *(const float4*)&amask[(size_t)b * S_ + kt * 128 + tid * 4];
            a.x *= QSCALE; a.y *= QSCALE; a.z *= QSCALE; a.w *= QSCALE;
            *(float4*)&sAm[bsel * 128 + tid * 4] = a;
        }
    };

    issue_kv(0, 0);
    CP_COMMIT();
    stage_am(0, 0);

    // hoist Q fragments (kt-invariant) — safe after this sync
    __syncthreads();
    uint32_t q4[4][4];
    #pragma unroll
    for (int ks = 0; ks < 4; ++ks) {
        const uint32_t kc = ks * 16 + lk8;
        const uint32_t qoff = (uint32_t)((w * 16 + lr16) * QSTR + kc) * 2;
        ldsm4(q4[ks], sb + ATT_Q + qoff);
    }

    float o[8][4] = {};
    float m0r = -1e30f, m1r = -1e30f;
    float l0r = 0.f, l1r = 0.f;
    const int i0 = q0 + w * 16 + g;
    const int i1 = i0 + 8;
    const int imax = q0 + w * 16 + 15;   // highest q row owned by this warp

    const int nkv = qt + 1;   // number of 128-row kv buffers
    for (int kt = 0; kt < nkv; ++kt) {
        const int bsel = kt & 1;
        CP_WAIT0();
        __syncthreads();
        if (kt + 1 < nkv) {
            issue_kv(kt + 1, bsel ^ 1);
            stage_am(kt + 1, bsel ^ 1);
        }
        CP_COMMIT();

        const uint32_t kb = sb + ATT_KV0 + bsel * ATT_KVSZ;

        #pragma unroll
        for (int half = 0; half < 2; ++half) {
            const int j0 = kt * 128 + half * 64;
            if (j0 > imax) continue;   // fully masked for this warp
            const int rbase = half * 64;
            const float* am = sAm + bsel * 128 + half * 64;

            // ---- S = Q @ K^T ----
            float s[8][4] = {};
            #pragma unroll
            for (int ks = 0; ks < 4; ++ks) {
                const uint32_t kc = ks * 16 + lk8;
                #pragma unroll
                for (int p = 0; p < 4; ++p) {
                    const uint32_t koff =
                        (uint32_t)((rbase + p * 16 + lr16) * QSTR + kc) * 2;
                    uint32_t kh4[4];
                    ldsm4(kh4, kb + koff);
                    uint32_t be[2] = {kh4[0], kh4[2]};
                    uint32_t bo[2] = {kh4[1], kh4[3]};
                    mma_f16(s[2 * p],     q4[ks], be);
                    mma_f16(s[2 * p + 1], q4[ks], bo);
                }
            }

            // ---- mask + online softmax (base-2) ----
            float rm0 = -1e30f, rm1 = -1e30f;
            if (j0 + 63 > imax - 15) {  // diagonal: this warp needs masking
                #pragma unroll
                for (int ntj = 0; ntj < 8; ++ntj) {
                    const float2 amv = *(const float2*)&am[ntj * 8 + 2 * t];
                    const int j = j0 + ntj * 8 + 2 * t;
                    float v0 = s[ntj][0] + amv.x;
                    float v1 = s[ntj][1] + amv.y;
                    float v2 = s[ntj][2] + amv.x;
                    float v3 = s[ntj][3] + amv.y;
                    if (j     > i0) v0 = -1e30f;
                    if (j + 1 > i0) v1 = -1e30f;
                    if (j     > i1) v2 = -1e30f;
                    if (j + 1 > i1) v3 = -1e30f;
                    s[ntj][0] = v0; s[ntj][1] = v1; s[ntj][2] = v2; s[ntj][3] = v3;
                    rm0 = fmaxf(rm0, fmaxf(v0, v1));
                    rm1 = fmaxf(rm1, fmaxf(v2, v3));
                }
            } else {
                #pragma unroll
                for (int ntj = 0; ntj < 8; ++ntj) {
                    const float2 amv = *(const float2*)&am[ntj * 8 + 2 * t];
                    float v0 = s[ntj][0] + amv.x;
                    float v1 = s[ntj][1] + amv.y;
                    float v2 = s[ntj][2] + amv.x;
                    float v3 = s[ntj][3] + amv.y;
                    s[ntj][0] = v0; s[ntj][1] = v1; s[ntj][2] = v2; s[ntj][3] = v3;
                    rm0 = fmaxf(rm0, fmaxf(v0, v1));
                    rm1 = fmaxf(rm1, fmaxf(v2, v3));
                }
            }
            rm0 = fmaxf(rm0, __shfl_xor_sync(0xffffffffu, rm0, 1));
            rm0 = fmaxf(rm0, __shfl_xor_sync(0xffffffffu, rm0, 2));
            rm1 = fmaxf(rm1, __shfl_xor_sync(0xffffffffu, rm1, 1));
            rm1 = fmaxf(rm1, __shfl_xor_sync(0xffffffffu, rm1, 2));

            const float mn0 = fmaxf(m0r, rm0);
            const float mn1 = fmaxf(m1r, rm1);
            const float c0 = ex2(m0r - mn0);
            const float c1 = ex2(m1r - mn1);
            m0r = mn0; m1r = mn1;

            // ---- fused exp + P pack ----
            uint32_t pa[4][4];
            #pragma unroll
            for (int ks = 0; ks < 4; ++ks) {
                pa[ks][0] = ex2h2(pack2h(s[2 * ks][0]     - mn0, s[2 * ks][1]     - mn0));
                pa[ks][1] = ex2h2(pack2h(s[2 * ks][2]     - mn1, s[2 * ks][3]     - mn1));
                pa[ks][2] = ex2h2(pack2h(s[2 * ks + 1][0] - mn0, s[2 * ks + 1][1] - mn0));
                pa[ks][3] = ex2h2(pack2h(s[2 * ks + 1][2] - mn1, s[2 * ks + 1][3] - mn1));
            }

            // ---- row sums via HADD2 trees ----
            __half2 a0 = __hadd2(__hadd2(u2h(pa[0][0]), u2h(pa[1][0])),
                                 __hadd2(u2h(pa[2][0]), u2h(pa[3][0])));
            __half2 b0 = __hadd2(__hadd2(u2h(pa[0][2]), u2h(pa[1][2])),
                                 __hadd2(u2h(pa[2][2]), u2h(pa[3][2])));
            float2 f0 = __half22float2(__hadd2(a0, b0));
            float rs0 = f0.x + f0.y;

            __half2 a1 = __hadd2(__hadd2(u2h(pa[0][1]), u2h(pa[1][1])),
                                 __hadd2(u2h(pa[2][1]), u2h(pa[3][1])));
            __half2 b1 = __hadd2(__hadd2(u2h(pa[0][3]), u2h(pa[1][3])),
                                 __hadd2(u2h(pa[2][3]), u2h(pa[3][3])));
            float2 f1 = __half22float2(__hadd2(a1, b1));
            float rs1 = f1.x + f1.y;

            rs0 += __shfl_xor_sync(0xffffffffu, rs0, 1);
            rs0 += __shfl_xor_sync(0xffffffffu, rs0, 2);
            rs1 += __shfl_xor_sync(0xffffffffu, rs1, 1);
            rs1 += __shfl_xor_sync(0xffffffffu, rs1, 2);
            l0r = l0r * c0 + rs0;
            l1r = l1r * c1 + rs1;
            #pragma unroll
            for (int ntd = 0; ntd < 8; ++ntd) {
                o[ntd][0] *= c0; o[ntd][1] *= c0;
                o[ntd][2] *= c1; o[ntd][3] *= c1;
            }

            // ---- O += P @ V (B-fragments via ldmatrix.trans) ----
            #pragma unroll
            for (int ks = 0; ks < 4; ++ks) {
                #pragma unroll
                for (int p = 0; p < 4; ++p) {
                    const uint32_t voff =
                        (uint32_t)((rbase + ks * 16 + lr16) * QSTR + p * 16 + lk8) * 2;
                    uint32_t v4[4];
                    ldsm4t(v4, kb + ATT_V + voff);
                    uint32_t b0v[2] = {v4[0], v4[1]};
                    uint32_t b1v[2] = {v4[2], v4[3]};
                    mma_f16(o[2 * p],     pa[ks], b0v);
                    mma_f16(o[2 * p + 1], pa[ks], b1v);
                }
            }
        }
    }

    // epilogue
    const float inv0 = 1.0f / l0r;
    const float inv1 = 1.0f / l1r;
    #pragma unroll
    for (int ntd = 0; ntd < 8; ++ntd) {
        const int d = h * HD_ + ntd * 8 + 2 * t;
        float2 r0 = make_float2(o[ntd][0] * inv0, o[ntd][1] * inv0);
        float2 r1 = make_float2(o[ntd][2] * inv1, o[ntd][3] * inv1);
        *(float2*)&out[((size_t)b * S_ + i0) * H_ + d] = r0;
        *(float2*)&out[((size_t)b * S_ + i1) * H_ + d] = r1;
    }
}

// ---------------------------------------------------------------------------
// Launch
// ---------------------------------------------------------------------------
extern "C" void kernel_launch(void* const* d_in, const int* in_sizes, int n_in,
                              void* d_out, int out_size)
{
    const float* hidden = (const float*)d_in[0];
    const float* amask  = (const float*)d_in[1];
    const float* Wq = (const float*)d_in[2];
    const float* bq = (const float*)d_in[3];
    const float* Wk = (const float*)d_in[4];
    const float* bk = (const float*)d_in[5];
    const float* Wv = (const float*)d_in[6];
    const float* bv = (const float*)d_in[7];
    float* out = (float*)d_out;

    // merged prepass (1 launch)
    const int ntot = NX4 + 3 * NW4;
    prep_kernel<<<(ntot + 255) / 256, 256>>>(hidden, Wq, Wk, Wv);

    // QKV projection: grid (8 n-tiles, 64 m-tiles, 3)
    cudaFuncSetAttribute(qkv_kernel,
                         cudaFuncAttributeMaxDynamicSharedMemorySize, QKV_SMEM);
    dim3 ggrid(H_ / 128, MROWS / 128, 3);
    qkv_kernel<<<ggrid, 256, QKV_SMEM>>>(bq, bk, bv);

    // attention: grid (16 q-tiles, 64 bh)
    cudaFuncSetAttribute(attn_kernel,
                         cudaFuncAttributeMaxDynamicSharedMemorySize, ATT_SMEM);
    dim3 agrid(S_ / 128, B_ * NH_);
    attn_kernel<<<agrid, 256, ATT_SMEM>>>(amask, out);
}

// round 14
// speedup vs baseline: 7.8513x; 1.0251x over previous
#include <cuda_runtime.h>
#include <cuda_fp16.h>
#include <cstdint>

// Problem constants
#define B_   4
#define S_   2048
#define H_   1024
#define NH_  16
#define HD_  64
#define MROWS (B_ * S_)        // 8192

// softmax folded scale: 1/8 * log2(e)
#define QSCALE 0.18033688011112042f

// ---------------------------------------------------------------------------
// Scratch. All operands single fp16, fp32 accumulation. Q pre-scaled.
// ---------------------------------------------------------------------------
__device__ __half g_xh[(size_t)MROWS * H_];
__device__ __half g_wh[3][(size_t)H_ * H_];
__device__ __half g_qh[(size_t)B_ * NH_ * S_ * HD_];
__device__ __half g_kh[(size_t)B_ * NH_ * S_ * HD_];
__device__ __half g_vh[(size_t)B_ * NH_ * S_ * HD_];

// ---------------------------------------------------------------------------
// helpers
// ---------------------------------------------------------------------------
__device__ __forceinline__ void mma_f16(float* d, const uint32_t* a, const uint32_t* b) {
    asm volatile(
        "mma.sync.aligned.m16n8k16.row.col.f32.f16.f16.f32 "
        "{%0,%1,%2,%3},{%4,%5,%6,%7},{%8,%9},{%0,%1,%2,%3};"
        : "+f"(d[0]), "+f"(d[1]), "+f"(d[2]), "+f"(d[3])
        : "r"(a[0]), "r"(a[1]), "r"(a[2]), "r"(a[3]), "r"(b[0]), "r"(b[1]));
}

__device__ __forceinline__ void ldsm4(uint32_t* r, uint32_t addr) {
    asm volatile(
        "ldmatrix.sync.aligned.m8n8.x4.shared.b16 {%0,%1,%2,%3}, [%4];"
        : "=r"(r[0]), "=r"(r[1]), "=r"(r[2]), "=r"(r[3]) : "r"(addr));
}

__device__ __forceinline__ void ldsm4t(uint32_t* r, uint32_t addr) {
    asm volatile(
        "ldmatrix.sync.aligned.m8n8.x4.trans.shared.b16 {%0,%1,%2,%3}, [%4];"
        : "=r"(r[0]), "=r"(r[1]), "=r"(r[2]), "=r"(r[3]) : "r"(addr));
}

__device__ __forceinline__ float ex2(float x) {
    float r;
    asm("ex2.approx.f32 %0, %1;" : "=f"(r) : "f"(x));
    return r;
}

__device__ __forceinline__ uint32_t ex2h2(uint32_t x) {
    uint32_t r;
    asm("ex2.approx.f16x2 %0, %1;" : "=r"(r) : "r"(x));
    return r;
}

__device__ __forceinline__ __half2 u2h(uint32_t x) {
    __half2 h;
    *(uint32_t*)&h = x;
    return h;
}

__device__ __forceinline__ uint32_t smem_u32(const void* p) {
    uint32_t a;
    asm("{ .reg .u64 tmp; cvta.to.shared.u64 tmp, %1; cvt.u32.u64 %0, tmp; }"
        : "=r"(a) : "l"(p));
    return a;
}

#define CP16(dst, src) \
    asm volatile("cp.async.cg.shared.global [%0], [%1], 16;" \
                 :: "r"(dst), "l"(src) : "memory")
#define CP_COMMIT() asm volatile("cp.async.commit_group;" ::: "memory")
#define CP_WAIT1()  asm volatile("cp.async.wait_group 1;" ::: "memory")

__device__ __forceinline__ uint32_t pack2h(float a, float b) {
    __half2 v = __floats2half2_rn(a, b);
    return *(uint32_t*)&v;
}

// ---------------------------------------------------------------------------
// Kernel 0: merged fp32 -> fp16 prepass (X + Wq + Wk + Wv in one launch).
// ---------------------------------------------------------------------------
#define NX4 (MROWS * H_ / 4)
#define NW4 (H_ * H_ / 4)

__global__ void prep_kernel(const float* __restrict__ x,
                            const float* __restrict__ w0,
                            const float* __restrict__ w1,
                            const float* __restrict__ w2)
{
    int i = blockIdx.x * blockDim.x + threadIdx.x;
    const float* src;
    uint32_t* dst;
    int idx;
    if (i < NX4) {
        src = x; dst = (uint32_t*)g_xh; idx = i;
    } else {
        int j = i - NX4;
        int z = j / NW4;
        idx = j - z * NW4;
        src = (z == 0) ? w0 : (z == 1) ? w1 : w2;
        dst = (uint32_t*)g_wh[z];
    }
    float4 v = ((const float4*)src)[idx];
    dst[idx * 2]     = pack2h(v.x, v.y);
    dst[idx * 2 + 1] = pack2h(v.z, v.w);
}

// ---------------------------------------------------------------------------
// Kernel 1: QKV projection, single-term fp16 HGEMM (fp32 accum).
// CTA 128x128, BK=64, 8 warps (4m x 2n), warp tile 32x64.
// 3-stage cp.async ring, wait_group 1 (2 loads in flight).
// Buffer: X@0, W@18432 (each 128 x 72 halves); 3 buffers of 36864 B.
// ---------------------------------------------------------------------------
#define GSTR 72
#define GMAT_B 18432
#define GBUF_B 36864
#define QKV_SMEM (3 * GBUF_B)

__global__ __launch_bounds__(256, 2)
void qkv_kernel(const float* __restrict__ bq,
                const float* __restrict__ bk,
                const float* __restrict__ bv)
{
    extern __shared__ char smem[];
    const uint32_t sb = smem_u32(smem);
    const int tid  = threadIdx.x;
    const int lane = tid & 31;
    const int w    = tid >> 5;
    const int wm = (w >> 1) * 32;
    const int wn = (w & 1) * 64;
    const int g = lane >> 2;
    const int t = lane & 3;
    const int lr16 = lane & 15;
    const int lk8  = (lane >> 4) * 8;

    const int z  = blockIdx.z;
    const int n0 = blockIdx.x * 128;
    const int m0 = blockIdx.y * 128;
    const __half* __restrict__ Wh = g_wh[z];
    const float* __restrict__ bias = (z == 0) ? bq : (z == 1) ? bk : bv;

    auto issue = [&](int ck) {
        const int k0 = ck * 64;
        const uint32_t bb = sb + (uint32_t)(ck % 3) * GBUF_B;
        #pragma unroll
        for (int i = 0; i < 4; ++i) {
            const int idx = i * 256 + tid;
            const int r = idx >> 3, c = idx & 7;
            const uint32_t doff = (uint32_t)(r * GSTR + c * 8) * 2;
            CP16(bb + doff,          (const char*)&g_xh[(size_t)(m0 + r) * H_ + k0 + c * 8]);
            CP16(bb + GMAT_B + doff, (const char*)&Wh[(size_t)(n0 + r) * H_ + k0 + c * 8]);
        }
    };

    float acc[2][8][4] = {};

    issue(0); CP_COMMIT();
    issue(1); CP_COMMIT();

    const int NCH = H_ / 64;  // 16
    for (int ck = 0; ck < NCH; ++ck) {
        CP_WAIT1();
        __syncthreads();
        if (ck + 2 < NCH) issue(ck + 2);
        CP_COMMIT();

        const uint32_t bb = sb + (uint32_t)(ck % 3) * GBUF_B;
        #pragma unroll
        for (int ks = 0; ks < 4; ++ks) {
            const uint32_t kc = ks * 16 + lk8;
            uint32_t ah[2][4];
            #pragma unroll
            for (int mt = 0; mt < 2; ++mt) {
                const uint32_t aoff = (uint32_t)((wm + mt * 16 + lr16) * GSTR + kc) * 2;
                ldsm4(ah[mt], bb + aoff);
            }
            #pragma unroll
            for (int np = 0; np < 4; ++np) {
                const uint32_t boff = (uint32_t)((wn + np * 16 + lr16) * GSTR + kc) * 2;
                uint32_t bh4[4];
                ldsm4(bh4, bb + GMAT_B + boff);
                uint32_t be[2] = {bh4[0], bh4[2]};
                uint32_t bo[2] = {bh4[1], bh4[3]};
                #pragma unroll
                for (int mt = 0; mt < 2; ++mt) {
                    mma_f16(acc[mt][2 * np],     ah[mt], be);
                    mma_f16(acc[mt][2 * np + 1], ah[mt], bo);
                }
            }
        }
    }

    // epilogue: bias (+QSCALE for Q) + vectorized head-major store
    const int bidx  = m0 >> 11;
    const int sbase = (m0 & (S_ - 1));
    __half* dst = (z == 0) ? g_qh : (z == 1) ? g_kh : g_vh;
    const float sc = (z == 0) ? QSCALE : 1.0f;
    #pragma unroll
    for (int mt = 0; mt < 2; ++mt) {
        #pragma unroll
        for (int nt = 0; nt < 8; ++nt) {
            const int nloc = wn + nt * 8 + 2 * t;
            const int d    = nloc & 63;
            const int hh   = (n0 + nloc) >> 6;
            const int bh_i = bidx * NH_ + hh;
            const float2 bi = *(const float2*)&bias[n0 + nloc];
            const int s0 = sbase + wm + mt * 16 + g;
            const float v0 = (acc[mt][nt][0] + bi.x) * sc;
            const float v1 = (acc[mt][nt][1] + bi.y) * sc;
            const float v2 = (acc[mt][nt][2] + bi.x) * sc;
            const float v3 = (acc[mt][nt][3] + bi.y) * sc;
            *(uint32_t*)&dst[((size_t)bh_i * S_ + s0) * HD_ + d]     = pack2h(v0, v1);
            *(uint32_t*)&dst[((size_t)bh_i * S_ + s0 + 8) * HD_ + d] = pack2h(v2, v3);
        }
    }
}

// ---------------------------------------------------------------------------
// Kernel 2: causal flash attention, base-2 softmax (Q pre-scaled).
// 3-stage 128-row KV ring (wait_group 1); Q staged in buf2 then reused.
// smem: KVbuf[3] @0/36864/73728 (each K 18432 + V 18432) |
//   amask[3][128] @110592 (1536). Total 112128.
// ---------------------------------------------------------------------------
#define QSTR 72
#define ATT_KVSZ 36864u
#define ATT_V 18432u
#define ATT_AM 110592u
#define ATT_SMEM 112128

__global__ __launch_bounds__(256, 2)
void attn_kernel(const float* __restrict__ amask, float* __restrict__ out)
{
    extern __shared__ char smem[];
    const uint32_t sb = smem_u32(smem);
    const int qt = 15 - (int)blockIdx.x;  // heavy tiles first
    const int bh = blockIdx.y;
    const int b  = bh >> 4;
    const int h  = bh & 15;
    const int q0 = qt * 128;
    const int tid  = threadIdx.x;
    const int lane = tid & 31;
    const int w    = tid >> 5;
    const int g = lane >> 2;
    const int t = lane & 3;
    const int lr16 = lane & 15;
    const int lk8  = (lane >> 4) * 8;

    float* sAm = (float*)(smem + ATT_AM);
    const uint32_t ATT_Q = 2u * ATT_KVSZ;   // stage Q in buf2 region

    // Q tile: 128 x 64 fp16 (pre-scaled) into buf2
    #pragma unroll
    for (int i = 0; i < 2; ++i) {
        const int idx = i * 256 + tid;
        const int r = idx >> 2, c = idx & 3;
        *(uint4*)(smem + ATT_Q + (r * QSTR + c * 16) * 2) =
            *(const uint4*)&g_qh[((size_t)bh * S_ + q0 + r) * HD_ + c * 16];
        *(uint4*)(smem + ATT_Q + (r * QSTR + c * 16 + 8) * 2) =
            *(const uint4*)&g_qh[((size_t)bh * S_ + q0 + r) * HD_ + c * 16 + 8];
    }

    auto issue_kv = [&](int kt) {
        const int j0 = kt * 128;
        const uint32_t kb = sb + (uint32_t)(kt % 3) * ATT_KVSZ;
        #pragma unroll
        for (int i = 0; i < 4; ++i) {
            const int idx = i * 256 + tid;
            const int r = idx >> 3, c = idx & 7;
            const uint32_t doff = (uint32_t)(r * QSTR + c * 8) * 2;
            CP16(kb + doff,
                 (const char*)&g_kh[((size_t)bh * S_ + j0 + r) * HD_ + c * 8]);
            CP16(kb + ATT_V + doff,
                 (const char*)&g_vh[((size_t)bh * S_ + j0 + r) * HD_ + c * 8]);
        }
    };

    auto stage_am = [&](int kt) {
        if (tid < 32) {
            float4 a = *(const float4*)&amask[(size_t)b * S_ + kt * 128 + tid * 4];
            a.x *= QSCALE; a.y *= QSCALE; a.z *= QSCALE; a.w *= QSCALE;
            *(float4*)&sAm[(kt % 3) * 128 + tid * 4] = a;
        }
    };

    const int nkv = qt + 1;   // number of 128-row kv buffers

    // hoist Q fragments; Q region (buf2) is first overwritten by issue(2),
    // which happens after the iteration-0 barrier (all warps hoisted by then).
    __syncthreads();
    uint32_t q4[4][4];
    #pragma unroll
    for (int ks = 0; ks < 4; ++ks) {
        const uint32_t kc = ks * 16 + lk8;
        const uint32_t qoff = (uint32_t)((w * 16 + lr16) * QSTR + kc) * 2;
        ldsm4(q4[ks], sb + ATT_Q + qoff);
    }

    issue_kv(0); CP_COMMIT();
    stage_am(0);
    if (nkv > 1) { issue_kv(1); stage_am(1); }
    CP_COMMIT();

    float o[8][4] = {};
    float m0r = -1e30f, m1r = -1e30f;
    float l0r = 0.f, l1r = 0.f;
    const int i0 = q0 + w * 16 + g;
    const int i1 = i0 + 8;
    const int imax = q0 + w * 16 + 15;

    for (int kt = 0; kt < nkv; ++kt) {
        CP_WAIT1();
        __syncthreads();
        if (kt + 2 < nkv) { issue_kv(kt + 2); stage_am(kt + 2); }
        CP_COMMIT();

        const uint32_t kb = sb + (uint32_t)(kt % 3) * ATT_KVSZ;

        #pragma unroll
        for (int half = 0; half < 2; ++half) {
            const int j0 = kt * 128 + half * 64;
            if (j0 > imax) continue;   // fully masked for this warp
            const int rbase = half * 64;
            const float* am = sAm + (kt % 3) * 128 + half * 64;

            // ---- S = Q @ K^T ----
            float s[8][4] = {};
            #pragma unroll
            for (int ks = 0; ks < 4; ++ks) {
                const uint32_t kc = ks * 16 + lk8;
                #pragma unroll
                for (int p = 0; p < 4; ++p) {
                    const uint32_t koff =
                        (uint32_t)((rbase + p * 16 + lr16) * QSTR + kc) * 2;
                    uint32_t kh4[4];
                    ldsm4(kh4, kb + koff);
                    uint32_t be[2] = {kh4[0], kh4[2]};
                    uint32_t bo[2] = {kh4[1], kh4[3]};
                    mma_f16(s[2 * p],     q4[ks], be);
                    mma_f16(s[2 * p + 1], q4[ks], bo);
                }
            }

            // ---- mask + online softmax (base-2) ----
            float rm0 = -1e30f, rm1 = -1e30f;
            if (j0 + 63 > imax - 15) {
                #pragma unroll
                for (int ntj = 0; ntj < 8; ++ntj) {
                    const float2 amv = *(const float2*)&am[ntj * 8 + 2 * t];
                    const int j = j0 + ntj * 8 + 2 * t;
                    float v0 = s[ntj][0] + amv.x;
                    float v1 = s[ntj][1] + amv.y;
                    float v2 = s[ntj][2] + amv.x;
                    float v3 = s[ntj][3] + amv.y;
                    if (j     > i0) v0 = -1e30f;
                    if (j + 1 > i0) v1 = -1e30f;
                    if (j     > i1) v2 = -1e30f;
                    if (j + 1 > i1) v3 = -1e30f;
                    s[ntj][0] = v0; s[ntj][1] = v1; s[ntj][2] = v2; s[ntj][3] = v3;
                    rm0 = fmaxf(rm0, fmaxf(v0, v1));
                    rm1 = fmaxf(rm1, fmaxf(v2, v3));
                }
            } else {
                #pragma unroll
                for (int ntj = 0; ntj < 8; ++ntj) {
                    const float2 amv = *(const float2*)&am[ntj * 8 + 2 * t];
                    float v0 = s[ntj][0] + amv.x;
                    float v1 = s[ntj][1] + amv.y;
                    float v2 = s[ntj][2] + amv.x;
                    float v3 = s[ntj][3] + amv.y;
                    s[ntj][0] = v0; s[ntj][1] = v1; s[ntj][2] = v2; s[ntj][3] = v3;
                    rm0 = fmaxf(rm0, fmaxf(v0, v1));
                    rm1 = fmaxf(rm1, fmaxf(v2, v3));
                }
            }
            rm0 = fmaxf(rm0, __shfl_xor_sync(0xffffffffu, rm0, 1));
            rm0 = fmaxf(rm0, __shfl_xor_sync(0xffffffffu, rm0, 2));
            rm1 = fmaxf(rm1, __shfl_xor_sync(0xffffffffu, rm1, 1));
            rm1 = fmaxf(rm1, __shfl_xor_sync(0xffffffffu, rm1, 2));

            const float mn0 = fmaxf(m0r, rm0);
            const float mn1 = fmaxf(m1r, rm1);
            const float c0 = ex2(m0r - mn0);
            const float c1 = ex2(m1r - mn1);
            m0r = mn0; m1r = mn1;

            // ---- fused exp + P pack ----
            uint32_t pa[4][4];
            #pragma unroll
            for (int ks = 0; ks < 4; ++ks) {
                pa[ks][0] = ex2h2(pack2h(s[2 * ks][0]     - mn0, s[2 * ks][1]     - mn0));
                pa[ks][1] = ex2h2(pack2h(s[2 * ks][2]     - mn1, s[2 * ks][3]     - mn1));
                pa[ks][2] = ex2h2(pack2h(s[2 * ks + 1][0] - mn0, s[2 * ks + 1][1] - mn0));
                pa[ks][3] = ex2h2(pack2h(s[2 * ks + 1][2] - mn1, s[2 * ks + 1][3] - mn1));
            }

            // ---- row sums via HADD2 trees ----
            __half2 a0 = __hadd2(__hadd2(u2h(pa[0][0]), u2h(pa[1][0])),
                                 __hadd2(u2h(pa[2][0]), u2h(pa[3][0])));
            __half2 b0 = __hadd2(__hadd2(u2h(pa[0][2]), u2h(pa[1][2])),
                                 __hadd2(u2h(pa[2][2]), u2h(pa[3][2])));
            float2 f0 = __half22float2(__hadd2(a0, b0));
            float rs0 = f0.x + f0.y;

            __half2 a1 = __hadd2(__hadd2(u2h(pa[0][1]), u2h(pa[1][1])),
                                 __hadd2(u2h(pa[2][1]), u2h(pa[3][1])));
            __half2 b1 = __hadd2(__hadd2(u2h(pa[0][3]), u2h(pa[1][3])),
                                 __hadd2(u2h(pa[2][3]), u2h(pa[3][3])));
            float2 f1 = __half22float2(__hadd2(a1, b1));
            float rs1 = f1.x + f1.y;

            rs0 += __shfl_xor_sync(0xffffffffu, rs0, 1);
            rs0 += __shfl_xor_sync(0xffffffffu, rs0, 2);
            rs1 += __shfl_xor_sync(0xffffffffu, rs1, 1);
            rs1 += __shfl_xor_sync(0xffffffffu, rs1, 2);
            l0r = l0r * c0 + rs0;
            l1r = l1r * c1 + rs1;
            #pragma unroll
            for (int ntd = 0; ntd < 8; ++ntd) {
                o[ntd][0] *= c0; o[ntd][1] *= c0;
                o[ntd][2] *= c1; o[ntd][3] *= c1;
            }

            // ---- O += P @ V (B-fragments via ldmatrix.trans) ----
            #pragma unroll
            for (int ks = 0; ks < 4; ++ks) {
                #pragma unroll
                for (int p = 0; p < 4; ++p) {
                    const uint32_t voff =
                        (uint32_t)((rbase + ks * 16 + lr16) * QSTR + p * 16 + lk8) * 2;
                    uint32_t v4[4];
                    ldsm4t(v4, kb + ATT_V + voff);
                    uint32_t b0v[2] = {v4[0], v4[1]};
                    uint32_t b1v[2] = {v4[2], v4[3]};
                    mma_f16(o[2 * p],     pa[ks], b0v);
                    mma_f16(o[2 * p + 1], pa[ks], b1v);
                }
            }
        }
    }

    // epilogue
    const float inv0 = 1.0f / l0r;
    const float inv1 = 1.0f / l1r;
    #pragma unroll
    for (int ntd = 0; ntd < 8; ++ntd) {
        const int d = h * HD_ + ntd * 8 + 2 * t;
        float2 r0 = make_float2(o[ntd][0] * inv0, o[ntd][1] * inv0);
        float2 r1 = make_float2(o[ntd][2] * inv1, o[ntd][3] * inv1);
        *(float2*)&out[((size_t)b * S_ + i0) * H_ + d] = r0;
        *(float2*)&out[((size_t)b * S_ + i1) * H_ + d] = r1;
    }
}

// ---------------------------------------------------------------------------
// Launch
// ---------------------------------------------------------------------------
extern "C" void kernel_launch(void* const* d_in, const int* in_sizes, int n_in,
                              void* d_out, int out_size)
{
    const float* hidden = (const float*)d_in[0];
    const float* amask  = (const float*)d_in[1];
    const float* Wq = (const float*)d_in[2];
    const float* bq = (const float*)d_in[3];
    const float* Wk = (const float*)d_in[4];
    const float* bk = (const float*)d_in[5];
    const float* Wv = (const float*)d_in[6];
    const float* bv = (const float*)d_in[7];
    float* out = (float*)d_out;

    // merged prepass (1 launch)
    const int ntot = NX4 + 3 * NW4;
    prep_kernel<<<(ntot + 255) / 256, 256>>>(hidden, Wq, Wk, Wv);

    // QKV projection: grid (8 n-tiles, 64 m-tiles, 3)
    cudaFuncSetAttribute(qkv_kernel,
                         cudaFuncAttributeMaxDynamicSharedMemorySize, QKV_SMEM);
    dim3 ggrid(H_ / 128, MROWS / 128, 3);
    qkv_kernel<<<ggrid, 256, QKV_SMEM>>>(bq, bk, bv);

    // attention: grid (16 q-tiles, 64 bh)
    cudaFuncSetAttribute(attn_kernel,
                         cudaFuncAttributeMaxDynamicSharedMemorySize, ATT_SMEM);
    dim3 agrid(S_ / 128, B_ * NH_);
    attn_kernel<<<agrid, 256, ATT_SMEM>>>(amask, out);
}